// round 1
// baseline (speedup 1.0000x reference)
#include <cuda_runtime.h>
#include <math.h>

// Problem constants
#define NPTS   65536
#define CIN    5
#define DCH    128
#define KNBR   16
#define KK     15          // neighbors actually used (drop first)
#define HH     64
#define WW     1024
#define HW     (HH*WW)     // 65536
#define EPS    1e-5f

// ---------------- device scratch (static; no allocations allowed) -------------
__device__ float d_xn[NPTS * 8];          // normalized input, padded to 8 floats/pt
__device__ float d_feats[NPTS * DCH];     // final per-point features (winners only)
__device__ int   d_winner[HW];            // winning point index per pixel (-1 = none)
__device__ int   d_live[HW];              // compacted list of winning points
__device__ int   d_live_count;

// folded constants
__device__ float d_waf[DCH * CIN];        // w2a * scale2a * s2b
__device__ float d_bf[DCH];               // folded bias before gelu
__device__ float d_wpe[DCH * CIN];        // final_w[:, :D] @ conv1_w
__device__ float d_be[DCH];               // folded final bias (point branch)
__device__ float d_sn[CIN];               // input-BN scale
__device__ float d_shn[CIN];              // input-BN shift

// ---------------- prep: fold all BNs / conv1 / final into tiny matrices ------
__global__ void prep_kernel(const float* ng, const float* nb_, const float* nm, const float* nv,
                            const float* c1w, const float* c1b,
                            const float* g2a, const float* b2a, const float* m2a, const float* v2a,
                            const float* w2a,
                            const float* g2b, const float* b2b, const float* m2b, const float* v2b,
                            const float* fw, const float* fb)
{
    int d = threadIdx.x;  // 0..127
    if (d < CIN) {
        float s = ng[d] * rsqrtf(nv[d] + EPS);
        d_sn[d]  = s;
        d_shn[d] = nb_[d] - nm[d] * s;
    }
    // bn2a folded into w2a, then bn2b folded on top
    float s2b = g2b[d] * rsqrtf(v2b[d] + EPS);
    float t2b = b2b[d] - m2b[d] * s2b;
    float cst = 0.f;
    #pragma unroll
    for (int c = 0; c < CIN; c++) {
        float sc = g2a[c] * rsqrtf(v2a[c] + EPS);
        float sh = b2a[c] - m2a[c] * sc;
        d_waf[d * CIN + c] = w2a[d * CIN + c] * sc * s2b;
        cst += w2a[d * CIN + c] * sh;
    }
    d_bf[d] = cst * s2b + t2b;

    // point branch: final_w[:, :D] @ conv1_w  -> 128x5
    #pragma unroll
    for (int c = 0; c < CIN; c++) {
        float acc = 0.f;
        for (int e = 0; e < DCH; e++)
            acc += fw[d * (2 * DCH) + e] * c1w[e * CIN + c];
        d_wpe[d * CIN + c] = acc;
    }
    float ab = 0.f;
    for (int e = 0; e < DCH; e++)
        ab += fw[d * (2 * DCH) + e] * c1b[e];
    d_be[d] = ab + fb[d];
}

// ---------------- normalize input into padded layout --------------------------
__global__ void norm_kernel(const float* pc)
{
    int t = blockIdx.x * blockDim.x + threadIdx.x;   // over NPTS*8
    if (t >= NPTS * 8) return;
    int n = t >> 3, c = t & 7;
    float v = 0.f;
    if (c < CIN) v = pc[n * CIN + c] * d_sn[c] + d_shn[c];
    d_xn[t] = v;
}

// ---------------- winner map (last-index-wins scatter semantics) --------------
__global__ void winit_kernel()
{
    int t = blockIdx.x * blockDim.x + threadIdx.x;
    if (t < HW) d_winner[t] = -1;
    if (t == 0) d_live_count = 0;
}

__global__ void wscat_kernel(const int* px, const int* py)
{
    int n = blockIdx.x * blockDim.x + threadIdx.x;
    if (n >= NPTS) return;
    int pix = py[n] * WW + px[n];
    atomicMax(&d_winner[pix], n);
}

__global__ void compact_kernel()
{
    int t = blockIdx.x * blockDim.x + threadIdx.x;
    if (t >= HW) return;
    int w = d_winner[t];
    if (w >= 0) {
        int p = atomicAdd(&d_live_count, 1);
        d_live[p] = w;
    }
}

// ---------------- main fused kernel ------------------------------------------
// One block = 128 threads = 128 output channels. Each block loops over live
// points. w2b row lives in registers; Wn (=final_w[:,D:]) lives in shared,
// transposed for conflict-free access.
#define SM_WN    (DCH * DCH)            // 16384 floats
#define SM_G     (KK * DCH)             // 1920
#define SM_NE    (DCH)                  // 128
#define SM_DIFF  (KK * CIN)             // 75 -> pad 80
#define SM_XI    8
#define SMEM_FLOATS (SM_WN + SM_G + SM_NE + 80 + SM_XI)
#define SMEM_BYTES  (SMEM_FLOATS * 4)

__global__ void __launch_bounds__(128, 2)
main_kernel(const float* __restrict__ w2b, const float* __restrict__ fw,
            const int* __restrict__ nbr)
{
    extern __shared__ float sm[];
    float* Wn_s   = sm;                       // [d*128 + e]
    float* g_s    = sm + SM_WN;               // [k*128 + d]
    float* ne_s   = g_s + SM_G;               // [128]
    float* diff_s = ne_s + SM_NE;             // [k*5 + c]
    float* xi_s   = diff_s + 80;              // [5]

    const int e = threadIdx.x;

    // w2b row e -> registers
    float wreg[DCH];
    #pragma unroll
    for (int d = 0; d < DCH; d++) wreg[d] = w2b[e * DCH + d];

    // Wn transposed into shared: Wn_s[d*128+e] = final_w[e, 128+d]
    for (int i = e; i < DCH * DCH; i += 128) {
        int dd = i >> 7, ee = i & 127;
        Wn_s[i] = fw[ee * (2 * DCH) + DCH + dd];
    }

    float wa[CIN], wpe[CIN];
    #pragma unroll
    for (int c = 0; c < CIN; c++) { wa[c] = d_waf[e * CIN + c]; wpe[c] = d_wpe[e * CIN + c]; }
    const float bfl = d_bf[e];
    const float bef = d_be[e];
    __syncthreads();

    const int cnt = d_live_count;

    for (int it = blockIdx.x; it < cnt; it += gridDim.x) {
        const int n = d_live[it];

        // stage neighbor diffs + center point
        if (e < 80) {
            if (e < KK * CIN) {
                int k = e / CIN, c = e - k * CIN;
                int j = nbr[n * KNBR + 1 + k];
                diff_s[e] = d_xn[j * 8 + c] - d_xn[n * 8 + c];
            } else if (e < KK * CIN + CIN) {
                int c = e - KK * CIN;
                xi_s[c] = d_xn[n * 8 + c];
            }
        }
        __syncthreads();

        // phase 1: g[k][e] = gelu(w2a_full . diff_k + bias)
        #pragma unroll 1
        for (int k = 0; k < KK; k++) {
            float pre = bfl;
            #pragma unroll
            for (int c = 0; c < CIN; c++) pre += wa[c] * diff_s[k * CIN + c];
            g_s[k * DCH + e] = 0.5f * pre * (1.0f + erff(pre * 0.70710678118654752f));
        }
        __syncthreads();

        // phase 2: neigh_emb[e] = max_k (w2b[e,:] . g[k,:])
        float vmax = -3.4e38f;
        #pragma unroll 1
        for (int k = 0; k < KK; k++) {
            const float* g = g_s + k * DCH;
            float a0 = 0.f, a1 = 0.f, a2 = 0.f, a3 = 0.f;
            #pragma unroll
            for (int d = 0; d < DCH; d += 4) {
                a0 = fmaf(wreg[d    ], g[d    ], a0);
                a1 = fmaf(wreg[d + 1], g[d + 1], a1);
                a2 = fmaf(wreg[d + 2], g[d + 2], a2);
                a3 = fmaf(wreg[d + 3], g[d + 3], a3);
            }
            vmax = fmaxf(vmax, (a0 + a1) + (a2 + a3));
        }
        ne_s[e] = vmax;
        __syncthreads();

        // phase 3: feats[e] = Wn[e,:] . neigh_emb + Wp_eff[e,:] . xi + b_eff
        float f = bef;
        #pragma unroll
        for (int c = 0; c < CIN; c++) f += wpe[c] * xi_s[c];
        float b0 = 0.f, b1 = 0.f, b2 = 0.f, b3 = 0.f;
        #pragma unroll
        for (int d = 0; d < DCH; d += 4) {
            b0 = fmaf(Wn_s[(d    ) * DCH + e], ne_s[d    ], b0);
            b1 = fmaf(Wn_s[(d + 1) * DCH + e], ne_s[d + 1], b1);
            b2 = fmaf(Wn_s[(d + 2) * DCH + e], ne_s[d + 2], b2);
            b3 = fmaf(Wn_s[(d + 3) * DCH + e], ne_s[d + 3], b3);
        }
        d_feats[n * DCH + e] = f + (b0 + b1) + (b2 + b3);
        __syncthreads();
    }
}

// ---------------- emit: scatter features to (D, H, W) with coalesced writes ---
#define EM_TILE 64
__global__ void emit_kernel(float* __restrict__ out)
{
    __shared__ float s[EM_TILE * 129];   // padded stride 129 -> conflict-free
    const int pixbase = blockIdx.x * EM_TILE;
    const int tid = threadIdx.x;

    // gather: contiguous 512B reads per winner row
    for (int i = tid; i < EM_TILE * DCH; i += blockDim.x) {
        int p = i >> 7, d = i & 127;
        int w = d_winner[pixbase + p];
        s[p * 129 + d] = (w >= 0) ? d_feats[w * DCH + d] : -1.0f;
    }
    __syncthreads();

    // write: coalesced along pixel dim for each channel
    for (int i = tid; i < EM_TILE * DCH; i += blockDim.x) {
        int d = i >> 6, p = i & 63;
        out[d * HW + pixbase + p] = s[p * 129 + d];
    }
}

// ---------------- launch ------------------------------------------------------
extern "C" void kernel_launch(void* const* d_in, const int* in_sizes, int n_in,
                              void* d_out, int out_size)
{
    const float* pc        = (const float*)d_in[0];
    const int*   neighbors = (const int*)  d_in[1];
    const int*   px        = (const int*)  d_in[2];
    const int*   py        = (const int*)  d_in[3];
    const float* ng        = (const float*)d_in[4];
    const float* nb_       = (const float*)d_in[5];
    const float* nm        = (const float*)d_in[6];
    const float* nv        = (const float*)d_in[7];
    const float* c1w       = (const float*)d_in[8];
    const float* c1b       = (const float*)d_in[9];
    const float* g2a       = (const float*)d_in[10];
    const float* b2a       = (const float*)d_in[11];
    const float* m2a       = (const float*)d_in[12];
    const float* v2a       = (const float*)d_in[13];
    const float* w2a       = (const float*)d_in[14];
    const float* g2b       = (const float*)d_in[15];
    const float* b2b       = (const float*)d_in[16];
    const float* m2b       = (const float*)d_in[17];
    const float* v2b       = (const float*)d_in[18];
    const float* w2b       = (const float*)d_in[19];
    const float* fw        = (const float*)d_in[20];
    const float* fb        = (const float*)d_in[21];
    float* out = (float*)d_out;

    cudaFuncSetAttribute(main_kernel, cudaFuncAttributeMaxDynamicSharedMemorySize, SMEM_BYTES);

    prep_kernel<<<1, 128>>>(ng, nb_, nm, nv, c1w, c1b,
                            g2a, b2a, m2a, v2a, w2a,
                            g2b, b2b, m2b, v2b, fw, fb);
    norm_kernel<<<(NPTS * 8) / 256, 256>>>(pc);
    winit_kernel<<<HW / 256, 256>>>();
    wscat_kernel<<<NPTS / 256, 256>>>(px, py);
    compact_kernel<<<HW / 256, 256>>>();
    main_kernel<<<296, 128, SMEM_BYTES>>>(w2b, fw, neighbors);
    emit_kernel<<<HW / EM_TILE, 256>>>(out);
}

// round 4
// speedup vs baseline: 1.9312x; 1.9312x over previous
#include <cuda_runtime.h>
#include <cuda_fp16.h>
#include <math.h>
#include <stdint.h>

// Problem constants
#define NPTS   65536
#define CIN    5
#define DCH    128
#define KNBR   16
#define KK     15
#define HH     64
#define WW     1024
#define HW     (HH*WW)
#define EPS    1e-5f

#define PTILE  8            // points per CTA tile
#define MROWS  (PTILE*KK)   // 120 G rows
#define PITCH  136          // fp16 row pitch (272B) for ldmatrix tiles
#define DPITCH 124          // f32 pitch for D_s

// ---------------- device scratch ----------------------------------------------
__device__ float d_xn[NPTS * 8];
__device__ float d_feats[NPTS * DCH];
__device__ int   d_winner[HW];
__device__ int   d_live[HW];
__device__ int   d_live_count;

__device__ float d_waf[DCH * CIN];
__device__ float d_bf[DCH];
__device__ float d_wpe[DCH * CIN];
__device__ float d_be[DCH];
__device__ float d_sn[CIN];
__device__ float d_shn[CIN];

// ---------------- PTX helpers -------------------------------------------------
__device__ __forceinline__ uint32_t smem_u32(const void* p) {
    uint32_t a;
    asm("{ .reg .u64 t; cvta.to.shared.u64 t, %1; cvt.u32.u64 %0, t; }" : "=r"(a) : "l"(p));
    return a;
}
__device__ __forceinline__ void ldsm_x4(uint32_t* r, uint32_t addr) {
    asm volatile("ldmatrix.sync.aligned.m8n8.x4.shared.b16 {%0,%1,%2,%3}, [%4];"
        : "=r"(r[0]), "=r"(r[1]), "=r"(r[2]), "=r"(r[3]) : "r"(addr));
}
__device__ __forceinline__ void ldsm_x2(uint32_t* r, uint32_t addr) {
    asm volatile("ldmatrix.sync.aligned.m8n8.x2.shared.b16 {%0,%1}, [%2];"
        : "=r"(r[0]), "=r"(r[1]) : "r"(addr));
}
__device__ __forceinline__ void mma16816(float* d, const uint32_t* a, const uint32_t* b) {
    asm volatile("mma.sync.aligned.m16n8k16.row.col.f32.f16.f16.f32 "
        "{%0,%1,%2,%3}, {%4,%5,%6,%7}, {%8,%9}, {%0,%1,%2,%3};"
        : "+f"(d[0]), "+f"(d[1]), "+f"(d[2]), "+f"(d[3])
        : "r"(a[0]), "r"(a[1]), "r"(a[2]), "r"(a[3]), "r"(b[0]), "r"(b[1]));
}

// ---------------- SMEM layout (bytes) -----------------------------------------
#define OFF_GHI   0                  // 128 x PITCH fp16 = 34816 (D_s reuses GHI/GLO)
#define OFF_GLO   34816
#define OFF_W     69632              // w2b fp16, 128 x PITCH = 34816
#define OFF_WN    104448             // 128x132 f32 = 67584
#define OFF_NE    172032             // 128x8 f32 = 4096
#define OFF_DIFF  176128             // 120x8 f32 = 3840
#define OFF_XI    179968             // 8x8 f32 = 256
#define OFF_IDS   180224             // 8 int = 32
#define SMEM_SZ   180256

// ---------------- prep / norm / winner kernels ---------------------------------
__global__ void prep_kernel(const float* ng, const float* nb_, const float* nm, const float* nv,
                            const float* c1w, const float* c1b,
                            const float* g2a, const float* b2a, const float* m2a, const float* v2a,
                            const float* w2a,
                            const float* g2b, const float* b2b, const float* m2b, const float* v2b,
                            const float* fw, const float* fb)
{
    int d = threadIdx.x;
    if (d < CIN) {
        float s = ng[d] * rsqrtf(nv[d] + EPS);
        d_sn[d]  = s;
        d_shn[d] = nb_[d] - nm[d] * s;
    }
    float s2b = g2b[d] * rsqrtf(v2b[d] + EPS);
    float t2b = b2b[d] - m2b[d] * s2b;
    float cst = 0.f;
    #pragma unroll
    for (int c = 0; c < CIN; c++) {
        float sc = g2a[c] * rsqrtf(v2a[c] + EPS);
        float sh = b2a[c] - m2a[c] * sc;
        d_waf[d * CIN + c] = w2a[d * CIN + c] * sc * s2b;
        cst += w2a[d * CIN + c] * sh;
    }
    d_bf[d] = cst * s2b + t2b;
    #pragma unroll
    for (int c = 0; c < CIN; c++) {
        float acc = 0.f;
        for (int e = 0; e < DCH; e++)
            acc += fw[d * (2 * DCH) + e] * c1w[e * CIN + c];
        d_wpe[d * CIN + c] = acc;
    }
    float ab = 0.f;
    for (int e = 0; e < DCH; e++)
        ab += fw[d * (2 * DCH) + e] * c1b[e];
    d_be[d] = ab + fb[d];
}

__global__ void norm_kernel(const float* pc)
{
    int t = blockIdx.x * blockDim.x + threadIdx.x;
    if (t >= NPTS * 8) return;
    int n = t >> 3, c = t & 7;
    float v = 0.f;
    if (c < CIN) v = pc[n * CIN + c] * d_sn[c] + d_shn[c];
    d_xn[t] = v;
}

__global__ void winit_kernel()
{
    int t = blockIdx.x * blockDim.x + threadIdx.x;
    if (t < HW) d_winner[t] = -1;
    if (t == 0) d_live_count = 0;
}

__global__ void wscat_kernel(const int* px, const int* py)
{
    int n = blockIdx.x * blockDim.x + threadIdx.x;
    if (n >= NPTS) return;
    atomicMax(&d_winner[py[n] * WW + px[n]], n);
}

__global__ void compact_kernel()
{
    int t = blockIdx.x * blockDim.x + threadIdx.x;
    if (t >= HW) return;
    int w = d_winner[t];
    if (w >= 0) {
        int p = atomicAdd(&d_live_count, 1);
        d_live[p] = w;
    }
}

// ---------------- main kernel: mma.sync fp16 (W single, G hi/lo) --------------
__global__ void __launch_bounds__(256, 1)
main_kernel(const float* __restrict__ w2b, const float* __restrict__ fw,
            const int* __restrict__ nbr)
{
    extern __shared__ char smem[];
    const uint32_t smb = smem_u32(smem);
    __half* Ghi_s = (__half*)(smem + OFF_GHI);
    __half* Glo_s = (__half*)(smem + OFF_GLO);
    __half* W_s   = (__half*)(smem + OFF_W);
    float*  D_s   = (float*)(smem + OFF_GHI);   // overlaps G (after MMA reads)
    float*  Wn_s  = (float*)(smem + OFF_WN);
    float*  ne_s  = (float*)(smem + OFF_NE);
    float*  diff_s= (float*)(smem + OFF_DIFF);
    float*  xi_s  = (float*)(smem + OFF_XI);
    int*    ids   = (int*)  (smem + OFF_IDS);

    const int tid  = threadIdx.x;
    const int wid  = tid >> 5;
    const int lane = tid & 31;

    // ---- prologue: weights into SMEM ----
    for (int i = tid; i < DCH * DCH; i += 256) {
        int e = i >> 7, d = i & 127;
        W_s[e * PITCH + d] = __float2half_rn(w2b[i]);
    }
    for (int i = tid; i < DCH * DCH; i += 256) {
        int dout = i >> 7, e = i & 127;
        Wn_s[e * 132 + dout] = fw[dout * (2 * DCH) + DCH + e];
    }

    // per-thread constants (channel for phase1; dout for phase3)
    const int dch = tid & 127;
    float wa[CIN], wpe[CIN];
    #pragma unroll
    for (int c = 0; c < CIN; c++) { wa[c] = d_waf[dch * CIN + c]; wpe[c] = d_wpe[dch * CIN + c]; }
    const float bfv = d_bf[dch];
    const float bev = d_be[dch];

    // ldmatrix address bases
    // A (W): rows e0 + (lane&15), k-half offset ((lane>>4)<<3)
    const uint32_t aAddr = smb + OFF_W + (((16 * wid + (lane & 15)) * PITCH + ((lane >> 4) << 3)) << 1);
    // B x4 (G, 2 n-blocks): row = 16q + ((lane>>4)<<3) + (lane&7); col-half ((lane>>3)&1)*8
    const uint32_t bRowX4 = ((lane >> 4) << 3) + (lane & 7);
    const uint32_t bColX4 = ((lane >> 3) & 1) << 3;
    const uint32_t bHi4 = smb + OFF_GHI + ((bRowX4 * PITCH + bColX4) << 1);
    const uint32_t bLo4 = smb + OFF_GLO + ((bRowX4 * PITCH + bColX4) << 1);
    // B x2 (last n-block, rows 112..119)
    const uint32_t bRowX2 = 112 + (lane & 7);
    const uint32_t bColX2 = ((lane >> 3) & 1) << 3;
    const uint32_t bHi2 = smb + OFF_GHI + ((bRowX2 * PITCH + bColX2) << 1);
    const uint32_t bLo2 = smb + OFF_GLO + ((bRowX2 * PITCH + bColX2) << 1);

    __syncthreads();

    const int cnt = d_live_count;

    for (int base = blockIdx.x * PTILE; base < cnt; base += gridDim.x * PTILE) {
        const int np = min(PTILE, cnt - base);

        if (tid < PTILE) {
            int idx = base + tid;
            if (idx >= cnt) idx = cnt - 1;
            ids[tid] = d_live[idx];
        }
        __syncthreads();

        // stage neighbor diffs + center points
        if (tid < MROWS) {
            int p = tid / KK, k = tid - p * KK;
            int n = ids[p];
            int j = nbr[n * KNBR + 1 + k];
            float4 a0 = ((const float4*)&d_xn[j * 8])[0];
            float4 b0 = ((const float4*)&d_xn[n * 8])[0];
            ((float4*)&diff_s[tid * 8])[0] = make_float4(a0.x - b0.x, a0.y - b0.y, a0.z - b0.z, a0.w - b0.w);
            float4 a1 = ((const float4*)&d_xn[j * 8])[1];
            float4 b1 = ((const float4*)&d_xn[n * 8])[1];
            ((float4*)&diff_s[tid * 8])[1] = make_float4(a1.x - b1.x, a1.y - b1.y, a1.z - b1.z, a1.w - b1.w);
        } else if (tid < MROWS + PTILE) {
            int p = tid - MROWS;
            int n = ids[p];
            ((float4*)&xi_s[p * 8])[0] = ((const float4*)&d_xn[n * 8])[0];
            ((float4*)&xi_s[p * 8])[1] = ((const float4*)&d_xn[n * 8])[1];
        }
        __syncthreads();

        // phase 1: gelu -> G[m][dch] fp16 hi/lo (row-major, pitch PITCH)
        // sigmoid-form gelu: x * sigmoid(1.5957691 * x * (1 + 0.044715 x^2))
        {
            const int mb = tid >> 7;
            #pragma unroll 4
            for (int i = 0; i < MROWS / 2; i++) {
                int m = mb + 2 * i;
                float pre = bfv;
                #pragma unroll
                for (int c = 0; c < CIN; c++) pre = fmaf(wa[c], diff_s[m * 8 + c], pre);
                float t = fmaf(0.044715f, pre * pre, 1.0f);
                float g = __fdividef(pre, 1.0f + __expf(-1.5957691f * pre * t));
                __half hi = __float2half_rn(g);
                __half lo = __float2half_rn(g - __half2float(hi));
                Ghi_s[m * PITCH + dch] = hi;
                Glo_s[m * PITCH + dch] = lo;
            }
        }
        __syncthreads();

        // phase 2: warp-level HMMA.  D[e,m] = sum_d W[e,d]*G[m,d]
        float acc[15][4];
        #pragma unroll
        for (int nb = 0; nb < 15; nb++)
            #pragma unroll
            for (int j = 0; j < 4; j++) acc[nb][j] = 0.f;

        #pragma unroll
        for (int kt = 0; kt < 8; kt++) {
            uint32_t a[4];
            ldsm_x4(a, aAddr + kt * 32);
            #pragma unroll
            for (int q = 0; q < 7; q++) {
                uint32_t bh[4], bl[4];
                ldsm_x4(bh, bHi4 + q * (16 * PITCH * 2) + kt * 32);
                ldsm_x4(bl, bLo4 + q * (16 * PITCH * 2) + kt * 32);
                mma16816(acc[2 * q],     a, bh);
                mma16816(acc[2 * q],     a, bl);
                mma16816(acc[2 * q + 1], a, bh + 2);
                mma16816(acc[2 * q + 1], a, bl + 2);
            }
            uint32_t b2h[2], b2l[2];
            ldsm_x2(b2h, bHi2 + kt * 32);
            ldsm_x2(b2l, bLo2 + kt * 32);
            mma16816(acc[14], a, b2h);
            mma16816(acc[14], a, b2l);
        }
        __syncthreads();   // all warps done reading G before overwriting as D_s

        // store D fragments: thread holds rows e0+g, e0+g+8; cols nb*8 + tg*2 + {0,1}
        {
            const int g  = lane >> 2, tg = lane & 3;
            const int eLo = 16 * wid + g, eHi = eLo + 8;
            #pragma unroll
            for (int nb = 0; nb < 15; nb++) {
                int m0 = nb * 8 + tg * 2;
                *(float2*)&D_s[eLo * DPITCH + m0] = make_float2(acc[nb][0], acc[nb][1]);
                *(float2*)&D_s[eHi * DPITCH + m0] = make_float2(acc[nb][2], acc[nb][3]);
            }
        }
        __syncthreads();

        // epilogue A: max over 15 neighbors -> ne_s[e][p]
        #pragma unroll
        for (int j = 0; j < 4; j++) {
            int pi = tid + 256 * j;       // 1024 (e,p) pairs
            int e = pi >> 3, p = pi & 7;
            const float* row = &D_s[e * DPITCH + p * KK];
            float v = row[0];
            #pragma unroll
            for (int k = 1; k < KK; k++) v = fmaxf(v, row[k]);
            ne_s[e * 8 + p] = v;
        }
        __syncthreads();

        // epilogue B: feats[p][dout] = be + Wp.xi + sum_e Wn[dout,e]*ne[e][p]
        {
            const int ph = tid >> 7;     // point half: 0 -> p 0..3, 1 -> p 4..7
            float f[4];
            #pragma unroll
            for (int j = 0; j < 4; j++) {
                int p = ph * 4 + j;
                float v = bev;
                #pragma unroll
                for (int c = 0; c < CIN; c++) v = fmaf(wpe[c], xi_s[p * 8 + c], v);
                f[j] = v;
            }
            #pragma unroll 8
            for (int e = 0; e < DCH; e++) {
                float w = Wn_s[e * 132 + dch];
                float4 nv4 = *(const float4*)&ne_s[e * 8 + ph * 4];
                f[0] = fmaf(w, nv4.x, f[0]);
                f[1] = fmaf(w, nv4.y, f[1]);
                f[2] = fmaf(w, nv4.z, f[2]);
                f[3] = fmaf(w, nv4.w, f[3]);
            }
            #pragma unroll
            for (int j = 0; j < 4; j++) {
                int p = ph * 4 + j;
                if (p < np) d_feats[ids[p] * DCH + dch] = f[j];
            }
        }
        __syncthreads();
    }
}

// ---------------- emit ---------------------------------------------------------
#define EM_TILE 64
__global__ void emit_kernel(float* __restrict__ out)
{
    __shared__ float s[EM_TILE * 129];
    const int pixbase = blockIdx.x * EM_TILE;
    const int tid = threadIdx.x;

    for (int i = tid; i < EM_TILE * DCH; i += blockDim.x) {
        int p = i >> 7, d = i & 127;
        int w = d_winner[pixbase + p];
        s[p * 129 + d] = (w >= 0) ? d_feats[w * DCH + d] : -1.0f;
    }
    __syncthreads();
    for (int i = tid; i < EM_TILE * DCH; i += blockDim.x) {
        int d = i >> 6, p = i & 63;
        out[d * HW + pixbase + p] = s[p * 129 + d];
    }
}

// ---------------- launch --------------------------------------------------------
extern "C" void kernel_launch(void* const* d_in, const int* in_sizes, int n_in,
                              void* d_out, int out_size)
{
    const float* pc        = (const float*)d_in[0];
    const int*   neighbors = (const int*)  d_in[1];
    const int*   px        = (const int*)  d_in[2];
    const int*   py        = (const int*)  d_in[3];
    const float* ng        = (const float*)d_in[4];
    const float* nb_       = (const float*)d_in[5];
    const float* nm        = (const float*)d_in[6];
    const float* nv        = (const float*)d_in[7];
    const float* c1w       = (const float*)d_in[8];
    const float* c1b       = (const float*)d_in[9];
    const float* g2a       = (const float*)d_in[10];
    const float* b2a       = (const float*)d_in[11];
    const float* m2a       = (const float*)d_in[12];
    const float* v2a       = (const float*)d_in[13];
    const float* w2a       = (const float*)d_in[14];
    const float* g2b       = (const float*)d_in[15];
    const float* b2b       = (const float*)d_in[16];
    const float* m2b       = (const float*)d_in[17];
    const float* v2b       = (const float*)d_in[18];
    const float* w2b       = (const float*)d_in[19];
    const float* fw        = (const float*)d_in[20];
    const float* fb        = (const float*)d_in[21];
    float* out = (float*)d_out;

    cudaFuncSetAttribute(main_kernel, cudaFuncAttributeMaxDynamicSharedMemorySize, SMEM_SZ);

    prep_kernel<<<1, 128>>>(ng, nb_, nm, nv, c1w, c1b,
                            g2a, b2a, m2a, v2a, w2a,
                            g2b, b2b, m2b, v2b, fw, fb);
    norm_kernel<<<(NPTS * 8) / 256, 256>>>(pc);
    winit_kernel<<<HW / 256, 256>>>();
    wscat_kernel<<<NPTS / 256, 256>>>(px, py);
    compact_kernel<<<HW / 256, 256>>>();
    main_kernel<<<296, 256, SMEM_SZ>>>(w2b, fw, neighbors);
    emit_kernel<<<HW / EM_TILE, 256>>>(out);
}

// round 5
// speedup vs baseline: 3.1549x; 1.6336x over previous
#include <cuda_runtime.h>
#include <cuda_fp16.h>
#include <math.h>
#include <stdint.h>

// Problem constants
#define NPTS   65536
#define CIN    5
#define DCH    128
#define KNBR   16
#define KK     15
#define HH     64
#define WW     1024
#define HW     (HH*WW)
#define EPS    1e-5f

#define PTILE  8            // points per CTA tile
#define MROWS  (PTILE*KK)   // 120 G rows
#define PITCH  136          // fp16 row pitch (272B) for ldmatrix tiles
#define WNP    132          // fp16 pitch for Wn

// ---------------- device scratch ----------------------------------------------
__device__ float d_xn[NPTS * 8];
__device__ float d_feats[NPTS * DCH];
__device__ int   d_winner[HW];
__device__ int   d_live[HW];
__device__ int   d_live_count;

__device__ float d_waf[DCH * CIN];
__device__ float d_bf[DCH];
__device__ float d_wpe[DCH * CIN];
__device__ float d_be[DCH];
__device__ float d_sn[CIN];
__device__ float d_shn[CIN];

// ---------------- PTX helpers -------------------------------------------------
__device__ __forceinline__ uint32_t smem_u32(const void* p) {
    uint32_t a;
    asm("{ .reg .u64 t; cvta.to.shared.u64 t, %1; cvt.u32.u64 %0, t; }" : "=r"(a) : "l"(p));
    return a;
}
__device__ __forceinline__ void ldsm_x4(uint32_t* r, uint32_t addr) {
    asm volatile("ldmatrix.sync.aligned.m8n8.x4.shared.b16 {%0,%1,%2,%3}, [%4];"
        : "=r"(r[0]), "=r"(r[1]), "=r"(r[2]), "=r"(r[3]) : "r"(addr));
}
__device__ __forceinline__ void ldsm_x2(uint32_t* r, uint32_t addr) {
    asm volatile("ldmatrix.sync.aligned.m8n8.x2.shared.b16 {%0,%1}, [%2];"
        : "=r"(r[0]), "=r"(r[1]) : "r"(addr));
}
__device__ __forceinline__ void mma16816(float* d, const uint32_t* a, const uint32_t* b) {
    asm volatile("mma.sync.aligned.m16n8k16.row.col.f32.f16.f16.f32 "
        "{%0,%1,%2,%3}, {%4,%5,%6,%7}, {%8,%9}, {%0,%1,%2,%3};"
        : "+f"(d[0]), "+f"(d[1]), "+f"(d[2]), "+f"(d[3])
        : "r"(a[0]), "r"(a[1]), "r"(a[2]), "r"(a[3]), "r"(b[0]), "r"(b[1]));
}

// ---------------- SMEM layout (bytes) -----------------------------------------
#define OFF_G     0                  // G fp16 128 x PITCH = 34816; D_h overlays
#define OFF_W     34816              // w2b fp16 128 x PITCH = 34816
#define OFF_WN    69632              // Wn fp16 128 x WNP = 33792
#define OFF_NE    103424             // 128x8 f32 = 4096
#define OFF_DIFF  107520             // 120x8 f32 = 3840
#define OFF_XI    111360             // 8x8 f32 = 256
#define OFF_IDS   111616             // 8 int = 32
#define SMEM_SZ   111648

// ---------------- prep / norm / winner kernels ---------------------------------
__global__ void prep_kernel(const float* ng, const float* nb_, const float* nm, const float* nv,
                            const float* c1w, const float* c1b,
                            const float* g2a, const float* b2a, const float* m2a, const float* v2a,
                            const float* w2a,
                            const float* g2b, const float* b2b, const float* m2b, const float* v2b,
                            const float* fw, const float* fb)
{
    int d = threadIdx.x;
    if (d < CIN) {
        float s = ng[d] * rsqrtf(nv[d] + EPS);
        d_sn[d]  = s;
        d_shn[d] = nb_[d] - nm[d] * s;
    }
    float s2b = g2b[d] * rsqrtf(v2b[d] + EPS);
    float t2b = b2b[d] - m2b[d] * s2b;
    float cst = 0.f;
    #pragma unroll
    for (int c = 0; c < CIN; c++) {
        float sc = g2a[c] * rsqrtf(v2a[c] + EPS);
        float sh = b2a[c] - m2a[c] * sc;
        d_waf[d * CIN + c] = w2a[d * CIN + c] * sc * s2b;
        cst += w2a[d * CIN + c] * sh;
    }
    d_bf[d] = cst * s2b + t2b;
    #pragma unroll
    for (int c = 0; c < CIN; c++) {
        float acc = 0.f;
        for (int e = 0; e < DCH; e++)
            acc += fw[d * (2 * DCH) + e] * c1w[e * CIN + c];
        d_wpe[d * CIN + c] = acc;
    }
    float ab = 0.f;
    for (int e = 0; e < DCH; e++)
        ab += fw[d * (2 * DCH) + e] * c1b[e];
    d_be[d] = ab + fb[d];
}

__global__ void norm_kernel(const float* pc)
{
    int t = blockIdx.x * blockDim.x + threadIdx.x;
    if (t >= NPTS * 8) return;
    int n = t >> 3, c = t & 7;
    float v = 0.f;
    if (c < CIN) v = pc[n * CIN + c] * d_sn[c] + d_shn[c];
    d_xn[t] = v;
}

__global__ void winit_kernel()
{
    int t = blockIdx.x * blockDim.x + threadIdx.x;
    if (t < HW) d_winner[t] = -1;
    if (t == 0) d_live_count = 0;
}

__global__ void wscat_kernel(const int* px, const int* py)
{
    int n = blockIdx.x * blockDim.x + threadIdx.x;
    if (n >= NPTS) return;
    atomicMax(&d_winner[py[n] * WW + px[n]], n);
}

__global__ void compact_kernel()
{
    int t = blockIdx.x * blockDim.x + threadIdx.x;
    if (t >= HW) return;
    int w = d_winner[t];
    if (w >= 0) {
        int p = atomicAdd(&d_live_count, 1);
        d_live[p] = w;
    }
}

// ---------------- main kernel: mma.sync fp16, single-precision-split-free ------
__global__ void __launch_bounds__(256, 2)
main_kernel(const float* __restrict__ w2b, const float* __restrict__ fw,
            const int* __restrict__ nbr)
{
    extern __shared__ char smem[];
    const uint32_t smb = smem_u32(smem);
    __half* G_s   = (__half*)(smem + OFF_G);
    __half* W_s   = (__half*)(smem + OFF_W);
    __half* D_h   = (__half*)(smem + OFF_G);    // overlays G after MMA
    __half* Wn_h  = (__half*)(smem + OFF_WN);
    float*  ne_s  = (float*)(smem + OFF_NE);
    float*  diff_s= (float*)(smem + OFF_DIFF);
    float*  xi_s  = (float*)(smem + OFF_XI);
    int*    ids   = (int*)  (smem + OFF_IDS);

    const int tid  = threadIdx.x;
    const int wid  = tid >> 5;
    const int lane = tid & 31;

    // ---- prologue: weights into SMEM ----
    for (int i = tid; i < DCH * DCH; i += 256) {
        int e = i >> 7, d = i & 127;
        W_s[e * PITCH + d] = __float2half_rn(w2b[i]);
    }
    for (int i = tid; i < DCH * DCH; i += 256) {
        int dout = i >> 7, e = i & 127;
        Wn_h[e * WNP + dout] = __float2half_rn(fw[dout * (2 * DCH) + DCH + e]);
    }

    const int dch = tid & 127;
    float wa[CIN], wpe[CIN];
    #pragma unroll
    for (int c = 0; c < CIN; c++) { wa[c] = d_waf[dch * CIN + c]; wpe[c] = d_wpe[dch * CIN + c]; }
    const float bfv = d_bf[dch];
    const float bev = d_be[dch];

    // ldmatrix address bases
    const uint32_t aAddr = smb + OFF_W + (((16 * wid + (lane & 15)) * PITCH + ((lane >> 4) << 3)) << 1);
    const uint32_t bRowX4 = ((lane >> 4) << 3) + (lane & 7);
    const uint32_t bColX4 = ((lane >> 3) & 1) << 3;
    const uint32_t bG4 = smb + OFF_G + ((bRowX4 * PITCH + bColX4) << 1);
    const uint32_t bRowX2 = 112 + (lane & 7);
    const uint32_t bG2 = smb + OFF_G + ((bRowX2 * PITCH + bColX4) << 1);

    __syncthreads();

    const int cnt = d_live_count;

    for (int base = blockIdx.x * PTILE; base < cnt; base += gridDim.x * PTILE) {
        const int np = min(PTILE, cnt - base);

        if (tid < PTILE) {
            int idx = base + tid;
            if (idx >= cnt) idx = cnt - 1;
            ids[tid] = d_live[idx];
        }
        __syncthreads();

        // stage neighbor diffs + center points
        if (tid < MROWS) {
            int p = tid / KK, k = tid - p * KK;
            int n = ids[p];
            int j = nbr[n * KNBR + 1 + k];
            float4 a0 = ((const float4*)&d_xn[j * 8])[0];
            float4 b0 = ((const float4*)&d_xn[n * 8])[0];
            ((float4*)&diff_s[tid * 8])[0] = make_float4(a0.x - b0.x, a0.y - b0.y, a0.z - b0.z, a0.w - b0.w);
            float4 a1 = ((const float4*)&d_xn[j * 8])[1];
            float4 b1 = ((const float4*)&d_xn[n * 8])[1];
            ((float4*)&diff_s[tid * 8])[1] = make_float4(a1.x - b1.x, a1.y - b1.y, a1.z - b1.z, a1.w - b1.w);
        } else if (tid < MROWS + PTILE) {
            int p = tid - MROWS;
            int n = ids[p];
            ((float4*)&xi_s[p * 8])[0] = ((const float4*)&d_xn[n * 8])[0];
            ((float4*)&xi_s[p * 8])[1] = ((const float4*)&d_xn[n * 8])[1];
        }
        __syncthreads();

        // phase 1: gelu -> G[m][dch] single fp16
        {
            const int mb = tid >> 7;
            #pragma unroll 4
            for (int i = 0; i < MROWS / 2; i++) {
                int m = mb + 2 * i;
                float pre = bfv;
                #pragma unroll
                for (int c = 0; c < CIN; c++) pre = fmaf(wa[c], diff_s[m * 8 + c], pre);
                float t = fmaf(0.044715f, pre * pre, 1.0f);
                float g = __fdividef(pre, 1.0f + __expf(-1.5957691f * pre * t));
                G_s[m * PITCH + dch] = __float2half_rn(g);
            }
        }
        __syncthreads();

        // phase 2: warp-level HMMA.  D[e,m] = sum_d W[e,d]*G[m,d]
        float acc[15][4];
        #pragma unroll
        for (int nb = 0; nb < 15; nb++)
            #pragma unroll
            for (int j = 0; j < 4; j++) acc[nb][j] = 0.f;

        #pragma unroll
        for (int kt = 0; kt < 8; kt++) {
            uint32_t a[4];
            ldsm_x4(a, aAddr + kt * 32);
            #pragma unroll
            for (int q = 0; q < 7; q++) {
                uint32_t bg[4];
                ldsm_x4(bg, bG4 + q * (16 * PITCH * 2) + kt * 32);
                mma16816(acc[2 * q],     a, bg);
                mma16816(acc[2 * q + 1], a, bg + 2);
            }
            uint32_t b2[2];
            ldsm_x2(b2, bG2 + kt * 32);
            mma16816(acc[14], a, b2);
        }
        __syncthreads();   // all warps done reading G before overwriting as D_h

        // store D fragments as fp16 into padded (p*16+k) layout
        {
            const int g  = lane >> 2, tg = lane & 3;
            const int eLo = 16 * wid + g, eHi = eLo + 8;
            #pragma unroll
            for (int nb = 0; nb < 15; nb++) {
                int m0 = nb * 8 + tg * 2;
                int p0 = m0 / KK,        k0 = m0 - p0 * KK;
                int p1 = (m0 + 1) / KK,  k1 = (m0 + 1) - p1 * KK;
                D_h[eLo * PITCH + p0 * 16 + k0] = __float2half_rn(acc[nb][0]);
                D_h[eLo * PITCH + p1 * 16 + k1] = __float2half_rn(acc[nb][1]);
                D_h[eHi * PITCH + p0 * 16 + k0] = __float2half_rn(acc[nb][2]);
                D_h[eHi * PITCH + p1 * 16 + k1] = __float2half_rn(acc[nb][3]);
            }
        }
        __syncthreads();

        // epilogue A: max over 15 neighbors -> ne_s[e][p]
        #pragma unroll
        for (int j = 0; j < 4; j++) {
            int pi = tid + 256 * j;
            int e = pi >> 3, p = pi & 7;
            const __half2* row = (const __half2*)(D_h + e * PITCH + p * 16);
            __half2 m2 = row[0];
            #pragma unroll
            for (int k = 1; k < 7; k++) m2 = __hmax2(m2, row[k]);
            float v = fmaxf(__low2float(m2), __high2float(m2));
            v = fmaxf(v, __half2float(D_h[e * PITCH + p * 16 + 14]));
            ne_s[e * 8 + p] = v;
        }
        __syncthreads();

        // epilogue B: feats[p][dout] = be + Wp.xi + sum_e Wn[dout,e]*ne[e][p]
        {
            const int ph = tid >> 7;
            float f[4];
            #pragma unroll
            for (int j = 0; j < 4; j++) {
                int p = ph * 4 + j;
                float v = bev;
                #pragma unroll
                for (int c = 0; c < CIN; c++) v = fmaf(wpe[c], xi_s[p * 8 + c], v);
                f[j] = v;
            }
            #pragma unroll 8
            for (int e = 0; e < DCH; e++) {
                float w = __half2float(Wn_h[e * WNP + dch]);
                float4 nv4 = *(const float4*)&ne_s[e * 8 + ph * 4];
                f[0] = fmaf(w, nv4.x, f[0]);
                f[1] = fmaf(w, nv4.y, f[1]);
                f[2] = fmaf(w, nv4.z, f[2]);
                f[3] = fmaf(w, nv4.w, f[3]);
            }
            #pragma unroll
            for (int j = 0; j < 4; j++) {
                int p = ph * 4 + j;
                if (p < np) d_feats[ids[p] * DCH + dch] = f[j];
            }
        }
        __syncthreads();
    }
}

// ---------------- emit ---------------------------------------------------------
#define EM_TILE 64
__global__ void emit_kernel(float* __restrict__ out)
{
    __shared__ float s[EM_TILE * 129];
    const int pixbase = blockIdx.x * EM_TILE;
    const int tid = threadIdx.x;

    for (int i = tid; i < EM_TILE * DCH; i += blockDim.x) {
        int p = i >> 7, d = i & 127;
        int w = d_winner[pixbase + p];
        s[p * 129 + d] = (w >= 0) ? d_feats[w * DCH + d] : -1.0f;
    }
    __syncthreads();
    for (int i = tid; i < EM_TILE * DCH; i += blockDim.x) {
        int d = i >> 6, p = i & 63;
        out[d * HW + pixbase + p] = s[p * 129 + d];
    }
}

// ---------------- launch --------------------------------------------------------
extern "C" void kernel_launch(void* const* d_in, const int* in_sizes, int n_in,
                              void* d_out, int out_size)
{
    const float* pc        = (const float*)d_in[0];
    const int*   neighbors = (const int*)  d_in[1];
    const int*   px        = (const int*)  d_in[2];
    const int*   py        = (const int*)  d_in[3];
    const float* ng        = (const float*)d_in[4];
    const float* nb_       = (const float*)d_in[5];
    const float* nm        = (const float*)d_in[6];
    const float* nv        = (const float*)d_in[7];
    const float* c1w       = (const float*)d_in[8];
    const float* c1b       = (const float*)d_in[9];
    const float* g2a       = (const float*)d_in[10];
    const float* b2a       = (const float*)d_in[11];
    const float* m2a       = (const float*)d_in[12];
    const float* v2a       = (const float*)d_in[13];
    const float* w2a       = (const float*)d_in[14];
    const float* g2b       = (const float*)d_in[15];
    const float* b2b       = (const float*)d_in[16];
    const float* m2b       = (const float*)d_in[17];
    const float* v2b       = (const float*)d_in[18];
    const float* w2b       = (const float*)d_in[19];
    const float* fw        = (const float*)d_in[20];
    const float* fb        = (const float*)d_in[21];
    float* out = (float*)d_out;

    cudaFuncSetAttribute(main_kernel, cudaFuncAttributeMaxDynamicSharedMemorySize, SMEM_SZ);

    prep_kernel<<<1, 128>>>(ng, nb_, nm, nv, c1w, c1b,
                            g2a, b2a, m2a, v2a, w2a,
                            g2b, b2b, m2b, v2b, fw, fb);
    norm_kernel<<<(NPTS * 8) / 256, 256>>>(pc);
    winit_kernel<<<HW / 256, 256>>>();
    wscat_kernel<<<NPTS / 256, 256>>>(px, py);
    compact_kernel<<<HW / 256, 256>>>();
    main_kernel<<<296, 256, SMEM_SZ>>>(w2b, fw, neighbors);
    emit_kernel<<<HW / EM_TILE, 256>>>(out);
}

// round 6
// speedup vs baseline: 3.5780x; 1.1341x over previous
#include <cuda_runtime.h>
#include <cuda_fp16.h>
#include <math.h>
#include <stdint.h>

// Problem constants
#define NPTS   65536
#define CIN    5
#define DCH    128
#define KNBR   16
#define KK     15
#define HH     64
#define WW     1024
#define HW     (HH*WW)
#define EPS    1e-5f

#define PTILE  8            // points per CTA tile
#define MROWS  (PTILE*KK)   // 120 G rows
#define PITCH  136          // fp16 pitch (272B) for G / W / Wn ldmatrix tiles

// ---------------- device scratch ----------------------------------------------
__device__ float d_xn[NPTS * 8];
__device__ float d_feats[NPTS * DCH];
__device__ int   d_winner[HW];
__device__ int   d_live[HW];
__device__ int   d_live_count;

__device__ float d_waf[DCH * CIN];
__device__ float d_bf[DCH];
__device__ float d_wpe[DCH * CIN];
__device__ float d_be[DCH];
__device__ float d_sn[CIN];
__device__ float d_shn[CIN];

// ---------------- PTX helpers -------------------------------------------------
__device__ __forceinline__ uint32_t smem_u32(const void* p) {
    uint32_t a;
    asm("{ .reg .u64 t; cvta.to.shared.u64 t, %1; cvt.u32.u64 %0, t; }" : "=r"(a) : "l"(p));
    return a;
}
__device__ __forceinline__ void ldsm_x4(uint32_t* r, uint32_t addr) {
    asm volatile("ldmatrix.sync.aligned.m8n8.x4.shared.b16 {%0,%1,%2,%3}, [%4];"
        : "=r"(r[0]), "=r"(r[1]), "=r"(r[2]), "=r"(r[3]) : "r"(addr));
}
__device__ __forceinline__ void ldsm_x2(uint32_t* r, uint32_t addr) {
    asm volatile("ldmatrix.sync.aligned.m8n8.x2.shared.b16 {%0,%1}, [%2];"
        : "=r"(r[0]), "=r"(r[1]) : "r"(addr));
}
__device__ __forceinline__ void mma16816(float* d, const uint32_t* a, const uint32_t* b) {
    asm volatile("mma.sync.aligned.m16n8k16.row.col.f32.f16.f16.f32 "
        "{%0,%1,%2,%3}, {%4,%5,%6,%7}, {%8,%9}, {%0,%1,%2,%3};"
        : "+f"(d[0]), "+f"(d[1]), "+f"(d[2]), "+f"(d[3])
        : "r"(a[0]), "r"(a[1]), "r"(a[2]), "r"(a[3]), "r"(b[0]), "r"(b[1]));
}
__device__ __forceinline__ float gelu_f(float x) {
    float t = fmaf(0.044715f, x * x, 1.0f);
    return __fdividef(x, 1.0f + __expf(-1.5957691f * x * t));
}

// ---------------- SMEM layout (bytes) -----------------------------------------
#define OFF_GD    0          // G half [m<120][e] pitch 136 (32640) / D half [e<128][128] pitch 128 (32768)
#define OFF_NEH   32768      // ne half [p<8][e] pitch 136 = 2176
#define OFF_W     34944      // w2b half [e][d] pitch 136 = 34816
#define OFF_WN    69760      // Wn  half [dout][e] pitch 136 = 34816
#define OFF_WA    104576     // wa  half [e][16] pitch 16 = 4096
#define OFF_DIFF  108672     // diff half [m<120][16] pitch 16 = 3840
#define OFF_XI    112512     // 8x8 f32 = 256
#define OFF_IDS   112768     // 8 int = 32
#define SMEM_SZ   112800

// ---------------- prep / norm / winner kernels ---------------------------------
__global__ void prep_kernel(const float* ng, const float* nb_, const float* nm, const float* nv,
                            const float* c1w, const float* c1b,
                            const float* g2a, const float* b2a, const float* m2a, const float* v2a,
                            const float* w2a,
                            const float* g2b, const float* b2b, const float* m2b, const float* v2b,
                            const float* fw, const float* fb)
{
    int d = threadIdx.x;
    if (d < CIN) {
        float s = ng[d] * rsqrtf(nv[d] + EPS);
        d_sn[d]  = s;
        d_shn[d] = nb_[d] - nm[d] * s;
    }
    float s2b = g2b[d] * rsqrtf(v2b[d] + EPS);
    float t2b = b2b[d] - m2b[d] * s2b;
    float cst = 0.f;
    #pragma unroll
    for (int c = 0; c < CIN; c++) {
        float sc = g2a[c] * rsqrtf(v2a[c] + EPS);
        float sh = b2a[c] - m2a[c] * sc;
        d_waf[d * CIN + c] = w2a[d * CIN + c] * sc * s2b;
        cst += w2a[d * CIN + c] * sh;
    }
    d_bf[d] = cst * s2b + t2b;
    #pragma unroll
    for (int c = 0; c < CIN; c++) {
        float acc = 0.f;
        for (int e = 0; e < DCH; e++)
            acc += fw[d * (2 * DCH) + e] * c1w[e * CIN + c];
        d_wpe[d * CIN + c] = acc;
    }
    float ab = 0.f;
    for (int e = 0; e < DCH; e++)
        ab += fw[d * (2 * DCH) + e] * c1b[e];
    d_be[d] = ab + fb[d];
}

__global__ void norm_kernel(const float* pc)
{
    int t = blockIdx.x * blockDim.x + threadIdx.x;
    if (t >= NPTS * 8) return;
    int n = t >> 3, c = t & 7;
    float v = 0.f;
    if (c < CIN) v = pc[n * CIN + c] * d_sn[c] + d_shn[c];
    d_xn[t] = v;
}

__global__ void winit_kernel()
{
    int t = blockIdx.x * blockDim.x + threadIdx.x;
    if (t < HW) d_winner[t] = -1;
    if (t == 0) d_live_count = 0;
}

__global__ void wscat_kernel(const int* px, const int* py)
{
    int n = blockIdx.x * blockDim.x + threadIdx.x;
    if (n >= NPTS) return;
    atomicMax(&d_winner[py[n] * WW + px[n]], n);
}

__global__ void compact_kernel()
{
    int t = blockIdx.x * blockDim.x + threadIdx.x;
    if (t >= HW) return;
    int w = d_winner[t];
    if (w >= 0) {
        int p = atomicAdd(&d_live_count, 1);
        d_live[p] = w;
    }
}

// ---------------- main kernel: 3 GEMMs on HMMA ---------------------------------
__global__ void __launch_bounds__(256, 2)
main_kernel(const float* __restrict__ w2b, const float* __restrict__ fw,
            const int* __restrict__ nbr)
{
    extern __shared__ char smem[];
    const uint32_t smb = smem_u32(smem);
    __half* G_s  = (__half*)(smem + OFF_GD);     // [m][e] pitch 136
    __half* D_h  = (__half*)(smem + OFF_GD);     // [e][p*16+k] pitch 128
    __half* ne_h = (__half*)(smem + OFF_NEH);    // [p][e] pitch 136
    __half* W_s  = (__half*)(smem + OFF_W);      // [e][d] pitch 136
    __half* Wn_s = (__half*)(smem + OFF_WN);     // [dout][e] pitch 136
    __half* Wa_s = (__half*)(smem + OFF_WA);     // [e][16] pitch 16
    float*  xi_s = (float*)(smem + OFF_XI);
    int*    ids  = (int*)(smem + OFF_IDS);

    const int tid  = threadIdx.x;
    const int wid  = tid >> 5;
    const int lane = tid & 31;
    const int tg   = lane & 3;

    // ---- prologue: weights into SMEM ----
    for (int i = tid; i < DCH * DCH; i += 256) {
        int e = i >> 7, d = i & 127;
        W_s[e * PITCH + d] = __float2half_rn(w2b[i]);
    }
    for (int i = tid; i < DCH * DCH; i += 256) {
        int dout = i >> 7, e = i & 127;
        Wn_s[dout * PITCH + e] = __float2half_rn(fw[dout * (2 * DCH) + DCH + e]);
    }
    for (int i = tid; i < DCH * 16; i += 256) {
        int e = i >> 4, k = i & 15;
        Wa_s[i] = (k < CIN) ? __float2half_rn(d_waf[e * CIN + k]) : __float2half_rn(0.f);
    }

    // per-thread fragment-row constants
    const int eLo = 16 * wid + (lane >> 2);
    const int eHi = eLo + 8;
    const float bfLo = d_bf[eLo], bfHi = d_bf[eHi];
    const float bevLo = d_be[eLo], bevHi = d_be[eHi];
    float wpeLo[CIN], wpeHi[CIN];
    #pragma unroll
    for (int c = 0; c < CIN; c++) { wpeLo[c] = d_wpe[eLo * CIN + c]; wpeHi[c] = d_wpe[eHi * CIN + c]; }

    // ldmatrix bases
    const uint32_t aW  = smb + OFF_W  + (((16 * wid + (lane & 15)) * PITCH + ((lane >> 4) << 3)) << 1);
    const uint32_t aWn = smb + OFF_WN + (((16 * wid + (lane & 15)) * PITCH + ((lane >> 4) << 3)) << 1);
    const uint32_t aWa = smb + OFF_WA + (((16 * wid + (lane & 15)) * 16 + ((lane >> 4) << 3)) << 1);
    const uint32_t bRowX4 = ((lane >> 4) << 3) + (lane & 7);
    const uint32_t colh   = ((lane >> 3) & 1) << 3;
    const uint32_t bG4 = smb + OFF_GD   + ((bRowX4 * PITCH + colh) << 1);
    const uint32_t bG2 = smb + OFF_GD   + (((112 + (lane & 7)) * PITCH + colh) << 1);
    const uint32_t bDf = smb + OFF_DIFF + (((lane & 7) * 16 + colh) << 1);
    const uint32_t bNe = smb + OFF_NEH  + (((lane & 7) * PITCH + colh) << 1);

    __syncthreads();

    uint32_t wa4[4];
    ldsm_x4(wa4, aWa);        // wa fragment is constant for whole kernel

    const int cnt = d_live_count;

    for (int base = blockIdx.x * PTILE; base < cnt; base += gridDim.x * PTILE) {
        const int np = min(PTILE, cnt - base);

        if (tid < PTILE) {
            int idx = base + tid;
            if (idx >= cnt) idx = cnt - 1;
            ids[tid] = d_live[idx];
        }
        __syncthreads();

        // stage neighbor diffs (fp16, k-padded to 16) + center points
        if (tid < MROWS) {
            int p = tid / KK, k = tid - p * KK;
            int n = ids[p];
            int j = nbr[n * KNBR + 1 + k];
            float4 a0 = ((const float4*)&d_xn[j * 8])[0];
            float4 b0 = ((const float4*)&d_xn[n * 8])[0];
            __half2 h01 = __floats2half2_rn(a0.x - b0.x, a0.y - b0.y);
            __half2 h23 = __floats2half2_rn(a0.z - b0.z, a0.w - b0.w);
            float d4 = d_xn[j * 8 + 4] - d_xn[n * 8 + 4];
            __half2 h45 = __floats2half2_rn(d4, 0.f);
            uint4 v;
            v.x = *(uint32_t*)&h01; v.y = *(uint32_t*)&h23; v.z = *(uint32_t*)&h45; v.w = 0u;
            ((uint4*)(smem + OFF_DIFF))[tid * 2]     = v;
            ((uint4*)(smem + OFF_DIFF))[tid * 2 + 1] = make_uint4(0u, 0u, 0u, 0u);
        } else if (tid < MROWS + PTILE) {
            int p = tid - MROWS;
            int n = ids[p];
            ((float4*)&xi_s[p * 8])[0] = ((const float4*)&d_xn[n * 8])[0];
            ((float4*)&xi_s[p * 8])[1] = ((const float4*)&d_xn[n * 8])[1];
        }
        __syncthreads();

        // phase 1: pre = wa . diff + bf (HMMA, k=16), gelu on fragments, store G fp16
        #pragma unroll
        for (int nb = 0; nb < 15; nb++) {
            uint32_t bd[2];
            ldsm_x2(bd, bDf + nb * 256);
            float pa[4] = {bfLo, bfLo, bfHi, bfHi};
            mma16816(pa, wa4, bd);
            int m0 = nb * 8 + tg * 2;
            G_s[m0 * PITCH + eLo]       = __float2half_rn(gelu_f(pa[0]));
            G_s[(m0 + 1) * PITCH + eLo] = __float2half_rn(gelu_f(pa[1]));
            G_s[m0 * PITCH + eHi]       = __float2half_rn(gelu_f(pa[2]));
            G_s[(m0 + 1) * PITCH + eHi] = __float2half_rn(gelu_f(pa[3]));
        }
        __syncthreads();

        // phase 2: D[e,m] = w2b . G^T  (HMMA)
        float acc[15][4];
        #pragma unroll
        for (int nb = 0; nb < 15; nb++)
            #pragma unroll
            for (int j = 0; j < 4; j++) acc[nb][j] = 0.f;

        #pragma unroll
        for (int kt = 0; kt < 8; kt++) {
            uint32_t a[4];
            ldsm_x4(a, aW + kt * 32);
            #pragma unroll
            for (int q = 0; q < 7; q++) {
                uint32_t bg[4];
                ldsm_x4(bg, bG4 + q * (16 * PITCH * 2) + kt * 32);
                mma16816(acc[2 * q],     a, bg);
                mma16816(acc[2 * q + 1], a, bg + 2);
            }
            uint32_t b2[2];
            ldsm_x2(b2, bG2 + kt * 32);
            mma16816(acc[14], a, b2);
        }
        __syncthreads();   // all warps done reading G before overwriting as D_h

        // store D fragments fp16 into padded (p*16+k) layout, pitch 128
        {
            #pragma unroll
            for (int nb = 0; nb < 15; nb++) {
                int m0 = nb * 8 + tg * 2;
                int p0 = m0 / KK,        k0 = m0 - p0 * KK;
                int p1 = (m0 + 1) / KK,  k1 = (m0 + 1) - p1 * KK;
                D_h[eLo * 128 + p0 * 16 + k0] = __float2half_rn(acc[nb][0]);
                D_h[eLo * 128 + p1 * 16 + k1] = __float2half_rn(acc[nb][1]);
                D_h[eHi * 128 + p0 * 16 + k0] = __float2half_rn(acc[nb][2]);
                D_h[eHi * 128 + p1 * 16 + k1] = __float2half_rn(acc[nb][3]);
            }
        }
        __syncthreads();

        // epilogue A: max over 15 neighbors -> ne_h[p][e] fp16
        #pragma unroll
        for (int j = 0; j < 4; j++) {
            int pi = tid + 256 * j;
            int e = pi >> 3, p = pi & 7;
            const __half2* row = (const __half2*)(D_h + e * 128 + p * 16);
            __half2 m2 = row[0];
            #pragma unroll
            for (int k = 1; k < 7; k++) m2 = __hmax2(m2, row[k]);
            float v = fmaxf(__low2float(m2), __high2float(m2));
            v = fmaxf(v, __half2float(D_h[e * 128 + p * 16 + 14]));
            ne_h[p * PITCH + e] = __float2half_rn(v);
        }
        __syncthreads();

        // epilogue B: feats[dout,p] = Wn . ne (HMMA) + be + Wp.xi
        {
            float f2[4] = {0.f, 0.f, 0.f, 0.f};
            #pragma unroll
            for (int kt = 0; kt < 8; kt++) {
                uint32_t a4[4], b2[2];
                ldsm_x4(a4, aWn + kt * 32);
                ldsm_x2(b2, bNe + kt * 32);
                mma16816(f2, a4, b2);
            }
            int p0 = tg * 2, p1 = p0 + 1;
            float uLo0 = bevLo, uLo1 = bevLo, uHi0 = bevHi, uHi1 = bevHi;
            #pragma unroll
            for (int c = 0; c < CIN; c++) {
                float x0 = xi_s[p0 * 8 + c], x1 = xi_s[p1 * 8 + c];
                uLo0 = fmaf(wpeLo[c], x0, uLo0);
                uLo1 = fmaf(wpeLo[c], x1, uLo1);
                uHi0 = fmaf(wpeHi[c], x0, uHi0);
                uHi1 = fmaf(wpeHi[c], x1, uHi1);
            }
            int n0 = ids[p0], n1 = ids[p1];
            if (p0 < np) {
                d_feats[n0 * DCH + eLo] = f2[0] + uLo0;
                d_feats[n0 * DCH + eHi] = f2[2] + uHi0;
            }
            if (p1 < np) {
                d_feats[n1 * DCH + eLo] = f2[1] + uLo1;
                d_feats[n1 * DCH + eHi] = f2[3] + uHi1;
            }
        }
        __syncthreads();
    }
}

// ---------------- emit ---------------------------------------------------------
#define EM_TILE 64
__global__ void emit_kernel(float* __restrict__ out)
{
    __shared__ float s[EM_TILE * 129];
    const int pixbase = blockIdx.x * EM_TILE;
    const int tid = threadIdx.x;

    for (int i = tid; i < EM_TILE * DCH; i += blockDim.x) {
        int p = i >> 7, d = i & 127;
        int w = d_winner[pixbase + p];
        s[p * 129 + d] = (w >= 0) ? d_feats[w * DCH + d] : -1.0f;
    }
    __syncthreads();
    for (int i = tid; i < EM_TILE * DCH; i += blockDim.x) {
        int d = i >> 6, p = i & 63;
        out[d * HW + pixbase + p] = s[p * 129 + d];
    }
}

// ---------------- launch --------------------------------------------------------
extern "C" void kernel_launch(void* const* d_in, const int* in_sizes, int n_in,
                              void* d_out, int out_size)
{
    const float* pc        = (const float*)d_in[0];
    const int*   neighbors = (const int*)  d_in[1];
    const int*   px        = (const int*)  d_in[2];
    const int*   py        = (const int*)  d_in[3];
    const float* ng        = (const float*)d_in[4];
    const float* nb_       = (const float*)d_in[5];
    const float* nm        = (const float*)d_in[6];
    const float* nv        = (const float*)d_in[7];
    const float* c1w       = (const float*)d_in[8];
    const float* c1b       = (const float*)d_in[9];
    const float* g2a       = (const float*)d_in[10];
    const float* b2a       = (const float*)d_in[11];
    const float* m2a       = (const float*)d_in[12];
    const float* v2a       = (const float*)d_in[13];
    const float* w2a       = (const float*)d_in[14];
    const float* g2b       = (const float*)d_in[15];
    const float* b2b       = (const float*)d_in[16];
    const float* m2b       = (const float*)d_in[17];
    const float* v2b       = (const float*)d_in[18];
    const float* w2b       = (const float*)d_in[19];
    const float* fw        = (const float*)d_in[20];
    const float* fb        = (const float*)d_in[21];
    float* out = (float*)d_out;

    cudaFuncSetAttribute(main_kernel, cudaFuncAttributeMaxDynamicSharedMemorySize, SMEM_SZ);

    prep_kernel<<<1, 128>>>(ng, nb_, nm, nv, c1w, c1b,
                            g2a, b2a, m2a, v2a, w2a,
                            g2b, b2b, m2b, v2b, fw, fb);
    norm_kernel<<<(NPTS * 8) / 256, 256>>>(pc);
    winit_kernel<<<HW / 256, 256>>>();
    wscat_kernel<<<NPTS / 256, 256>>>(px, py);
    compact_kernel<<<HW / 256, 256>>>();
    main_kernel<<<296, 256, SMEM_SZ>>>(w2b, fw, neighbors);
    emit_kernel<<<HW / EM_TILE, 256>>>(out);
}

// round 7
// speedup vs baseline: 5.0437x; 1.4096x over previous
#include <cuda_runtime.h>
#include <cuda_fp16.h>
#include <math.h>
#include <stdint.h>

// Problem constants
#define NPTS   65536
#define CIN    5
#define DCH    128
#define KNBR   16
#define KK     15
#define HH     64
#define WW     1024
#define HW     (HH*WW)
#define EPS    1e-5f

#define PTILE  8            // points per CTA tile
#define MROWS  (PTILE*KK)   // 120 G rows, row m = k*8 + p (neighbor-major!)
#define PITCH  136          // fp16 pitch (272B, 16B-aligned rows) for ldsm tiles

// ---------------- device scratch ----------------------------------------------
__device__ float d_xn[NPTS * 8];
__device__ float d_feats[NPTS * DCH];
__device__ int   d_winner[HW];
__device__ int   d_live[HW];
__device__ int   d_live_count;

__device__ float d_waf[DCH * CIN];
__device__ float d_bf[DCH];
__device__ float d_wpe[DCH * CIN];
__device__ float d_be[DCH];
__device__ float d_sn[CIN];
__device__ float d_shn[CIN];

// ---------------- PTX helpers -------------------------------------------------
__device__ __forceinline__ uint32_t smem_u32(const void* p) {
    uint32_t a;
    asm("{ .reg .u64 t; cvta.to.shared.u64 t, %1; cvt.u32.u64 %0, t; }" : "=r"(a) : "l"(p));
    return a;
}
__device__ __forceinline__ void ldsm_x4(uint32_t* r, uint32_t addr) {
    asm volatile("ldmatrix.sync.aligned.m8n8.x4.shared.b16 {%0,%1,%2,%3}, [%4];"
        : "=r"(r[0]), "=r"(r[1]), "=r"(r[2]), "=r"(r[3]) : "r"(addr));
}
__device__ __forceinline__ void ldsm_x2(uint32_t* r, uint32_t addr) {
    asm volatile("ldmatrix.sync.aligned.m8n8.x2.shared.b16 {%0,%1}, [%2];"
        : "=r"(r[0]), "=r"(r[1]) : "r"(addr));
}
__device__ __forceinline__ void mma16816(float* d, const uint32_t* a, const uint32_t* b) {
    asm volatile("mma.sync.aligned.m16n8k16.row.col.f32.f16.f16.f32 "
        "{%0,%1,%2,%3}, {%4,%5,%6,%7}, {%8,%9}, {%0,%1,%2,%3};"
        : "+f"(d[0]), "+f"(d[1]), "+f"(d[2]), "+f"(d[3])
        : "r"(a[0]), "r"(a[1]), "r"(a[2]), "r"(a[3]), "r"(b[0]), "r"(b[1]));
}
// gelu via tanh.approx (single MUFU-class op)
__device__ __forceinline__ float gelu_f(float x) {
    float z = x * fmaf(0.035677408f, x * x, 0.79788456f);
    float t;
    asm("tanh.approx.f32 %0, %1;" : "=f"(t) : "f"(z));
    float hx = 0.5f * x;
    return fmaf(hx, t, hx);
}

// ---------------- SMEM layout (bytes) -----------------------------------------
#define OFF_G     0          // G half [m<120][e] pitch 136 = 32640
#define OFF_NEH   32768      // ne half [p<8][e] pitch 136 = 2176
#define OFF_W     34944      // w2b half [e][d] pitch 136 = 34816
#define OFF_WN    69760      // Wn  half [dout][e] pitch 136 = 34816
#define OFF_WA    104576     // wa  half [e][16] pitch 16 = 4096
#define OFF_DIFF  108672     // diff half [m<120][16] pitch 16 = 3840
#define OFF_XI    112512     // 8x8 f32 = 256
#define OFF_IDS   112768     // 8 int = 32
#define SMEM_SZ   112800

// ---------------- prep / norm / winner kernels ---------------------------------
__global__ void prep_kernel(const float* ng, const float* nb_, const float* nm, const float* nv,
                            const float* c1w, const float* c1b,
                            const float* g2a, const float* b2a, const float* m2a, const float* v2a,
                            const float* w2a,
                            const float* g2b, const float* b2b, const float* m2b, const float* v2b,
                            const float* fw, const float* fb)
{
    int d = threadIdx.x;
    if (d < CIN) {
        float s = ng[d] * rsqrtf(nv[d] + EPS);
        d_sn[d]  = s;
        d_shn[d] = nb_[d] - nm[d] * s;
    }
    float s2b = g2b[d] * rsqrtf(v2b[d] + EPS);
    float t2b = b2b[d] - m2b[d] * s2b;
    float cst = 0.f;
    #pragma unroll
    for (int c = 0; c < CIN; c++) {
        float sc = g2a[c] * rsqrtf(v2a[c] + EPS);
        float sh = b2a[c] - m2a[c] * sc;
        d_waf[d * CIN + c] = w2a[d * CIN + c] * sc * s2b;
        cst += w2a[d * CIN + c] * sh;
    }
    d_bf[d] = cst * s2b + t2b;
    #pragma unroll
    for (int c = 0; c < CIN; c++) {
        float acc = 0.f;
        for (int e = 0; e < DCH; e++)
            acc += fw[d * (2 * DCH) + e] * c1w[e * CIN + c];
        d_wpe[d * CIN + c] = acc;
    }
    float ab = 0.f;
    for (int e = 0; e < DCH; e++)
        ab += fw[d * (2 * DCH) + e] * c1b[e];
    d_be[d] = ab + fb[d];
}

__global__ void norm_kernel(const float* pc)
{
    int t = blockIdx.x * blockDim.x + threadIdx.x;
    if (t >= NPTS * 8) return;
    int n = t >> 3, c = t & 7;
    float v = 0.f;
    if (c < CIN) v = pc[n * CIN + c] * d_sn[c] + d_shn[c];
    d_xn[t] = v;
}

__global__ void winit_kernel()
{
    int t = blockIdx.x * blockDim.x + threadIdx.x;
    if (t < HW) d_winner[t] = -1;
    if (t == 0) d_live_count = 0;
}

__global__ void wscat_kernel(const int* px, const int* py)
{
    int n = blockIdx.x * blockDim.x + threadIdx.x;
    if (n >= NPTS) return;
    atomicMax(&d_winner[py[n] * WW + px[n]], n);
}

__global__ void compact_kernel()
{
    int t = blockIdx.x * blockDim.x + threadIdx.x;
    if (t >= HW) return;
    int w = d_winner[t];
    if (w >= 0) {
        int p = atomicAdd(&d_live_count, 1);
        d_live[p] = w;
    }
}

// ---------------- main kernel: 3 GEMMs on HMMA, register max ------------------
__global__ void __launch_bounds__(256, 2)
main_kernel(const float* __restrict__ w2b, const float* __restrict__ fw,
            const int* __restrict__ nbr)
{
    extern __shared__ char smem[];
    const uint32_t smb = smem_u32(smem);
    __half* G_s  = (__half*)(smem + OFF_G);      // [m = k*8+p][e] pitch 136
    __half* ne_h = (__half*)(smem + OFF_NEH);    // [p][e] pitch 136
    __half* W_s  = (__half*)(smem + OFF_W);      // [e][d] pitch 136
    __half* Wn_s = (__half*)(smem + OFF_WN);     // [dout][e] pitch 136
    __half* Wa_s = (__half*)(smem + OFF_WA);     // [e][16] pitch 16
    float*  xi_s = (float*)(smem + OFF_XI);
    int*    ids  = (int*)(smem + OFF_IDS);

    const int tid  = threadIdx.x;
    const int wid  = tid >> 5;
    const int lane = tid & 31;
    const int tg   = lane & 3;

    // ---- prologue: weights into SMEM ----
    for (int i = tid; i < DCH * DCH; i += 256) {
        int e = i >> 7, d = i & 127;
        W_s[e * PITCH + d] = __float2half_rn(w2b[i]);
    }
    for (int i = tid; i < DCH * DCH; i += 256) {
        int dout = i >> 7, e = i & 127;
        Wn_s[dout * PITCH + e] = __float2half_rn(fw[dout * (2 * DCH) + DCH + e]);
    }
    for (int i = tid; i < DCH * 16; i += 256) {
        int e = i >> 4, k = i & 15;
        Wa_s[i] = (k < CIN) ? __float2half_rn(d_waf[e * CIN + k]) : __float2half_rn(0.f);
    }

    // per-thread fragment-row constants
    const int eLo = 16 * wid + (lane >> 2);
    const int eHi = eLo + 8;
    const float bfLo = d_bf[eLo], bfHi = d_bf[eHi];
    const float bevLo = d_be[eLo], bevHi = d_be[eHi];
    float wpeLo[CIN], wpeHi[CIN];
    #pragma unroll
    for (int c = 0; c < CIN; c++) { wpeLo[c] = d_wpe[eLo * CIN + c]; wpeHi[c] = d_wpe[eHi * CIN + c]; }

    // ldmatrix bases
    const uint32_t aW  = smb + OFF_W  + (((16 * wid + (lane & 15)) * PITCH + ((lane >> 4) << 3)) << 1);
    const uint32_t aWn = smb + OFF_WN + (((16 * wid + (lane & 15)) * PITCH + ((lane >> 4) << 3)) << 1);
    const uint32_t aWa = smb + OFF_WA + (((16 * wid + (lane & 15)) * 16 + ((lane >> 4) << 3)) << 1);
    const uint32_t bRowX4 = ((lane >> 4) << 3) + (lane & 7);
    const uint32_t colh   = ((lane >> 3) & 1) << 3;
    const uint32_t bG4 = smb + OFF_G    + ((bRowX4 * PITCH + colh) << 1);
    const uint32_t bG2 = smb + OFF_G    + (((112 + (lane & 7)) * PITCH + colh) << 1);
    const uint32_t bDf = smb + OFF_DIFF + (((lane & 7) * 16 + colh) << 1);
    const uint32_t bNe = smb + OFF_NEH  + (((lane & 7) * PITCH + colh) << 1);

    __syncthreads();

    uint32_t wa4[4];
    ldsm_x4(wa4, aWa);        // wa fragment constant for whole kernel

    const int cnt = d_live_count;

    for (int base = blockIdx.x * PTILE; base < cnt; base += gridDim.x * PTILE) {
        const int np = min(PTILE, cnt - base);

        if (tid < PTILE) {
            int idx = base + tid;
            if (idx >= cnt) idx = cnt - 1;
            ids[tid] = d_live[idx];
        }
        __syncthreads();

        // stage neighbor diffs, row m = k*8 + p (neighbor-major), fp16 k-padded 16
        if (tid < MROWS) {
            int k = tid >> 3, p = tid & 7;
            int n = ids[p];
            int j = nbr[n * KNBR + 1 + k];
            float4 a0 = ((const float4*)&d_xn[j * 8])[0];
            float4 b0 = ((const float4*)&d_xn[n * 8])[0];
            __half2 h01 = __floats2half2_rn(a0.x - b0.x, a0.y - b0.y);
            __half2 h23 = __floats2half2_rn(a0.z - b0.z, a0.w - b0.w);
            float d4 = d_xn[j * 8 + 4] - d_xn[n * 8 + 4];
            __half2 h45 = __floats2half2_rn(d4, 0.f);
            uint4 v;
            v.x = *(uint32_t*)&h01; v.y = *(uint32_t*)&h23; v.z = *(uint32_t*)&h45; v.w = 0u;
            ((uint4*)(smem + OFF_DIFF))[tid * 2]     = v;
            ((uint4*)(smem + OFF_DIFF))[tid * 2 + 1] = make_uint4(0u, 0u, 0u, 0u);
        } else if (tid < MROWS + PTILE) {
            int p = tid - MROWS;
            int n = ids[p];
            ((float4*)&xi_s[p * 8])[0] = ((const float4*)&d_xn[n * 8])[0];
            ((float4*)&xi_s[p * 8])[1] = ((const float4*)&d_xn[n * 8])[1];
        }
        __syncthreads();

        // phase 1: pre = wa . diff + bf (HMMA k=16), gelu on fragments, store G fp16
        #pragma unroll
        for (int nb = 0; nb < 15; nb++) {
            uint32_t bd[2];
            ldsm_x2(bd, bDf + nb * 256);
            float pa[4] = {bfLo, bfLo, bfHi, bfHi};
            mma16816(pa, wa4, bd);
            int m0 = nb * 8 + tg * 2;
            G_s[m0 * PITCH + eLo]       = __float2half_rn(gelu_f(pa[0]));
            G_s[(m0 + 1) * PITCH + eLo] = __float2half_rn(gelu_f(pa[1]));
            G_s[m0 * PITCH + eHi]       = __float2half_rn(gelu_f(pa[2]));
            G_s[(m0 + 1) * PITCH + eHi] = __float2half_rn(gelu_f(pa[3]));
        }
        __syncthreads();

        // phase 2: D[e, m] = w2b . G^T  (HMMA). m = k*8+p, so thread tg's
        // columns {2tg, 2tg+1} within every 8-block are points 2tg, 2tg+1 for
        // neighbor k = block index. Max over k is a pure register reduction.
        float acc[15][4];
        #pragma unroll
        for (int k = 0; k < 15; k++)
            #pragma unroll
            for (int j = 0; j < 4; j++) acc[k][j] = 0.f;

        #pragma unroll
        for (int kt = 0; kt < 8; kt++) {
            uint32_t a[4];
            ldsm_x4(a, aW + kt * 32);
            #pragma unroll
            for (int q = 0; q < 7; q++) {
                uint32_t bg[4];
                ldsm_x4(bg, bG4 + q * (16 * PITCH * 2) + kt * 32);
                mma16816(acc[2 * q],     a, bg);
                mma16816(acc[2 * q + 1], a, bg + 2);
            }
            uint32_t b2[2];
            ldsm_x2(b2, bG2 + kt * 32);
            mma16816(acc[14], a, b2);
        }

        // in-register max over neighbors k
        {
            float mLo0 = acc[0][0], mLo1 = acc[0][1], mHi0 = acc[0][2], mHi1 = acc[0][3];
            #pragma unroll
            for (int k = 1; k < 15; k++) {
                mLo0 = fmaxf(mLo0, acc[k][0]);
                mLo1 = fmaxf(mLo1, acc[k][1]);
                mHi0 = fmaxf(mHi0, acc[k][2]);
                mHi1 = fmaxf(mHi1, acc[k][3]);
            }
            int p0 = tg * 2, p1 = p0 + 1;
            ne_h[p0 * PITCH + eLo] = __float2half_rn(mLo0);
            ne_h[p1 * PITCH + eLo] = __float2half_rn(mLo1);
            ne_h[p0 * PITCH + eHi] = __float2half_rn(mHi0);
            ne_h[p1 * PITCH + eHi] = __float2half_rn(mHi1);
        }
        __syncthreads();

        // epilogue: feats[dout,p] = Wn . ne (HMMA) + be + Wp.xi
        {
            float f2[4] = {0.f, 0.f, 0.f, 0.f};
            #pragma unroll
            for (int kt = 0; kt < 8; kt++) {
                uint32_t a4[4], b2[2];
                ldsm_x4(a4, aWn + kt * 32);
                ldsm_x2(b2, bNe + kt * 32);
                mma16816(f2, a4, b2);
            }
            int p0 = tg * 2, p1 = p0 + 1;
            float uLo0 = bevLo, uLo1 = bevLo, uHi0 = bevHi, uHi1 = bevHi;
            #pragma unroll
            for (int c = 0; c < CIN; c++) {
                float x0 = xi_s[p0 * 8 + c], x1 = xi_s[p1 * 8 + c];
                uLo0 = fmaf(wpeLo[c], x0, uLo0);
                uLo1 = fmaf(wpeLo[c], x1, uLo1);
                uHi0 = fmaf(wpeHi[c], x0, uHi0);
                uHi1 = fmaf(wpeHi[c], x1, uHi1);
            }
            int n0 = ids[p0], n1 = ids[p1];
            if (p0 < np) {
                d_feats[n0 * DCH + eLo] = f2[0] + uLo0;
                d_feats[n0 * DCH + eHi] = f2[2] + uHi0;
            }
            if (p1 < np) {
                d_feats[n1 * DCH + eLo] = f2[1] + uLo1;
                d_feats[n1 * DCH + eHi] = f2[3] + uHi1;
            }
        }
        __syncthreads();
    }
}

// ---------------- emit ---------------------------------------------------------
#define EM_TILE 64
__global__ void emit_kernel(float* __restrict__ out)
{
    __shared__ float s[EM_TILE * 129];
    const int pixbase = blockIdx.x * EM_TILE;
    const int tid = threadIdx.x;

    for (int i = tid; i < EM_TILE * DCH; i += blockDim.x) {
        int p = i >> 7, d = i & 127;
        int w = d_winner[pixbase + p];
        s[p * 129 + d] = (w >= 0) ? d_feats[w * DCH + d] : -1.0f;
    }
    __syncthreads();
    for (int i = tid; i < EM_TILE * DCH; i += blockDim.x) {
        int d = i >> 6, p = i & 63;
        out[d * HW + pixbase + p] = s[p * 129 + d];
    }
}

// ---------------- launch --------------------------------------------------------
extern "C" void kernel_launch(void* const* d_in, const int* in_sizes, int n_in,
                              void* d_out, int out_size)
{
    const float* pc        = (const float*)d_in[0];
    const int*   neighbors = (const int*)  d_in[1];
    const int*   px        = (const int*)  d_in[2];
    const int*   py        = (const int*)  d_in[3];
    const float* ng        = (const float*)d_in[4];
    const float* nb_       = (const float*)d_in[5];
    const float* nm        = (const float*)d_in[6];
    const float* nv        = (const float*)d_in[7];
    const float* c1w       = (const float*)d_in[8];
    const float* c1b       = (const float*)d_in[9];
    const float* g2a       = (const float*)d_in[10];
    const float* b2a       = (const float*)d_in[11];
    const float* m2a       = (const float*)d_in[12];
    const float* v2a       = (const float*)d_in[13];
    const float* w2a       = (const float*)d_in[14];
    const float* g2b       = (const float*)d_in[15];
    const float* b2b       = (const float*)d_in[16];
    const float* m2b       = (const float*)d_in[17];
    const float* v2b       = (const float*)d_in[18];
    const float* w2b       = (const float*)d_in[19];
    const float* fw        = (const float*)d_in[20];
    const float* fb        = (const float*)d_in[21];
    float* out = (float*)d_out;

    cudaFuncSetAttribute(main_kernel, cudaFuncAttributeMaxDynamicSharedMemorySize, SMEM_SZ);

    prep_kernel<<<1, 128>>>(ng, nb_, nm, nv, c1w, c1b,
                            g2a, b2a, m2a, v2a, w2a,
                            g2b, b2b, m2b, v2b, fw, fb);
    norm_kernel<<<(NPTS * 8) / 256, 256>>>(pc);
    winit_kernel<<<HW / 256, 256>>>();
    wscat_kernel<<<HW / 256, 256>>>(px, py);
    compact_kernel<<<HW / 256, 256>>>();
    main_kernel<<<296, 256, SMEM_SZ>>>(w2b, fw, neighbors);
    emit_kernel<<<HW / EM_TILE, 256>>>(out);
}

// round 8
// speedup vs baseline: 7.2169x; 1.4309x over previous
#include <cuda_runtime.h>
#include <cuda_fp16.h>
#include <math.h>
#include <stdint.h>

// Problem constants
#define NPTS   65536
#define CIN    5
#define DCH    128
#define KNBR   16
#define KK     15
#define HH     64
#define WW     1024
#define HW     (HH*WW)
#define EPS    1e-5f

#define PTILE  8            // points per CTA tile
#define MROWS  (PTILE*KK)   // 120 G rows, row m = k*8 + p (neighbor-major)
#define PITCHB 272          // byte pitch (136 halfs) for G / W / Wn / ne tiles

// ---------------- device scratch ----------------------------------------------
__device__ float d_xn[NPTS * 8];
__device__ float d_feats[NPTS * DCH];
__device__ int   d_winner[HW];
__device__ int   d_live[HW];
__device__ int   d_live_count;

__device__ float d_waf[DCH * CIN];
__device__ float d_bf[DCH];
__device__ float d_wpe[DCH * CIN];
__device__ float d_be[DCH];
__device__ float d_sn[CIN];
__device__ float d_shn[CIN];

// ---------------- PTX helpers -------------------------------------------------
__device__ __forceinline__ uint32_t smem_u32(const void* p) {
    uint32_t a;
    asm("{ .reg .u64 t; cvta.to.shared.u64 t, %1; cvt.u32.u64 %0, t; }" : "=r"(a) : "l"(p));
    return a;
}
__device__ __forceinline__ void ldsm_x4(uint32_t* r, uint32_t addr) {
    asm volatile("ldmatrix.sync.aligned.m8n8.x4.shared.b16 {%0,%1,%2,%3}, [%4];"
        : "=r"(r[0]), "=r"(r[1]), "=r"(r[2]), "=r"(r[3]) : "r"(addr));
}
__device__ __forceinline__ void ldsm_x2(uint32_t* r, uint32_t addr) {
    asm volatile("ldmatrix.sync.aligned.m8n8.x2.shared.b16 {%0,%1}, [%2];"
        : "=r"(r[0]), "=r"(r[1]) : "r"(addr));
}
__device__ __forceinline__ void ldsm_x1(uint32_t* r, uint32_t addr) {
    asm volatile("ldmatrix.sync.aligned.m8n8.x1.shared.b16 {%0}, [%1];"
        : "=r"(r[0]) : "r"(addr));
}
__device__ __forceinline__ void mma16816(float* d, const uint32_t* a, const uint32_t* b) {
    asm volatile("mma.sync.aligned.m16n8k16.row.col.f32.f16.f16.f32 "
        "{%0,%1,%2,%3}, {%4,%5,%6,%7}, {%8,%9}, {%0,%1,%2,%3};"
        : "+f"(d[0]), "+f"(d[1]), "+f"(d[2]), "+f"(d[3])
        : "r"(a[0]), "r"(a[1]), "r"(a[2]), "r"(a[3]), "r"(b[0]), "r"(b[1]));
}
__device__ __forceinline__ void mma16808(float* d, const uint32_t* a, uint32_t b) {
    asm volatile("mma.sync.aligned.m16n8k8.row.col.f32.f16.f16.f32 "
        "{%0,%1,%2,%3}, {%4,%5}, {%6}, {%0,%1,%2,%3};"
        : "+f"(d[0]), "+f"(d[1]), "+f"(d[2]), "+f"(d[3])
        : "r"(a[0]), "r"(a[1]), "r"(b));
}
__device__ __forceinline__ float gelu_f(float x) {
    float z = x * fmaf(0.035677408f, x * x, 0.79788456f);
    float t;
    asm("tanh.approx.f32 %0, %1;" : "=f"(t) : "f"(z));
    float hx = 0.5f * x;
    return fmaf(hx, t, hx);
}

// ---------------- SMEM layout (bytes) -----------------------------------------
#define OFF_G     0          // G half [m<120][e<128] pitch 136h = 32640
#define OFF_W     32768      // w2b half [e][d] pitch 136h = 34816
#define OFF_WN    67584      // Wn half [dout][e] pitch 136h = 34816
#define OFF_WA    102400     // wa half [e][8] pitch 8h = 2048
#define OFF_DIFF0 104448     // diff half [m<120][8] = 1920
#define OFF_DIFF1 106368
#define OFF_NE0   108288     // ne half [p<8][e] pitch 136h = 2176 (k 0..7 partial)
#define OFF_NE1   110464     //                                (k 8..14 partial)
#define OFF_XI0   112640     // 8x8 f32 = 256
#define OFF_XI1   112896
#define OFF_IDS   113152     // int ids[2][8]
#define SMEM_SZ   113216

// ---------------- prep: parallel fold ------------------------------------------
__device__ __forceinline__ float blockSum(float v, float* red, int tid) {
    #pragma unroll
    for (int off = 16; off; off >>= 1) v += __shfl_down_sync(0xFFFFFFFFu, v, off);
    if ((tid & 31) == 0) red[tid >> 5] = v;
    __syncthreads();
    float r = (red[0] + red[1]) + (red[2] + red[3]);
    __syncthreads();
    return r;
}

__global__ void prep_kernel(const float* ng, const float* nb_, const float* nm, const float* nv,
                            const float* c1w, const float* c1b,
                            const float* g2a, const float* b2a, const float* m2a, const float* v2a,
                            const float* w2a,
                            const float* g2b, const float* b2b, const float* m2b, const float* v2b,
                            const float* fw, const float* fb)
{
    __shared__ float red[4];
    const int d = blockIdx.x, e = threadIdx.x;
    const float f = fw[d * (2 * DCH) + e];

    float s[6];
    #pragma unroll
    for (int c = 0; c < CIN; c++) s[c] = blockSum(f * c1w[e * CIN + c], red, e);
    s[5] = blockSum(f * c1b[e], red, e);

    if (e == 0) {
        #pragma unroll
        for (int c = 0; c < CIN; c++) d_wpe[d * CIN + c] = s[c];
        d_be[d] = s[5] + fb[d];

        float s2b = g2b[d] * rsqrtf(v2b[d] + EPS);
        float t2b = b2b[d] - m2b[d] * s2b;
        float cst = 0.f;
        #pragma unroll
        for (int c = 0; c < CIN; c++) {
            float sc = g2a[c] * rsqrtf(v2a[c] + EPS);
            float sh = b2a[c] - m2a[c] * sc;
            d_waf[d * CIN + c] = w2a[d * CIN + c] * sc * s2b;
            cst += w2a[d * CIN + c] * sh;
        }
        d_bf[d] = cst * s2b + t2b;
    }
    if (d == 0 && e < CIN) {
        float sn = ng[e] * rsqrtf(nv[e] + EPS);
        d_sn[e]  = sn;
        d_shn[e] = nb_[e] - nm[e] * sn;
    }
}

// ---------------- norm + winit merged ------------------------------------------
__global__ void norm_kernel(const float* pc)
{
    int t = blockIdx.x * blockDim.x + threadIdx.x;
    if (t < HW) d_winner[t] = -1;
    if (t == 0) d_live_count = 0;
    if (t >= NPTS * 8) return;
    int n = t >> 3, c = t & 7;
    float v = 0.f;
    if (c < CIN) v = pc[n * CIN + c] * d_sn[c] + d_shn[c];
    d_xn[t] = v;
}

__global__ void wscat_kernel(const int* px, const int* py)
{
    int n = blockIdx.x * blockDim.x + threadIdx.x;
    if (n >= NPTS) return;
    atomicMax(&d_winner[py[n] * WW + px[n]], n);
}

__global__ void compact_kernel()
{
    int t = blockIdx.x * blockDim.x + threadIdx.x;
    if (t >= HW) return;
    int w = d_winner[t];
    if (w >= 0) {
        int p = atomicAdd(&d_live_count, 1);
        d_live[p] = w;
    }
}

// ---------------- main kernel --------------------------------------------------
__global__ void __launch_bounds__(256, 2)
main_kernel(const float* __restrict__ w2b, const float* __restrict__ fw,
            const int* __restrict__ nbr)
{
    extern __shared__ char smem[];
    const uint32_t smb = smem_u32(smem);
    __half* G_s  = (__half*)(smem + OFF_G);
    __half* W_s  = (__half*)(smem + OFF_W);
    __half* Wn_s = (__half*)(smem + OFF_WN);
    __half* Wa_s = (__half*)(smem + OFF_WA);
    int*    ids_s = (int*)(smem + OFF_IDS);

    const int tid  = threadIdx.x;
    const int wid  = tid >> 5;
    const int lane = tid & 31;
    const int tg   = lane & 3;
    const int g    = lane >> 2;

    // ---- prologue: weights into SMEM ----
    for (int i = tid; i < DCH * DCH; i += 256) {
        int e = i >> 7, d = i & 127;
        W_s[e * 136 + d] = __float2half_rn(w2b[i]);
    }
    for (int i = tid; i < DCH * DCH; i += 256) {
        int dout = i >> 7, e = i & 127;
        Wn_s[dout * 136 + e] = __float2half_rn(fw[dout * (2 * DCH) + DCH + e]);
    }
    for (int i = tid; i < DCH * 8; i += 256) {
        int e = i >> 3, k = i & 7;
        Wa_s[i] = (k < CIN) ? __float2half_rn(d_waf[e * CIN + k]) : __float2half_rn(0.f);
    }

    // phase-1 / epilogue row constants (e-rows 16*wid .. +15)
    const int eLo = 16 * wid + g;
    const int eHi = eLo + 8;
    const float bfLo = d_bf[eLo], bfHi = d_bf[eHi];
    const float bevLo = d_be[eLo], bevHi = d_be[eHi];
    float wpeLo[CIN], wpeHi[CIN];
    #pragma unroll
    for (int c = 0; c < CIN; c++) { wpeLo[c] = d_wpe[eLo * CIN + c]; wpeHi[c] = d_wpe[eHi * CIN + c]; }

    // phase-2 warp mapping: eb = e-block (32 rows), mh = m-half (k subset)
    const int eb = wid & 3, mh = wid >> 2;
    const int nq = 8 - mh;          // n-blocks in this half (8 or 7)

    const uint32_t colh = ((lane >> 3) & 1) << 3;
    // ldmatrix bases
    const uint32_t aWa = smb + OFF_WA + ((16 * wid + (lane & 15)) << 4);              // pitch 16B
    const uint32_t aW2 = smb + OFF_W  + (eb * 32 + (lane & 15)) * PITCHB + (((lane >> 4) << 3) << 1);
    const uint32_t aWn = smb + OFF_WN + (16 * wid + (lane & 15)) * PITCHB + (((lane >> 4) << 3) << 1);
    const uint32_t bGm = smb + OFF_G  + (64 * mh + ((lane >> 4) << 3) + (lane & 7)) * PITCHB + (colh << 1);
    const uint32_t bG2x = smb + OFF_G + (112 + (lane & 7)) * PITCHB + (colh << 1);
    const uint32_t bDf  = smb + OFF_DIFF0 + ((lane & 7) << 4);                        // pitch 16B
    const uint32_t bNe0 = smb + OFF_NE0 + (lane & 7) * PITCHB + (colh << 1);
    const uint32_t bNe1 = bNe0 + (OFF_NE1 - OFF_NE0);

    __syncthreads();

    uint32_t wa2[2];
    ldsm_x2(wa2, aWa);              // phase-1 A fragment, constant

    const int cnt = d_live_count;
    const int stride = gridDim.x * PTILE;
    int buf = 0;

    // staging registers
    uint32_t s0 = 0, s1 = 0, s2 = 0;
    int sid = 0;
    float sx[8];

    // prefetch macro: loads tile at pbase into regs
    #define PREFETCH(pbase) do { \
        if (tid < 128) { \
            int _p = (tid < MROWS) ? (tid & 7) : (tid - MROWS); \
            int _idx = (pbase) + _p; \
            _idx = min(_idx, cnt - 1); if (_idx < 0) _idx = 0; \
            sid = d_live[_idx]; \
            if (tid < MROWS) { \
                int _k = tid >> 3; \
                int _j = nbr[sid * KNBR + 1 + _k]; \
                float4 _a0 = ((const float4*)&d_xn[_j * 8])[0]; \
                float4 _b0 = ((const float4*)&d_xn[sid * 8])[0]; \
                float _a4 = d_xn[_j * 8 + 4], _b4 = d_xn[sid * 8 + 4]; \
                __half2 _h01 = __floats2half2_rn(_a0.x - _b0.x, _a0.y - _b0.y); \
                __half2 _h23 = __floats2half2_rn(_a0.z - _b0.z, _a0.w - _b0.w); \
                __half2 _h45 = __floats2half2_rn(_a4 - _b4, 0.f); \
                s0 = *(uint32_t*)&_h01; s1 = *(uint32_t*)&_h23; s2 = *(uint32_t*)&_h45; \
            } else { \
                float4 _q0 = ((const float4*)&d_xn[sid * 8])[0]; \
                float4 _q1 = ((const float4*)&d_xn[sid * 8])[1]; \
                sx[0] = _q0.x; sx[1] = _q0.y; sx[2] = _q0.z; sx[3] = _q0.w; \
                sx[4] = _q1.x; sx[5] = _q1.y; sx[6] = _q1.z; sx[7] = _q1.w; \
            } \
        } \
    } while (0)

    PREFETCH(blockIdx.x * PTILE);

    for (int base = blockIdx.x * PTILE; base < cnt; base += stride) {
        const int np = min(PTILE, cnt - base);

        // commit staged regs to smem buffers
        if (tid < MROWS) {
            ((uint4*)(smem + OFF_DIFF0 + buf * (OFF_DIFF1 - OFF_DIFF0)))[tid] = make_uint4(s0, s1, s2, 0u);
            if (tid < PTILE) ids_s[buf * 8 + tid] = sid;
        } else if (tid < 128) {
            float* xb = (float*)(smem + OFF_XI0 + buf * (OFF_XI1 - OFF_XI0));
            int p = tid - MROWS;
            ((float4*)(xb + p * 8))[0] = make_float4(sx[0], sx[1], sx[2], sx[3]);
            ((float4*)(xb + p * 8))[1] = make_float4(sx[4], sx[5], sx[6], sx[7]);
        }
        __syncthreads();

        // prefetch next tile (overlaps with compute below)
        PREFETCH(base + stride);

        // phase 1: pre = wa . diff + bf (HMMA k=8), gelu, store G fp16
        {
            const uint32_t dfb = bDf + buf * (OFF_DIFF1 - OFF_DIFF0);
            #pragma unroll
            for (int nb = 0; nb < 15; nb++) {
                uint32_t bd;
                ldsm_x1(&bd, dfb + nb * 128);
                float pa[4] = {bfLo, bfLo, bfHi, bfHi};
                mma16808(pa, wa2, bd);
                int m0 = nb * 8 + tg * 2;
                G_s[m0 * 136 + eLo]       = __float2half_rn(gelu_f(pa[0]));
                G_s[(m0 + 1) * 136 + eLo] = __float2half_rn(gelu_f(pa[1]));
                G_s[m0 * 136 + eHi]       = __float2half_rn(gelu_f(pa[2]));
                G_s[(m0 + 1) * 136 + eHi] = __float2half_rn(gelu_f(pa[3]));
            }
        }
        __syncthreads();

        // phase 2: D[e,m] = w2b . G^T, warp = (eb, mh); B shared by 2 A-blocks
        float acc[2][8][4];
        #pragma unroll
        for (int t = 0; t < 2; t++)
            #pragma unroll
            for (int q = 0; q < 8; q++)
                #pragma unroll
                for (int j = 0; j < 4; j++) acc[t][q][j] = 0.f;

        if (mh == 0) {
            #pragma unroll
            for (int kt = 0; kt < 8; kt++) {
                uint32_t a0[4], a1[4];
                ldsm_x4(a0, aW2 + kt * 32);
                ldsm_x4(a1, aW2 + 16 * PITCHB + kt * 32);
                #pragma unroll
                for (int q2 = 0; q2 < 4; q2++) {
                    uint32_t bg[4];
                    ldsm_x4(bg, bGm + q2 * (16 * PITCHB) + kt * 32);
                    mma16816(acc[0][2 * q2],     a0, bg);
                    mma16816(acc[0][2 * q2 + 1], a0, bg + 2);
                    mma16816(acc[1][2 * q2],     a1, bg);
                    mma16816(acc[1][2 * q2 + 1], a1, bg + 2);
                }
            }
        } else {
            #pragma unroll
            for (int kt = 0; kt < 8; kt++) {
                uint32_t a0[4], a1[4];
                ldsm_x4(a0, aW2 + kt * 32);
                ldsm_x4(a1, aW2 + 16 * PITCHB + kt * 32);
                #pragma unroll
                for (int q2 = 0; q2 < 3; q2++) {
                    uint32_t bg[4];
                    ldsm_x4(bg, bGm + q2 * (16 * PITCHB) + kt * 32);
                    mma16816(acc[0][2 * q2],     a0, bg);
                    mma16816(acc[0][2 * q2 + 1], a0, bg + 2);
                    mma16816(acc[1][2 * q2],     a1, bg);
                    mma16816(acc[1][2 * q2 + 1], a1, bg + 2);
                }
                uint32_t b2[2];
                ldsm_x2(b2, bG2x + kt * 32);
                mma16816(acc[0][6], a0, b2);
                mma16816(acc[1][6], a1, b2);
            }
        }

        // in-register partial max over this warp's neighbor subset
        {
            __half* nep = (__half*)(smem + OFF_NE0 + mh * (OFF_NE1 - OFF_NE0));
            int p0 = tg * 2, p1 = p0 + 1;
            #pragma unroll
            for (int t = 0; t < 2; t++) {
                float m0 = acc[t][0][0], m1 = acc[t][0][1], m2 = acc[t][0][2], m3 = acc[t][0][3];
                #pragma unroll
                for (int q = 1; q < 8; q++) {
                    if (q < nq) {
                        m0 = fmaxf(m0, acc[t][q][0]);
                        m1 = fmaxf(m1, acc[t][q][1]);
                        m2 = fmaxf(m2, acc[t][q][2]);
                        m3 = fmaxf(m3, acc[t][q][3]);
                    }
                }
                int eA = eb * 32 + 16 * t + g;
                nep[p0 * 136 + eA]     = __float2half_rn(m0);
                nep[p1 * 136 + eA]     = __float2half_rn(m1);
                nep[p0 * 136 + eA + 8] = __float2half_rn(m2);
                nep[p1 * 136 + eA + 8] = __float2half_rn(m3);
            }
        }
        __syncthreads();

        // epilogue: feats[dout,p] = Wn . max(ne0, ne1) (HMMA) + be + Wp.xi
        {
            float f2[4] = {0.f, 0.f, 0.f, 0.f};
            #pragma unroll
            for (int kt = 0; kt < 8; kt++) {
                uint32_t a4[4], b0[2], b1[2], c[2];
                ldsm_x4(a4, aWn + kt * 32);
                ldsm_x2(b0, bNe0 + kt * 32);
                ldsm_x2(b1, bNe1 + kt * 32);
                __half2 c0 = __hmax2(*(__half2*)&b0[0], *(__half2*)&b1[0]);
                __half2 c1 = __hmax2(*(__half2*)&b0[1], *(__half2*)&b1[1]);
                c[0] = *(uint32_t*)&c0; c[1] = *(uint32_t*)&c1;
                mma16816(f2, a4, c);
            }
            const float* xb = (const float*)(smem + OFF_XI0 + buf * (OFF_XI1 - OFF_XI0));
            int p0 = tg * 2, p1 = p0 + 1;
            float uLo0 = bevLo, uLo1 = bevLo, uHi0 = bevHi, uHi1 = bevHi;
            #pragma unroll
            for (int c = 0; c < CIN; c++) {
                float x0 = xb[p0 * 8 + c], x1 = xb[p1 * 8 + c];
                uLo0 = fmaf(wpeLo[c], x0, uLo0);
                uLo1 = fmaf(wpeLo[c], x1, uLo1);
                uHi0 = fmaf(wpeHi[c], x0, uHi0);
                uHi1 = fmaf(wpeHi[c], x1, uHi1);
            }
            int n0 = ids_s[buf * 8 + p0], n1 = ids_s[buf * 8 + p1];
            if (p0 < np) {
                d_feats[n0 * DCH + eLo] = f2[0] + uLo0;
                d_feats[n0 * DCH + eHi] = f2[2] + uHi0;
            }
            if (p1 < np) {
                d_feats[n1 * DCH + eLo] = f2[1] + uLo1;
                d_feats[n1 * DCH + eHi] = f2[3] + uHi1;
            }
        }
        buf ^= 1;
    }
    #undef PREFETCH
}

// ---------------- emit ---------------------------------------------------------
#define EM_TILE 64
__global__ void emit_kernel(float* __restrict__ out)
{
    __shared__ float s[EM_TILE * 129];
    const int pixbase = blockIdx.x * EM_TILE;
    const int tid = threadIdx.x;

    for (int i = tid; i < EM_TILE * DCH; i += blockDim.x) {
        int p = i >> 7, d = i & 127;
        int w = d_winner[pixbase + p];
        s[p * 129 + d] = (w >= 0) ? d_feats[w * DCH + d] : -1.0f;
    }
    __syncthreads();
    for (int i = tid; i < EM_TILE * DCH; i += blockDim.x) {
        int d = i >> 6, p = i & 63;
        out[d * HW + pixbase + p] = s[p * 129 + d];
    }
}

// ---------------- launch --------------------------------------------------------
extern "C" void kernel_launch(void* const* d_in, const int* in_sizes, int n_in,
                              void* d_out, int out_size)
{
    const float* pc        = (const float*)d_in[0];
    const int*   neighbors = (const int*)  d_in[1];
    const int*   px        = (const int*)  d_in[2];
    const int*   py        = (const int*)  d_in[3];
    const float* ng        = (const float*)d_in[4];
    const float* nb_       = (const float*)d_in[5];
    const float* nm        = (const float*)d_in[6];
    const float* nv        = (const float*)d_in[7];
    const float* c1w       = (const float*)d_in[8];
    const float* c1b       = (const float*)d_in[9];
    const float* g2a       = (const float*)d_in[10];
    const float* b2a       = (const float*)d_in[11];
    const float* m2a       = (const float*)d_in[12];
    const float* v2a       = (const float*)d_in[13];
    const float* w2a       = (const float*)d_in[14];
    const float* g2b       = (const float*)d_in[15];
    const float* b2b       = (const float*)d_in[16];
    const float* m2b       = (const float*)d_in[17];
    const float* v2b       = (const float*)d_in[18];
    const float* w2b       = (const float*)d_in[19];
    const float* fw        = (const float*)d_in[20];
    const float* fb        = (const float*)d_in[21];
    float* out = (float*)d_out;

    cudaFuncSetAttribute(main_kernel, cudaFuncAttributeMaxDynamicSharedMemorySize, SMEM_SZ);

    prep_kernel<<<128, 128>>>(ng, nb_, nm, nv, c1w, c1b,
                              g2a, b2a, m2a, v2a, w2a,
                              g2b, b2b, m2b, v2b, fw, fb);
    norm_kernel<<<(NPTS * 8) / 256, 256>>>(pc);
    wscat_kernel<<<NPTS / 256, 256>>>(px, py);
    compact_kernel<<<HW / 256, 256>>>();
    main_kernel<<<296, 256, SMEM_SZ>>>(w2b, fw, neighbors);
    emit_kernel<<<HW / EM_TILE, 256>>>(out);
}

// round 9
// speedup vs baseline: 7.3782x; 1.0223x over previous
#include <cuda_runtime.h>
#include <cuda_fp16.h>
#include <math.h>
#include <stdint.h>

// Problem constants
#define NPTS   65536
#define CIN    5
#define DCH    128
#define KNBR   16
#define KK     15
#define HH     64
#define WW     1024
#define HW     (HH*WW)
#define EPS    1e-5f

#define PTILE  8            // points per CTA tile
#define MROWS  (PTILE*KK)   // 120 G rows, row m = k*8 + p (neighbor-major)
#define PITCHB 272          // byte pitch (136 halfs) for G / W / Wn / ne tiles

// ---------------- device scratch ----------------------------------------------
__device__ float d_xn[NPTS * 8];
__device__ float d_feats[NPTS * DCH];
__device__ int   d_winner[HW];
__device__ int   d_live[HW];
__device__ int   d_live_count;

__device__ float d_waf[DCH * CIN];
__device__ float d_bf[DCH];
__device__ float d_wpe[DCH * CIN];
__device__ float d_be[DCH];
__device__ float d_sn[CIN];
__device__ float d_shn[CIN];

// ---------------- PTX helpers -------------------------------------------------
__device__ __forceinline__ uint32_t smem_u32(const void* p) {
    uint32_t a;
    asm("{ .reg .u64 t; cvta.to.shared.u64 t, %1; cvt.u32.u64 %0, t; }" : "=r"(a) : "l"(p));
    return a;
}
__device__ __forceinline__ void ldsm_x4(uint32_t* r, uint32_t addr) {
    asm volatile("ldmatrix.sync.aligned.m8n8.x4.shared.b16 {%0,%1,%2,%3}, [%4];"
        : "=r"(r[0]), "=r"(r[1]), "=r"(r[2]), "=r"(r[3]) : "r"(addr));
}
__device__ __forceinline__ void ldsm_x2(uint32_t* r, uint32_t addr) {
    asm volatile("ldmatrix.sync.aligned.m8n8.x2.shared.b16 {%0,%1}, [%2];"
        : "=r"(r[0]), "=r"(r[1]) : "r"(addr));
}
__device__ __forceinline__ void ldsm_x1(uint32_t* r, uint32_t addr) {
    asm volatile("ldmatrix.sync.aligned.m8n8.x1.shared.b16 {%0}, [%1];"
        : "=r"(r[0]) : "r"(addr));
}
__device__ __forceinline__ void mma16816(float* d, const uint32_t* a, const uint32_t* b) {
    asm volatile("mma.sync.aligned.m16n8k16.row.col.f32.f16.f16.f32 "
        "{%0,%1,%2,%3}, {%4,%5,%6,%7}, {%8,%9}, {%0,%1,%2,%3};"
        : "+f"(d[0]), "+f"(d[1]), "+f"(d[2]), "+f"(d[3])
        : "r"(a[0]), "r"(a[1]), "r"(a[2]), "r"(a[3]), "r"(b[0]), "r"(b[1]));
}
__device__ __forceinline__ void mma16808(float* d, const uint32_t* a, uint32_t b) {
    asm volatile("mma.sync.aligned.m16n8k8.row.col.f32.f16.f16.f32 "
        "{%0,%1,%2,%3}, {%4,%5}, {%6}, {%0,%1,%2,%3};"
        : "+f"(d[0]), "+f"(d[1]), "+f"(d[2]), "+f"(d[3])
        : "r"(a[0]), "r"(a[1]), "r"(b));
}
// packed gelu on 2 values: g = 0.5x(1 + tanh(x*(0.79788456 + 0.035677408 x^2)))
__device__ __forceinline__ __half2 gelu_h2(__half2 x, __half2 c0, __half2 c1, __half2 h05) {
    __half2 z = __hmul2(x, __hfma2(c1, __hmul2(x, x), c0));
    uint32_t t;
    asm("tanh.approx.f16x2 %0, %1;" : "=r"(t) : "r"(*(uint32_t*)&z));
    __half2 hx = __hmul2(x, h05);
    return __hfma2(hx, *(__half2*)&t, hx);
}

// ---------------- SMEM layout (bytes) -----------------------------------------
#define OFF_G     0          // G half [m<120][e<128] pitch 136h = 32640
#define OFF_W     32768      // w2b half [e][d] pitch 136h = 34816
#define OFF_WN    67584      // Wn half [dout][e] pitch 136h = 34816
#define OFF_WA    102400     // wa half [e][8] pitch 8h = 2048
#define OFF_DIFF0 104448     // diff half [m<120][8] = 1920
#define OFF_DIFF1 106368
#define OFF_NE0   108288     // ne half [p<8][e] pitch 136h = 2176 (k 0..7 partial)
#define OFF_NE1   110464     //                                (k 8..14 partial)
#define OFF_XI0   112640     // 8x8 f32 = 256
#define OFF_XI1   112896
#define OFF_IDS   113152     // int ids[2][8]
#define SMEM_SZ   113216

// ---------------- prep: parallel fold ------------------------------------------
__device__ __forceinline__ float blockSum(float v, float* red, int tid) {
    #pragma unroll
    for (int off = 16; off; off >>= 1) v += __shfl_down_sync(0xFFFFFFFFu, v, off);
    if ((tid & 31) == 0) red[tid >> 5] = v;
    __syncthreads();
    float r = (red[0] + red[1]) + (red[2] + red[3]);
    __syncthreads();
    return r;
}

__global__ void prep_kernel(const float* ng, const float* nb_, const float* nm, const float* nv,
                            const float* c1w, const float* c1b,
                            const float* g2a, const float* b2a, const float* m2a, const float* v2a,
                            const float* w2a,
                            const float* g2b, const float* b2b, const float* m2b, const float* v2b,
                            const float* fw, const float* fb)
{
    __shared__ float red[4];
    const int d = blockIdx.x, e = threadIdx.x;
    const float f = fw[d * (2 * DCH) + e];

    float s[6];
    #pragma unroll
    for (int c = 0; c < CIN; c++) s[c] = blockSum(f * c1w[e * CIN + c], red, e);
    s[5] = blockSum(f * c1b[e], red, e);

    if (e == 0) {
        #pragma unroll
        for (int c = 0; c < CIN; c++) d_wpe[d * CIN + c] = s[c];
        d_be[d] = s[5] + fb[d];

        float s2b = g2b[d] * rsqrtf(v2b[d] + EPS);
        float t2b = b2b[d] - m2b[d] * s2b;
        float cst = 0.f;
        #pragma unroll
        for (int c = 0; c < CIN; c++) {
            float sc = g2a[c] * rsqrtf(v2a[c] + EPS);
            float sh = b2a[c] - m2a[c] * sc;
            d_waf[d * CIN + c] = w2a[d * CIN + c] * sc * s2b;
            cst += w2a[d * CIN + c] * sh;
        }
        d_bf[d] = cst * s2b + t2b;
    }
    if (d == 0 && e < CIN) {
        float sn = ng[e] * rsqrtf(nv[e] + EPS);
        d_sn[e]  = sn;
        d_shn[e] = nb_[e] - nm[e] * sn;
    }
}

// ---------------- norm + winit merged ------------------------------------------
__global__ void norm_kernel(const float* pc)
{
    int t = blockIdx.x * blockDim.x + threadIdx.x;
    if (t < HW) d_winner[t] = -1;
    if (t == 0) d_live_count = 0;
    if (t >= NPTS * 8) return;
    int n = t >> 3, c = t & 7;
    float v = 0.f;
    if (c < CIN) v = pc[n * CIN + c] * d_sn[c] + d_shn[c];
    d_xn[t] = v;
}

__global__ void wscat_kernel(const int* px, const int* py)
{
    int n = blockIdx.x * blockDim.x + threadIdx.x;
    if (n >= NPTS) return;
    atomicMax(&d_winner[py[n] * WW + px[n]], n);
}

// warp-aggregated compaction: one atomic per warp
__global__ void compact_kernel()
{
    int t = blockIdx.x * blockDim.x + threadIdx.x;
    int w = (t < HW) ? d_winner[t] : -1;
    unsigned mask = __ballot_sync(0xFFFFFFFFu, w >= 0);
    if (mask == 0) return;
    int lane = threadIdx.x & 31;
    int leader = __ffs(mask) - 1;
    int pos = 0;
    if (lane == leader) pos = atomicAdd(&d_live_count, __popc(mask));
    pos = __shfl_sync(0xFFFFFFFFu, pos, leader);
    if (w >= 0) d_live[pos + __popc(mask & ((1u << lane) - 1))] = w;
}

// ---------------- main kernel --------------------------------------------------
__global__ void __launch_bounds__(256, 2)
main_kernel(const float* __restrict__ w2b, const float* __restrict__ fw,
            const int* __restrict__ nbr)
{
    extern __shared__ char smem[];
    const uint32_t smb = smem_u32(smem);
    __half* G_s  = (__half*)(smem + OFF_G);
    __half* W_s  = (__half*)(smem + OFF_W);
    __half* Wn_s = (__half*)(smem + OFF_WN);
    __half* Wa_s = (__half*)(smem + OFF_WA);
    int*    ids_s = (int*)(smem + OFF_IDS);

    const int tid  = threadIdx.x;
    const int wid  = tid >> 5;
    const int lane = tid & 31;
    const int tg   = lane & 3;
    const int g    = lane >> 2;

    // ---- prologue: weights into SMEM ----
    for (int i = tid; i < DCH * DCH; i += 256) {
        int e = i >> 7, d = i & 127;
        W_s[e * 136 + d] = __float2half_rn(w2b[i]);
    }
    for (int i = tid; i < DCH * DCH; i += 256) {
        int dout = i >> 7, e = i & 127;
        Wn_s[dout * 136 + e] = __float2half_rn(fw[dout * (2 * DCH) + DCH + e]);
    }
    for (int i = tid; i < DCH * 8; i += 256) {
        int e = i >> 3, k = i & 7;
        Wa_s[i] = (k < CIN) ? __float2half_rn(d_waf[e * CIN + k]) : __float2half_rn(0.f);
    }

    // phase-1 / epilogue row constants (e-rows 16*wid .. +15)
    const int eLo = 16 * wid + g;
    const int eHi = eLo + 8;
    const float bfLo = d_bf[eLo], bfHi = d_bf[eHi];
    const float bevLo = d_be[eLo], bevHi = d_be[eHi];
    float wpeLo[CIN], wpeHi[CIN];
    #pragma unroll
    for (int c = 0; c < CIN; c++) { wpeLo[c] = d_wpe[eLo * CIN + c]; wpeHi[c] = d_wpe[eHi * CIN + c]; }

    // gelu constants
    const __half2 gc0 = __float2half2_rn(0.79788456f);
    const __half2 gc1 = __float2half2_rn(0.035677408f);
    const __half2 gh5 = __float2half2_rn(0.5f);

    // phase-2 warp mapping: eb = e-block (32 rows), mh = m-half (k subset)
    const int eb = wid & 3, mh = wid >> 2;
    const int nq = 8 - mh;          // n-blocks in this half (8 or 7)

    const uint32_t colh = ((lane >> 3) & 1) << 3;
    // ldmatrix bases
    const uint32_t aWa = smb + OFF_WA + ((16 * wid + (lane & 15)) << 4);              // pitch 16B
    const uint32_t aW2 = smb + OFF_W  + (eb * 32 + (lane & 15)) * PITCHB + (((lane >> 4) << 3) << 1);
    const uint32_t aWn = smb + OFF_WN + (16 * wid + (lane & 15)) * PITCHB + (((lane >> 4) << 3) << 1);
    const uint32_t bGm = smb + OFF_G  + (64 * mh + ((lane >> 4) << 3) + (lane & 7)) * PITCHB + (colh << 1);
    const uint32_t bG2x = smb + OFF_G + (112 + (lane & 7)) * PITCHB + (colh << 1);
    const uint32_t bDf  = smb + OFF_DIFF0 + ((lane & 7) << 4);                        // pitch 16B
    const uint32_t bNe0 = smb + OFF_NE0 + (lane & 7) * PITCHB + (colh << 1);
    const uint32_t bNe1 = bNe0 + (OFF_NE1 - OFF_NE0);

    __syncthreads();

    uint32_t wa2[2];
    ldsm_x2(wa2, aWa);              // phase-1 A fragment, constant

    const int cnt = d_live_count;
    const int stride = gridDim.x * PTILE;
    int buf = 0;

    // staging registers
    uint32_t s0 = 0, s1 = 0, s2 = 0;
    int sid = 0;
    float sx[8];

    #define PREFETCH(pbase) do { \
        if (tid < 128) { \
            int _p = (tid < MROWS) ? (tid & 7) : (tid - MROWS); \
            int _idx = (pbase) + _p; \
            _idx = min(_idx, cnt - 1); if (_idx < 0) _idx = 0; \
            sid = d_live[_idx]; \
            if (tid < MROWS) { \
                int _k = tid >> 3; \
                int _j = nbr[sid * KNBR + 1 + _k]; \
                float4 _a0 = ((const float4*)&d_xn[_j * 8])[0]; \
                float4 _b0 = ((const float4*)&d_xn[sid * 8])[0]; \
                float _a4 = d_xn[_j * 8 + 4], _b4 = d_xn[sid * 8 + 4]; \
                __half2 _h01 = __floats2half2_rn(_a0.x - _b0.x, _a0.y - _b0.y); \
                __half2 _h23 = __floats2half2_rn(_a0.z - _b0.z, _a0.w - _b0.w); \
                __half2 _h45 = __floats2half2_rn(_a4 - _b4, 0.f); \
                s0 = *(uint32_t*)&_h01; s1 = *(uint32_t*)&_h23; s2 = *(uint32_t*)&_h45; \
            } else { \
                float4 _q0 = ((const float4*)&d_xn[sid * 8])[0]; \
                float4 _q1 = ((const float4*)&d_xn[sid * 8])[1]; \
                sx[0] = _q0.x; sx[1] = _q0.y; sx[2] = _q0.z; sx[3] = _q0.w; \
                sx[4] = _q1.x; sx[5] = _q1.y; sx[6] = _q1.z; sx[7] = _q1.w; \
            } \
        } \
    } while (0)

    PREFETCH(blockIdx.x * PTILE);

    for (int base = blockIdx.x * PTILE; base < cnt; base += stride) {
        const int np = min(PTILE, cnt - base);

        // commit staged regs to smem buffers
        if (tid < MROWS) {
            ((uint4*)(smem + OFF_DIFF0 + buf * (OFF_DIFF1 - OFF_DIFF0)))[tid] = make_uint4(s0, s1, s2, 0u);
            if (tid < PTILE) ids_s[buf * 8 + tid] = sid;
        } else if (tid < 128) {
            float* xb = (float*)(smem + OFF_XI0 + buf * (OFF_XI1 - OFF_XI0));
            int p = tid - MROWS;
            ((float4*)(xb + p * 8))[0] = make_float4(sx[0], sx[1], sx[2], sx[3]);
            ((float4*)(xb + p * 8))[1] = make_float4(sx[4], sx[5], sx[6], sx[7]);
        }
        __syncthreads();

        // prefetch next tile (overlaps with compute below)
        PREFETCH(base + stride);

        // phase 1: pre = wa . diff + bf (HMMA k=8), packed-half2 gelu, store G fp16
        {
            const uint32_t dfb = bDf + buf * (OFF_DIFF1 - OFF_DIFF0);
            #pragma unroll
            for (int nb = 0; nb < 15; nb++) {
                uint32_t bd;
                ldsm_x1(&bd, dfb + nb * 128);
                float pa[4] = {bfLo, bfLo, bfHi, bfHi};
                mma16808(pa, wa2, bd);
                int m0 = nb * 8 + tg * 2;
                __half2 gA = gelu_h2(__floats2half2_rn(pa[0], pa[1]), gc0, gc1, gh5);
                __half2 gB = gelu_h2(__floats2half2_rn(pa[2], pa[3]), gc0, gc1, gh5);
                G_s[m0 * 136 + eLo]       = __low2half(gA);
                G_s[(m0 + 1) * 136 + eLo] = __high2half(gA);
                G_s[m0 * 136 + eHi]       = __low2half(gB);
                G_s[(m0 + 1) * 136 + eHi] = __high2half(gB);
            }
        }
        __syncthreads();

        // phase 2: D[e,m] = w2b . G^T, warp = (eb, mh); B shared by 2 A-blocks
        float acc[2][8][4];
        #pragma unroll
        for (int t = 0; t < 2; t++)
            #pragma unroll
            for (int q = 0; q < 8; q++)
                #pragma unroll
                for (int j = 0; j < 4; j++) acc[t][q][j] = 0.f;

        if (mh == 0) {
            #pragma unroll
            for (int kt = 0; kt < 8; kt++) {
                uint32_t a0[4], a1[4];
                ldsm_x4(a0, aW2 + kt * 32);
                ldsm_x4(a1, aW2 + 16 * PITCHB + kt * 32);
                #pragma unroll
                for (int q2 = 0; q2 < 4; q2++) {
                    uint32_t bg[4];
                    ldsm_x4(bg, bGm + q2 * (16 * PITCHB) + kt * 32);
                    mma16816(acc[0][2 * q2],     a0, bg);
                    mma16816(acc[0][2 * q2 + 1], a0, bg + 2);
                    mma16816(acc[1][2 * q2],     a1, bg);
                    mma16816(acc[1][2 * q2 + 1], a1, bg + 2);
                }
            }
        } else {
            #pragma unroll
            for (int kt = 0; kt < 8; kt++) {
                uint32_t a0[4], a1[4];
                ldsm_x4(a0, aW2 + kt * 32);
                ldsm_x4(a1, aW2 + 16 * PITCHB + kt * 32);
                #pragma unroll
                for (int q2 = 0; q2 < 3; q2++) {
                    uint32_t bg[4];
                    ldsm_x4(bg, bGm + q2 * (16 * PITCHB) + kt * 32);
                    mma16816(acc[0][2 * q2],     a0, bg);
                    mma16816(acc[0][2 * q2 + 1], a0, bg + 2);
                    mma16816(acc[1][2 * q2],     a1, bg);
                    mma16816(acc[1][2 * q2 + 1], a1, bg + 2);
                }
                uint32_t b2[2];
                ldsm_x2(b2, bG2x + kt * 32);
                mma16816(acc[0][6], a0, b2);
                mma16816(acc[1][6], a1, b2);
            }
        }

        // in-register partial max over this warp's neighbor subset
        {
            __half* nep = (__half*)(smem + OFF_NE0 + mh * (OFF_NE1 - OFF_NE0));
            int p0 = tg * 2, p1 = p0 + 1;
            #pragma unroll
            for (int t = 0; t < 2; t++) {
                float m0 = acc[t][0][0], m1 = acc[t][0][1], m2 = acc[t][0][2], m3 = acc[t][0][3];
                #pragma unroll
                for (int q = 1; q < 8; q++) {
                    if (q < nq) {
                        m0 = fmaxf(m0, acc[t][q][0]);
                        m1 = fmaxf(m1, acc[t][q][1]);
                        m2 = fmaxf(m2, acc[t][q][2]);
                        m3 = fmaxf(m3, acc[t][q][3]);
                    }
                }
                int eA = eb * 32 + 16 * t + g;
                nep[p0 * 136 + eA]     = __float2half_rn(m0);
                nep[p1 * 136 + eA]     = __float2half_rn(m1);
                nep[p0 * 136 + eA + 8] = __float2half_rn(m2);
                nep[p1 * 136 + eA + 8] = __float2half_rn(m3);
            }
        }
        __syncthreads();

        // epilogue: feats[dout,p] = Wn . max(ne0, ne1) (HMMA) + be + Wp.xi
        {
            float f2[4] = {0.f, 0.f, 0.f, 0.f};
            #pragma unroll
            for (int kt = 0; kt < 8; kt++) {
                uint32_t a4[4], b0[2], b1[2], c[2];
                ldsm_x4(a4, aWn + kt * 32);
                ldsm_x2(b0, bNe0 + kt * 32);
                ldsm_x2(b1, bNe1 + kt * 32);
                __half2 c0 = __hmax2(*(__half2*)&b0[0], *(__half2*)&b1[0]);
                __half2 c1 = __hmax2(*(__half2*)&b0[1], *(__half2*)&b1[1]);
                c[0] = *(uint32_t*)&c0; c[1] = *(uint32_t*)&c1;
                mma16816(f2, a4, c);
            }
            const float* xb = (const float*)(smem + OFF_XI0 + buf * (OFF_XI1 - OFF_XI0));
            int p0 = tg * 2, p1 = p0 + 1;
            float uLo0 = bevLo, uLo1 = bevLo, uHi0 = bevHi, uHi1 = bevHi;
            #pragma unroll
            for (int c = 0; c < CIN; c++) {
                float x0 = xb[p0 * 8 + c], x1 = xb[p1 * 8 + c];
                uLo0 = fmaf(wpeLo[c], x0, uLo0);
                uLo1 = fmaf(wpeLo[c], x1, uLo1);
                uHi0 = fmaf(wpeHi[c], x0, uHi0);
                uHi1 = fmaf(wpeHi[c], x1, uHi1);
            }
            int n0 = ids_s[buf * 8 + p0], n1 = ids_s[buf * 8 + p1];
            if (p0 < np) {
                d_feats[n0 * DCH + eLo] = f2[0] + uLo0;
                d_feats[n0 * DCH + eHi] = f2[2] + uHi0;
            }
            if (p1 < np) {
                d_feats[n1 * DCH + eLo] = f2[1] + uLo1;
                d_feats[n1 * DCH + eHi] = f2[3] + uHi1;
            }
        }
        buf ^= 1;
    }
    #undef PREFETCH
}

// ---------------- emit ---------------------------------------------------------
#define EM_TILE 64
__global__ void emit_kernel(float* __restrict__ out)
{
    __shared__ float s[EM_TILE * 129];
    const int pixbase = blockIdx.x * EM_TILE;
    const int tid = threadIdx.x;

    for (int i = tid; i < EM_TILE * DCH; i += blockDim.x) {
        int p = i >> 7, d = i & 127;
        int w = d_winner[pixbase + p];
        s[p * 129 + d] = (w >= 0) ? d_feats[w * DCH + d] : -1.0f;
    }
    __syncthreads();
    for (int i = tid; i < EM_TILE * DCH; i += blockDim.x) {
        int d = i >> 6, p = i & 63;
        out[d * HW + pixbase + p] = s[p * 129 + d];
    }
}

// ---------------- launch --------------------------------------------------------
extern "C" void kernel_launch(void* const* d_in, const int* in_sizes, int n_in,
                              void* d_out, int out_size)
{
    const float* pc        = (const float*)d_in[0];
    const int*   neighbors = (const int*)  d_in[1];
    const int*   px        = (const int*)  d_in[2];
    const int*   py        = (const int*)  d_in[3];
    const float* ng        = (const float*)d_in[4];
    const float* nb_       = (const float*)d_in[5];
    const float* nm        = (const float*)d_in[6];
    const float* nv        = (const float*)d_in[7];
    const float* c1w       = (const float*)d_in[8];
    const float* c1b       = (const float*)d_in[9];
    const float* g2a       = (const float*)d_in[10];
    const float* b2a       = (const float*)d_in[11];
    const float* m2a       = (const float*)d_in[12];
    const float* v2a       = (const float*)d_in[13];
    const float* w2a       = (const float*)d_in[14];
    const float* g2b       = (const float*)d_in[15];
    const float* b2b       = (const float*)d_in[16];
    const float* m2b       = (const float*)d_in[17];
    const float* v2b       = (const float*)d_in[18];
    const float* w2b       = (const float*)d_in[19];
    const float* fw        = (const float*)d_in[20];
    const float* fb        = (const float*)d_in[21];
    float* out = (float*)d_out;

    cudaFuncSetAttribute(main_kernel, cudaFuncAttributeMaxDynamicSharedMemorySize, SMEM_SZ);

    prep_kernel<<<128, 128>>>(ng, nb_, nm, nv, c1w, c1b,
                              g2a, b2a, m2a, v2a, w2a,
                              g2b, b2b, m2b, v2b, fw, fb);
    norm_kernel<<<(NPTS * 8) / 256, 256>>>(pc);
    wscat_kernel<<<NPTS / 256, 256>>>(px, py);
    compact_kernel<<<HW / 256, 256>>>();
    main_kernel<<<296, 256, SMEM_SZ>>>(w2b, fw, neighbors);
    emit_kernel<<<HW / EM_TILE, 256>>>(out);
}

// round 12
// speedup vs baseline: 7.5323x; 1.0209x over previous
#include <cuda_runtime.h>
#include <cuda_fp16.h>
#include <math.h>
#include <stdint.h>

// Problem constants
#define NPTS   65536
#define CIN    5
#define DCH    128
#define KNBR   16
#define KK     15
#define HH     64
#define WW     1024
#define HW     (HH*WW)
#define EPS    1e-5f

#define PTILE  8            // points per CTA tile
#define MROWS  (PTILE*KK)   // 120 G rows, row m = k*8 + p (neighbor-major)
#define PITCHB 272          // byte pitch (136 halfs) for G / W / Wn / ne tiles

// ---------------- device scratch ----------------------------------------------
__device__ float d_xn[NPTS * 8];
__device__ float d_feats[NPTS * DCH];
__device__ int   d_winner[HW];
__device__ int   d_live[HW];
__device__ int   d_live_count;

__device__ float d_waf[DCH * CIN];
__device__ float d_bf[DCH];
__device__ float d_wpe[DCH * CIN];
__device__ float d_be[DCH];
__device__ float d_sn[CIN];
__device__ float d_shn[CIN];

// ---------------- PTX helpers -------------------------------------------------
__device__ __forceinline__ uint32_t smem_u32(const void* p) {
    uint32_t a;
    asm("{ .reg .u64 t; cvta.to.shared.u64 t, %1; cvt.u32.u64 %0, t; }" : "=r"(a) : "l"(p));
    return a;
}
__device__ __forceinline__ void ldsm_x4(uint32_t* r, uint32_t addr) {
    asm volatile("ldmatrix.sync.aligned.m8n8.x4.shared.b16 {%0,%1,%2,%3}, [%4];"
        : "=r"(r[0]), "=r"(r[1]), "=r"(r[2]), "=r"(r[3]) : "r"(addr));
}
__device__ __forceinline__ void ldsm_x2(uint32_t* r, uint32_t addr) {
    asm volatile("ldmatrix.sync.aligned.m8n8.x2.shared.b16 {%0,%1}, [%2];"
        : "=r"(r[0]), "=r"(r[1]) : "r"(addr));
}
__device__ __forceinline__ void ldsm_x1(uint32_t* r, uint32_t addr) {
    asm volatile("ldmatrix.sync.aligned.m8n8.x1.shared.b16 {%0}, [%1];"
        : "=r"(r[0]) : "r"(addr));
}
__device__ __forceinline__ void mma16816(float* d, const uint32_t* a, const uint32_t* b) {
    asm volatile("mma.sync.aligned.m16n8k16.row.col.f32.f16.f16.f32 "
        "{%0,%1,%2,%3}, {%4,%5,%6,%7}, {%8,%9}, {%0,%1,%2,%3};"
        : "+f"(d[0]), "+f"(d[1]), "+f"(d[2]), "+f"(d[3])
        : "r"(a[0]), "r"(a[1]), "r"(a[2]), "r"(a[3]), "r"(b[0]), "r"(b[1]));
}
__device__ __forceinline__ void mma16808(float* d, const uint32_t* a, uint32_t b) {
    asm volatile("mma.sync.aligned.m16n8k8.row.col.f32.f16.f16.f32 "
        "{%0,%1,%2,%3}, {%4,%5}, {%6}, {%0,%1,%2,%3};"
        : "+f"(d[0]), "+f"(d[1]), "+f"(d[2]), "+f"(d[3])
        : "r"(a[0]), "r"(a[1]), "r"(b));
}
// packed gelu on 2 values
__device__ __forceinline__ __half2 gelu_h2(__half2 x, __half2 c0, __half2 c1, __half2 h05) {
    __half2 z = __hmul2(x, __hfma2(c1, __hmul2(x, x), c0));
    uint32_t t;
    asm("tanh.approx.f16x2 %0, %1;" : "=r"(t) : "r"(*(uint32_t*)&z));
    __half2 hx = __hmul2(x, h05);
    return __hfma2(hx, *(__half2*)&t, hx);
}

// ---------------- SMEM layout (bytes) -----------------------------------------
#define OFF_G     0          // G half [m<120][e<128] pitch 136h = 32640
#define OFF_W     32768      // w2b half [e][d] pitch 136h = 34816
#define OFF_WN    67584      // Wn half [dout][e] pitch 136h = 34816
#define OFF_WA    102400     // wa half [e][8] pitch 8h = 2048
#define OFF_DIFF0 104448     // diff half [m<120][8] = 1920
#define OFF_DIFF1 106368
#define OFF_NE0   108288     // ne half [p<8][e] pitch 136h = 2176 (k 0..7 partial)
#define OFF_NE1   110464     //                                (k 8..14 partial)
#define OFF_XI0   112640     // 8x8 f32 = 256
#define OFF_XI1   112896
#define OFF_IDS   113152     // int ids[2][8]
#define SMEM_SZ   113216

// ---------------- prep: parallel fold ------------------------------------------
__device__ __forceinline__ float blockSum(float v, float* red, int tid) {
    #pragma unroll
    for (int off = 16; off; off >>= 1) v += __shfl_down_sync(0xFFFFFFFFu, v, off);
    if ((tid & 31) == 0) red[tid >> 5] = v;
    __syncthreads();
    float r = (red[0] + red[1]) + (red[2] + red[3]);
    __syncthreads();
    return r;
}

__global__ void prep_kernel(const float* ng, const float* nb_, const float* nm, const float* nv,
                            const float* c1w, const float* c1b,
                            const float* g2a, const float* b2a, const float* m2a, const float* v2a,
                            const float* w2a,
                            const float* g2b, const float* b2b, const float* m2b, const float* v2b,
                            const float* fw, const float* fb)
{
    __shared__ float red[4];
    const int d = blockIdx.x, e = threadIdx.x;
    const float f = fw[d * (2 * DCH) + e];

    float s[6];
    #pragma unroll
    for (int c = 0; c < CIN; c++) s[c] = blockSum(f * c1w[e * CIN + c], red, e);
    s[5] = blockSum(f * c1b[e], red, e);

    if (e == 0) {
        #pragma unroll
        for (int c = 0; c < CIN; c++) d_wpe[d * CIN + c] = s[c];
        d_be[d] = s[5] + fb[d];

        float s2b = g2b[d] * rsqrtf(v2b[d] + EPS);
        float t2b = b2b[d] - m2b[d] * s2b;
        float cst = 0.f;
        #pragma unroll
        for (int c = 0; c < CIN; c++) {
            float sc = g2a[c] * rsqrtf(v2a[c] + EPS);
            float sh = b2a[c] - m2a[c] * sc;
            d_waf[d * CIN + c] = w2a[d * CIN + c] * sc * s2b;
            cst += w2a[d * CIN + c] * sh;
        }
        d_bf[d] = cst * s2b + t2b;
    }
    if (d == 0 && e < CIN) {
        float sn = ng[e] * rsqrtf(nv[e] + EPS);
        d_sn[e]  = sn;
        d_shn[e] = nb_[e] - nm[e] * sn;
    }
}

// ---------------- norm + winit merged ------------------------------------------
__global__ void norm_kernel(const float* pc)
{
    int t = blockIdx.x * blockDim.x + threadIdx.x;
    if (t < HW) d_winner[t] = -1;
    if (t == 0) d_live_count = 0;
    if (t >= NPTS * 8) return;
    int n = t >> 3, c = t & 7;
    float v = 0.f;
    if (c < CIN) v = pc[n * CIN + c] * d_sn[c] + d_shn[c];
    d_xn[t] = v;
}

// 4-wide scatter: MLP=4 per thread
__global__ void wscat_kernel(const int* px, const int* py)
{
    int t = blockIdx.x * blockDim.x + threadIdx.x;       // over NPTS/4
    int4 x4 = ((const int4*)px)[t];
    int4 y4 = ((const int4*)py)[t];
    int n0 = t * 4;
    atomicMax(&d_winner[y4.x * WW + x4.x], n0);
    atomicMax(&d_winner[y4.y * WW + x4.y], n0 + 1);
    atomicMax(&d_winner[y4.z * WW + x4.z], n0 + 2);
    atomicMax(&d_winner[y4.w * WW + x4.w], n0 + 3);
}

// 4-wide warp-aggregated compaction
__global__ void compact_kernel()
{
    int t = blockIdx.x * blockDim.x + threadIdx.x;       // over HW/4
    int4 w4 = ((const int4*)d_winner)[t];
    int lane = threadIdx.x & 31;
    int cntl = (w4.x >= 0) + (w4.y >= 0) + (w4.z >= 0) + (w4.w >= 0);
    int pref = cntl;
    #pragma unroll
    for (int off = 1; off < 32; off <<= 1) {
        int v = __shfl_up_sync(0xFFFFFFFFu, pref, off);
        if (lane >= off) pref += v;
    }
    int total = __shfl_sync(0xFFFFFFFFu, pref, 31);
    int excl = pref - cntl;
    int basep = 0;
    if (lane == 31 && total) basep = atomicAdd(&d_live_count, total);
    basep = __shfl_sync(0xFFFFFFFFu, basep, 31);
    int p = basep + excl;
    if (w4.x >= 0) d_live[p++] = w4.x;
    if (w4.y >= 0) d_live[p++] = w4.y;
    if (w4.z >= 0) d_live[p++] = w4.z;
    if (w4.w >= 0) d_live[p++] = w4.w;
}

// ---------------- main kernel --------------------------------------------------
__global__ void __launch_bounds__(256, 2)
main_kernel(const float* __restrict__ w2b, const float* __restrict__ fw,
            const int* __restrict__ nbr)
{
    extern __shared__ char smem[];
    const uint32_t smb = smem_u32(smem);
    __half* G_s  = (__half*)(smem + OFF_G);
    __half* W_s  = (__half*)(smem + OFF_W);
    __half* Wn_s = (__half*)(smem + OFF_WN);
    __half* Wa_s = (__half*)(smem + OFF_WA);
    int*    ids_s = (int*)(smem + OFF_IDS);

    const int tid  = threadIdx.x;
    const int wid  = tid >> 5;
    const int lane = tid & 31;
    const int tg   = lane & 3;
    const int g    = lane >> 2;

    // ---- prologue: weights into SMEM ----
    for (int i = tid; i < DCH * DCH; i += 256) {
        int e = i >> 7, d = i & 127;
        W_s[e * 136 + d] = __float2half_rn(w2b[i]);
    }
    for (int i = tid; i < DCH * DCH; i += 256) {
        int dout = i >> 7, e = i & 127;
        Wn_s[dout * 136 + e] = __float2half_rn(fw[dout * (2 * DCH) + DCH + e]);
    }
    for (int i = tid; i < DCH * 8; i += 256) {
        int e = i >> 3, k = i & 7;
        Wa_s[i] = (k < CIN) ? __float2half_rn(d_waf[e * CIN + k]) : __float2half_rn(0.f);
    }

    const int eLo = 16 * wid + g;
    const int eHi = eLo + 8;
    const float bfLo = d_bf[eLo], bfHi = d_bf[eHi];
    const float bevLo = d_be[eLo], bevHi = d_be[eHi];
    float wpeLo[CIN], wpeHi[CIN];
    #pragma unroll
    for (int c = 0; c < CIN; c++) { wpeLo[c] = d_wpe[eLo * CIN + c]; wpeHi[c] = d_wpe[eHi * CIN + c]; }

    const __half2 gc0 = __float2half2_rn(0.79788456f);
    const __half2 gc1 = __float2half2_rn(0.035677408f);
    const __half2 gh5 = __float2half2_rn(0.5f);

    const int eb = wid & 3, mh = wid >> 2;
    const int nq = 8 - mh;

    const uint32_t colh = ((lane >> 3) & 1) << 3;
    const uint32_t aWa = smb + OFF_WA + ((16 * wid + (lane & 15)) << 4);
    const uint32_t aW2 = smb + OFF_W  + (eb * 32 + (lane & 15)) * PITCHB + (((lane >> 4) << 3) << 1);
    const uint32_t aWn = smb + OFF_WN + (16 * wid + (lane & 15)) * PITCHB + (((lane >> 4) << 3) << 1);
    const uint32_t bGm = smb + OFF_G  + (64 * mh + ((lane >> 4) << 3) + (lane & 7)) * PITCHB + (colh << 1);
    const uint32_t bG2x = smb + OFF_G + (112 + (lane & 7)) * PITCHB + (colh << 1);
    const uint32_t bDf  = smb + OFF_DIFF0 + ((lane & 7) << 4);
    const uint32_t bNe0 = smb + OFF_NE0 + (lane & 7) * PITCHB + (colh << 1);
    const uint32_t bNe1 = bNe0 + (OFF_NE1 - OFF_NE0);

    __syncthreads();

    uint32_t wa2[2];
    ldsm_x2(wa2, aWa);

    const int cnt = d_live_count;
    const int stride = gridDim.x * PTILE;
    int buf = 0;

    uint32_t s0 = 0, s1 = 0, s2 = 0;
    int sid = 0;
    float sx[8];

    #define PREFETCH(pbase) do { \
        if (tid < 128) { \
            int _p = (tid < MROWS) ? (tid & 7) : (tid - MROWS); \
            int _idx = (pbase) + _p; \
            _idx = min(_idx, cnt - 1); if (_idx < 0) _idx = 0; \
            sid = d_live[_idx]; \
            if (tid < MROWS) { \
                int _k = tid >> 3; \
                int _j = nbr[sid * KNBR + 1 + _k]; \
                float4 _a0 = ((const float4*)&d_xn[_j * 8])[0]; \
                float4 _b0 = ((const float4*)&d_xn[sid * 8])[0]; \
                float _a4 = d_xn[_j * 8 + 4], _b4 = d_xn[sid * 8 + 4]; \
                __half2 _h01 = __floats2half2_rn(_a0.x - _b0.x, _a0.y - _b0.y); \
                __half2 _h23 = __floats2half2_rn(_a0.z - _b0.z, _a0.w - _b0.w); \
                __half2 _h45 = __floats2half2_rn(_a4 - _b4, 0.f); \
                s0 = *(uint32_t*)&_h01; s1 = *(uint32_t*)&_h23; s2 = *(uint32_t*)&_h45; \
            } else { \
                float4 _q0 = ((const float4*)&d_xn[sid * 8])[0]; \
                float4 _q1 = ((const float4*)&d_xn[sid * 8])[1]; \
                sx[0] = _q0.x; sx[1] = _q0.y; sx[2] = _q0.z; sx[3] = _q0.w; \
                sx[4] = _q1.x; sx[5] = _q1.y; sx[6] = _q1.z; sx[7] = _q1.w; \
            } \
        } \
    } while (0)

    #define COMMIT(bi) do { \
        if (tid < MROWS) { \
            ((uint4*)(smem + OFF_DIFF0 + (bi) * (OFF_DIFF1 - OFF_DIFF0)))[tid] = make_uint4(s0, s1, s2, 0u); \
            if (tid < PTILE) ids_s[(bi) * 8 + tid] = sid; \
        } else if (tid < 128) { \
            float* _xb = (float*)(smem + OFF_XI0 + (bi) * (OFF_XI1 - OFF_XI0)); \
            int _p = tid - MROWS; \
            ((float4*)(_xb + _p * 8))[0] = make_float4(sx[0], sx[1], sx[2], sx[3]); \
            ((float4*)(_xb + _p * 8))[1] = make_float4(sx[4], sx[5], sx[6], sx[7]); \
        } \
    } while (0)

    // pre-loop: stage + commit tile 0, then stage tile 1
    const int base0 = blockIdx.x * PTILE;
    PREFETCH(base0);
    COMMIT(0);
    __syncthreads();
    PREFETCH(base0 + stride);

    for (int base = base0; base < cnt; base += stride) {
        const int np = min(PTILE, cnt - base);

        // phase 1: pre = wa.diff + bf (HMMA k=8), gelu, store G
        {
            const uint32_t dfb = bDf + buf * (OFF_DIFF1 - OFF_DIFF0);
            #pragma unroll
            for (int nb = 0; nb < 15; nb++) {
                uint32_t bd;
                ldsm_x1(&bd, dfb + nb * 128);
                float pa[4] = {bfLo, bfLo, bfHi, bfHi};
                mma16808(pa, wa2, bd);
                int m0 = nb * 8 + tg * 2;
                __half2 gA = gelu_h2(__floats2half2_rn(pa[0], pa[1]), gc0, gc1, gh5);
                __half2 gB = gelu_h2(__floats2half2_rn(pa[2], pa[3]), gc0, gc1, gh5);
                G_s[m0 * 136 + eLo]       = __low2half(gA);
                G_s[(m0 + 1) * 136 + eLo] = __high2half(gA);
                G_s[m0 * 136 + eHi]       = __low2half(gB);
                G_s[(m0 + 1) * 136 + eHi] = __high2half(gB);
            }
        }
        __syncthreads();   // sync1: G ready

        // phase 2: D = w2b . G^T, warp = (eb, mh)
        float acc[2][8][4];
        #pragma unroll
        for (int t = 0; t < 2; t++)
            #pragma unroll
            for (int q = 0; q < 8; q++)
                #pragma unroll
                for (int j = 0; j < 4; j++) acc[t][q][j] = 0.f;

        if (mh == 0) {
            #pragma unroll
            for (int kt = 0; kt < 8; kt++) {
                uint32_t a0[4], a1[4];
                ldsm_x4(a0, aW2 + kt * 32);
                ldsm_x4(a1, aW2 + 16 * PITCHB + kt * 32);
                #pragma unroll
                for (int q2 = 0; q2 < 4; q2++) {
                    uint32_t bg[4];
                    ldsm_x4(bg, bGm + q2 * (16 * PITCHB) + kt * 32);
                    mma16816(acc[0][2 * q2],     a0, bg);
                    mma16816(acc[0][2 * q2 + 1], a0, bg + 2);
                    mma16816(acc[1][2 * q2],     a1, bg);
                    mma16816(acc[1][2 * q2 + 1], a1, bg + 2);
                }
            }
        } else {
            #pragma unroll
            for (int kt = 0; kt < 8; kt++) {
                uint32_t a0[4], a1[4];
                ldsm_x4(a0, aW2 + kt * 32);
                ldsm_x4(a1, aW2 + 16 * PITCHB + kt * 32);
                #pragma unroll
                for (int q2 = 0; q2 < 3; q2++) {
                    uint32_t bg[4];
                    ldsm_x4(bg, bGm + q2 * (16 * PITCHB) + kt * 32);
                    mma16816(acc[0][2 * q2],     a0, bg);
                    mma16816(acc[0][2 * q2 + 1], a0, bg + 2);
                    mma16816(acc[1][2 * q2],     a1, bg);
                    mma16816(acc[1][2 * q2 + 1], a1, bg + 2);
                }
                uint32_t b2[2];
                ldsm_x2(b2, bG2x + kt * 32);
                mma16816(acc[0][6], a0, b2);
                mma16816(acc[1][6], a1, b2);
            }
        }

        // partial max stores + commit next tile's staged data
        {
            __half* nep = (__half*)(smem + OFF_NE0 + mh * (OFF_NE1 - OFF_NE0));
            int p0 = tg * 2, p1 = p0 + 1;
            #pragma unroll
            for (int t = 0; t < 2; t++) {
                float m0 = acc[t][0][0], m1 = acc[t][0][1], m2 = acc[t][0][2], m3 = acc[t][0][3];
                #pragma unroll
                for (int q = 1; q < 8; q++) {
                    if (q < nq) {
                        m0 = fmaxf(m0, acc[t][q][0]);
                        m1 = fmaxf(m1, acc[t][q][1]);
                        m2 = fmaxf(m2, acc[t][q][2]);
                        m3 = fmaxf(m3, acc[t][q][3]);
                    }
                }
                int eA = eb * 32 + 16 * t + g;
                nep[p0 * 136 + eA]     = __float2half_rn(m0);
                nep[p1 * 136 + eA]     = __float2half_rn(m1);
                nep[p0 * 136 + eA + 8] = __float2half_rn(m2);
                nep[p1 * 136 + eA + 8] = __float2half_rn(m3);
            }
        }
        COMMIT(buf ^ 1);
        __syncthreads();   // sync2: NE + next diff/xi/ids ready

        // epilogue (tile t) — no barrier after; fast warps roll into phase1(t+1)
        {
            float f2[4] = {0.f, 0.f, 0.f, 0.f};
            #pragma unroll
            for (int kt = 0; kt < 8; kt++) {
                uint32_t a4[4], b0[2], b1[2], c[2];
                ldsm_x4(a4, aWn + kt * 32);
                ldsm_x2(b0, bNe0 + kt * 32);
                ldsm_x2(b1, bNe1 + kt * 32);
                __half2 c0 = __hmax2(*(__half2*)&b0[0], *(__half2*)&b1[0]);
                __half2 c1 = __hmax2(*(__half2*)&b0[1], *(__half2*)&b1[1]);
                c[0] = *(uint32_t*)&c0; c[1] = *(uint32_t*)&c1;
                mma16816(f2, a4, c);
            }
            const float* xb = (const float*)(smem + OFF_XI0 + buf * (OFF_XI1 - OFF_XI0));
            int p0 = tg * 2, p1 = p0 + 1;
            float uLo0 = bevLo, uLo1 = bevLo, uHi0 = bevHi, uHi1 = bevHi;
            #pragma unroll
            for (int c = 0; c < CIN; c++) {
                float x0 = xb[p0 * 8 + c], x1 = xb[p1 * 8 + c];
                uLo0 = fmaf(wpeLo[c], x0, uLo0);
                uLo1 = fmaf(wpeLo[c], x1, uLo1);
                uHi0 = fmaf(wpeHi[c], x0, uHi0);
                uHi1 = fmaf(wpeHi[c], x1, uHi1);
            }
            int n0 = ids_s[buf * 8 + p0], n1 = ids_s[buf * 8 + p1];
            if (p0 < np) {
                d_feats[n0 * DCH + eLo] = f2[0] + uLo0;
                d_feats[n0 * DCH + eHi] = f2[2] + uHi0;
            }
            if (p1 < np) {
                d_feats[n1 * DCH + eLo] = f2[1] + uLo1;
                d_feats[n1 * DCH + eHi] = f2[3] + uHi1;
            }
        }

        // prefetch tile t+2 (overlaps with next iteration's compute)
        PREFETCH(base + 2 * stride);
        buf ^= 1;
    }
    #undef PREFETCH
    #undef COMMIT
}

// ---------------- emit ---------------------------------------------------------
#define EM_TILE 64
__global__ void emit_kernel(float* __restrict__ out)
{
    __shared__ float s[EM_TILE * 129];
    const int pixbase = blockIdx.x * EM_TILE;
    const int tid = threadIdx.x;

    for (int i = tid; i < EM_TILE * DCH; i += blockDim.x) {
        int p = i >> 7, d = i & 127;
        int w = d_winner[pixbase + p];
        s[p * 129 + d] = (w >= 0) ? d_feats[w * DCH + d] : -1.0f;
    }
    __syncthreads();
    for (int i = tid; i < EM_TILE * DCH; i += blockDim.x) {
        int d = i >> 6, p = i & 63;
        out[d * HW + pixbase + p] = s[p * 129 + d];
    }
}

// ---------------- launch --------------------------------------------------------
extern "C" void kernel_launch(void* const* d_in, const int* in_sizes, int n_in,
                              void* d_out, int out_size)
{
    const float* pc        = (const float*)d_in[0];
    const int*   neighbors = (const int*)  d_in[1];
    const int*   px        = (const int*)  d_in[2];
    const int*   py        = (const int*)  d_in[3];
    const float* ng        = (const float*)d_in[4];
    const float* nb_       = (const float*)d_in[5];
    const float* nm        = (const float*)d_in[6];
    const float* nv        = (const float*)d_in[7];
    const float* c1w       = (const float*)d_in[8];
    const float* c1b       = (const float*)d_in[9];
    const float* g2a       = (const float*)d_in[10];
    const float* b2a       = (const float*)d_in[11];
    const float* m2a       = (const float*)d_in[12];
    const float* v2a       = (const float*)d_in[13];
    const float* w2a       = (const float*)d_in[14];
    const float* g2b       = (const float*)d_in[15];
    const float* b2b       = (const float*)d_in[16];
    const float* m2b       = (const float*)d_in[17];
    const float* v2b       = (const float*)d_in[18];
    const float* w2b       = (const float*)d_in[19];
    const float* fw        = (const float*)d_in[20];
    const float* fb        = (const float*)d_in[21];
    float* out = (float*)d_out;

    cudaFuncSetAttribute(main_kernel, cudaFuncAttributeMaxDynamicSharedMemorySize, SMEM_SZ);

    prep_kernel<<<128, 128>>>(ng, nb_, nm, nv, c1w, c1b,
                              g2a, b2a, m2a, v2a, w2a,
                              g2b, b2b, m2b, v2b, fw, fb);
    norm_kernel<<<(NPTS * 8) / 256, 256>>>(pc);
    wscat_kernel<<<NPTS / 4 / 256, 256>>>(px, py);
    compact_kernel<<<HW / 4 / 256, 256>>>();
    main_kernel<<<296, 256, SMEM_SZ>>>(w2b, fw, neighbors);
    emit_kernel<<<HW / EM_TILE, 256>>>(out);
}

// round 13
// speedup vs baseline: 7.8903x; 1.0475x over previous
#include <cuda_runtime.h>
#include <cuda_fp16.h>
#include <math.h>
#include <stdint.h>

// Problem constants
#define NPTS   65536
#define CIN    5
#define DCH    128
#define KNBR   16
#define KK     15
#define HH     64
#define WW     1024
#define HW     (HH*WW)
#define EPS    1e-5f

#define PTILE  8            // points per CTA tile
#define MROWS  (PTILE*KK)   // 120 G rows, row m = k*8 + p (neighbor-major)
#define PITCHB 272          // byte pitch (136 halfs) for G / W / Wn / ne tiles

// ---------------- device scratch ----------------------------------------------
__device__ float d_xn[NPTS * 8];
__device__ float d_feats[NPTS * DCH];
__device__ int   d_winner[HW];
__device__ int   d_live[HW];
__device__ int   d_live_count;

__device__ float d_waf[DCH * CIN];
__device__ float d_bf[DCH];
__device__ float d_wpe[DCH * CIN];
__device__ float d_be[DCH];
__device__ float d_sn[CIN];
__device__ float d_shn[CIN];

// ---------------- PTX helpers -------------------------------------------------
__device__ __forceinline__ uint32_t smem_u32(const void* p) {
    uint32_t a;
    asm("{ .reg .u64 t; cvta.to.shared.u64 t, %1; cvt.u32.u64 %0, t; }" : "=r"(a) : "l"(p));
    return a;
}
__device__ __forceinline__ void ldsm_x4(uint32_t* r, uint32_t addr) {
    asm volatile("ldmatrix.sync.aligned.m8n8.x4.shared.b16 {%0,%1,%2,%3}, [%4];"
        : "=r"(r[0]), "=r"(r[1]), "=r"(r[2]), "=r"(r[3]) : "r"(addr));
}
__device__ __forceinline__ void ldsm_x2(uint32_t* r, uint32_t addr) {
    asm volatile("ldmatrix.sync.aligned.m8n8.x2.shared.b16 {%0,%1}, [%2];"
        : "=r"(r[0]), "=r"(r[1]) : "r"(addr));
}
__device__ __forceinline__ void ldsm_x1(uint32_t* r, uint32_t addr) {
    asm volatile("ldmatrix.sync.aligned.m8n8.x1.shared.b16 {%0}, [%1];"
        : "=r"(r[0]) : "r"(addr));
}
__device__ __forceinline__ void mma16816(float* d, const uint32_t* a, const uint32_t* b) {
    asm volatile("mma.sync.aligned.m16n8k16.row.col.f32.f16.f16.f32 "
        "{%0,%1,%2,%3}, {%4,%5,%6,%7}, {%8,%9}, {%0,%1,%2,%3};"
        : "+f"(d[0]), "+f"(d[1]), "+f"(d[2]), "+f"(d[3])
        : "r"(a[0]), "r"(a[1]), "r"(a[2]), "r"(a[3]), "r"(b[0]), "r"(b[1]));
}
// fp16-accumulator variant: D/C are 2 .f16x2 regs
__device__ __forceinline__ void mma16816h(uint32_t* d, const uint32_t* a, const uint32_t* b) {
    asm volatile("mma.sync.aligned.m16n8k16.row.col.f16.f16.f16.f16 "
        "{%0,%1}, {%2,%3,%4,%5}, {%6,%7}, {%0,%1};"
        : "+r"(d[0]), "+r"(d[1])
        : "r"(a[0]), "r"(a[1]), "r"(a[2]), "r"(a[3]), "r"(b[0]), "r"(b[1]));
}
__device__ __forceinline__ void mma16808(float* d, const uint32_t* a, uint32_t b) {
    asm volatile("mma.sync.aligned.m16n8k8.row.col.f32.f16.f16.f32 "
        "{%0,%1,%2,%3}, {%4,%5}, {%6}, {%0,%1,%2,%3};"
        : "+f"(d[0]), "+f"(d[1]), "+f"(d[2]), "+f"(d[3])
        : "r"(a[0]), "r"(a[1]), "r"(b));
}
// packed gelu on 2 values
__device__ __forceinline__ __half2 gelu_h2(__half2 x, __half2 c0, __half2 c1, __half2 h05) {
    __half2 z = __hmul2(x, __hfma2(c1, __hmul2(x, x), c0));
    uint32_t t;
    asm("tanh.approx.f16x2 %0, %1;" : "=r"(t) : "r"(*(uint32_t*)&z));
    __half2 hx = __hmul2(x, h05);
    return __hfma2(hx, *(__half2*)&t, hx);
}

// ---------------- SMEM layout (bytes) -----------------------------------------
#define OFF_G     0          // G half [m<120][e<128] pitch 136h = 32640
#define OFF_W     32768      // w2b half [e][d] pitch 136h = 34816
#define OFF_WN    67584      // Wn half [dout][e] pitch 136h = 34816
#define OFF_WA    102400     // wa half [e][8] pitch 8h = 2048
#define OFF_DIFF0 104448     // diff half [m<120][8] = 1920
#define OFF_DIFF1 106368
#define OFF_NE0   108288     // ne half [p<8][e] pitch 136h = 2176 (k 0..7 partial)
#define OFF_NE1   110464     //                                (k 8..14 partial)
#define OFF_XI0   112640     // 8x8 f32 = 256
#define OFF_XI1   112896
#define OFF_IDS   113152     // int ids[2][8]
#define SMEM_SZ   113216

// ---------------- prep: parallel fold ------------------------------------------
__device__ __forceinline__ float blockSum(float v, float* red, int tid) {
    #pragma unroll
    for (int off = 16; off; off >>= 1) v += __shfl_down_sync(0xFFFFFFFFu, v, off);
    if ((tid & 31) == 0) red[tid >> 5] = v;
    __syncthreads();
    float r = (red[0] + red[1]) + (red[2] + red[3]);
    __syncthreads();
    return r;
}

__global__ void prep_kernel(const float* ng, const float* nb_, const float* nm, const float* nv,
                            const float* c1w, const float* c1b,
                            const float* g2a, const float* b2a, const float* m2a, const float* v2a,
                            const float* w2a,
                            const float* g2b, const float* b2b, const float* m2b, const float* v2b,
                            const float* fw, const float* fb)
{
    __shared__ float red[4];
    const int d = blockIdx.x, e = threadIdx.x;
    const float f = fw[d * (2 * DCH) + e];

    float s[6];
    #pragma unroll
    for (int c = 0; c < CIN; c++) s[c] = blockSum(f * c1w[e * CIN + c], red, e);
    s[5] = blockSum(f * c1b[e], red, e);

    if (e == 0) {
        #pragma unroll
        for (int c = 0; c < CIN; c++) d_wpe[d * CIN + c] = s[c];
        d_be[d] = s[5] + fb[d];

        float s2b = g2b[d] * rsqrtf(v2b[d] + EPS);
        float t2b = b2b[d] - m2b[d] * s2b;
        float cst = 0.f;
        #pragma unroll
        for (int c = 0; c < CIN; c++) {
            float sc = g2a[c] * rsqrtf(v2a[c] + EPS);
            float sh = b2a[c] - m2a[c] * sc;
            d_waf[d * CIN + c] = w2a[d * CIN + c] * sc * s2b;
            cst += w2a[d * CIN + c] * sh;
        }
        d_bf[d] = cst * s2b + t2b;
    }
    if (d == 0 && e < CIN) {
        float sn = ng[e] * rsqrtf(nv[e] + EPS);
        d_sn[e]  = sn;
        d_shn[e] = nb_[e] - nm[e] * sn;
    }
}

// ---------------- norm + winit merged ------------------------------------------
__global__ void norm_kernel(const float* pc)
{
    int t = blockIdx.x * blockDim.x + threadIdx.x;
    if (t < HW) d_winner[t] = -1;
    if (t == 0) d_live_count = 0;
    if (t >= NPTS * 8) return;
    int n = t >> 3, c = t & 7;
    float v = 0.f;
    if (c < CIN) v = pc[n * CIN + c] * d_sn[c] + d_shn[c];
    d_xn[t] = v;
}

// 4-wide scatter: MLP=4 per thread
__global__ void wscat_kernel(const int* px, const int* py)
{
    int t = blockIdx.x * blockDim.x + threadIdx.x;       // over NPTS/4
    int4 x4 = ((const int4*)px)[t];
    int4 y4 = ((const int4*)py)[t];
    int n0 = t * 4;
    atomicMax(&d_winner[y4.x * WW + x4.x], n0);
    atomicMax(&d_winner[y4.y * WW + x4.y], n0 + 1);
    atomicMax(&d_winner[y4.z * WW + x4.z], n0 + 2);
    atomicMax(&d_winner[y4.w * WW + x4.w], n0 + 3);
}

// 4-wide warp-aggregated compaction
__global__ void compact_kernel()
{
    int t = blockIdx.x * blockDim.x + threadIdx.x;       // over HW/4
    int4 w4 = ((const int4*)d_winner)[t];
    int lane = threadIdx.x & 31;
    int cntl = (w4.x >= 0) + (w4.y >= 0) + (w4.z >= 0) + (w4.w >= 0);
    int pref = cntl;
    #pragma unroll
    for (int off = 1; off < 32; off <<= 1) {
        int v = __shfl_up_sync(0xFFFFFFFFu, pref, off);
        if (lane >= off) pref += v;
    }
    int total = __shfl_sync(0xFFFFFFFFu, pref, 31);
    int excl = pref - cntl;
    int basep = 0;
    if (lane == 31 && total) basep = atomicAdd(&d_live_count, total);
    basep = __shfl_sync(0xFFFFFFFFu, basep, 31);
    int p = basep + excl;
    if (w4.x >= 0) d_live[p++] = w4.x;
    if (w4.y >= 0) d_live[p++] = w4.y;
    if (w4.z >= 0) d_live[p++] = w4.z;
    if (w4.w >= 0) d_live[p++] = w4.w;
}

// ---------------- main kernel --------------------------------------------------
__global__ void __launch_bounds__(256, 2)
main_kernel(const float* __restrict__ w2b, const float* __restrict__ fw,
            const int* __restrict__ nbr)
{
    extern __shared__ char smem[];
    const uint32_t smb = smem_u32(smem);
    __half* G_s  = (__half*)(smem + OFF_G);
    __half* W_s  = (__half*)(smem + OFF_W);
    __half* Wn_s = (__half*)(smem + OFF_WN);
    __half* Wa_s = (__half*)(smem + OFF_WA);
    int*    ids_s = (int*)(smem + OFF_IDS);

    const int tid  = threadIdx.x;
    const int wid  = tid >> 5;
    const int lane = tid & 31;
    const int tg   = lane & 3;
    const int g    = lane >> 2;

    // ---- prologue: weights into SMEM ----
    for (int i = tid; i < DCH * DCH; i += 256) {
        int e = i >> 7, d = i & 127;
        W_s[e * 136 + d] = __float2half_rn(w2b[i]);
    }
    for (int i = tid; i < DCH * DCH; i += 256) {
        int dout = i >> 7, e = i & 127;
        Wn_s[dout * 136 + e] = __float2half_rn(fw[dout * (2 * DCH) + DCH + e]);
    }
    for (int i = tid; i < DCH * 8; i += 256) {
        int e = i >> 3, k = i & 7;
        Wa_s[i] = (k < CIN) ? __float2half_rn(d_waf[e * CIN + k]) : __float2half_rn(0.f);
    }

    const int eLo = 16 * wid + g;
    const int eHi = eLo + 8;
    const float bfLo = d_bf[eLo], bfHi = d_bf[eHi];
    const float bevLo = d_be[eLo], bevHi = d_be[eHi];
    float wpeLo[CIN], wpeHi[CIN];
    #pragma unroll
    for (int c = 0; c < CIN; c++) { wpeLo[c] = d_wpe[eLo * CIN + c]; wpeHi[c] = d_wpe[eHi * CIN + c]; }

    const __half2 gc0 = __float2half2_rn(0.79788456f);
    const __half2 gc1 = __float2half2_rn(0.035677408f);
    const __half2 gh5 = __float2half2_rn(0.5f);

    const int eb = wid & 3, mh = wid >> 2;
    const int nq = 8 - mh;

    const uint32_t colh = ((lane >> 3) & 1) << 3;
    const uint32_t aWa = smb + OFF_WA + ((16 * wid + (lane & 15)) << 4);
    const uint32_t aW2 = smb + OFF_W  + (eb * 32 + (lane & 15)) * PITCHB + (((lane >> 4) << 3) << 1);
    const uint32_t aWn = smb + OFF_WN + (16 * wid + (lane & 15)) * PITCHB + (((lane >> 4) << 3) << 1);
    const uint32_t bGm = smb + OFF_G  + (64 * mh + ((lane >> 4) << 3) + (lane & 7)) * PITCHB + (colh << 1);
    const uint32_t bG2x = smb + OFF_G + (112 + (lane & 7)) * PITCHB + (colh << 1);
    const uint32_t bDf  = smb + OFF_DIFF0 + ((lane & 7) << 4);
    const uint32_t bNe0 = smb + OFF_NE0 + (lane & 7) * PITCHB + (colh << 1);
    const uint32_t bNe1 = bNe0 + (OFF_NE1 - OFF_NE0);

    __syncthreads();

    uint32_t wa2[2];
    ldsm_x2(wa2, aWa);
    // hoist loop-invariant epilogue Wn fragments (weights are static in smem)
    uint32_t wnf[8][4];
    #pragma unroll
    for (int kt = 0; kt < 8; kt++) ldsm_x4(wnf[kt], aWn + kt * 32);

    const int cnt = d_live_count;
    const int stride = gridDim.x * PTILE;
    int buf = 0;

    uint32_t s0 = 0, s1 = 0, s2 = 0;
    int sid = 0;
    float sx[8];

    #define PREFETCH(pbase) do { \
        if (tid < 128) { \
            int _p = (tid < MROWS) ? (tid & 7) : (tid - MROWS); \
            int _idx = (pbase) + _p; \
            _idx = min(_idx, cnt - 1); if (_idx < 0) _idx = 0; \
            sid = d_live[_idx]; \
            if (tid < MROWS) { \
                int _k = tid >> 3; \
                int _j = nbr[sid * KNBR + 1 + _k]; \
                float4 _a0 = ((const float4*)&d_xn[_j * 8])[0]; \
                float4 _b0 = ((const float4*)&d_xn[sid * 8])[0]; \
                float _a4 = d_xn[_j * 8 + 4], _b4 = d_xn[sid * 8 + 4]; \
                __half2 _h01 = __floats2half2_rn(_a0.x - _b0.x, _a0.y - _b0.y); \
                __half2 _h23 = __floats2half2_rn(_a0.z - _b0.z, _a0.w - _b0.w); \
                __half2 _h45 = __floats2half2_rn(_a4 - _b4, 0.f); \
                s0 = *(uint32_t*)&_h01; s1 = *(uint32_t*)&_h23; s2 = *(uint32_t*)&_h45; \
            } else { \
                float4 _q0 = ((const float4*)&d_xn[sid * 8])[0]; \
                float4 _q1 = ((const float4*)&d_xn[sid * 8])[1]; \
                sx[0] = _q0.x; sx[1] = _q0.y; sx[2] = _q0.z; sx[3] = _q0.w; \
                sx[4] = _q1.x; sx[5] = _q1.y; sx[6] = _q1.z; sx[7] = _q1.w; \
            } \
        } \
    } while (0)

    #define COMMIT(bi) do { \
        if (tid < MROWS) { \
            ((uint4*)(smem + OFF_DIFF0 + (bi) * (OFF_DIFF1 - OFF_DIFF0)))[tid] = make_uint4(s0, s1, s2, 0u); \
            if (tid < PTILE) ids_s[(bi) * 8 + tid] = sid; \
        } else if (tid < 128) { \
            float* _xb = (float*)(smem + OFF_XI0 + (bi) * (OFF_XI1 - OFF_XI0)); \
            int _p = tid - MROWS; \
            ((float4*)(_xb + _p * 8))[0] = make_float4(sx[0], sx[1], sx[2], sx[3]); \
            ((float4*)(_xb + _p * 8))[1] = make_float4(sx[4], sx[5], sx[6], sx[7]); \
        } \
    } while (0)

    // pre-loop: stage + commit tile 0, then stage tile 1
    const int base0 = blockIdx.x * PTILE;
    PREFETCH(base0);
    COMMIT(0);
    __syncthreads();
    PREFETCH(base0 + stride);

    for (int base = base0; base < cnt; base += stride) {
        const int np = min(PTILE, cnt - base);

        // phase 1: pre = wa.diff + bf (HMMA k=8), gelu, store G
        {
            const uint32_t dfb = bDf + buf * (OFF_DIFF1 - OFF_DIFF0);
            #pragma unroll
            for (int nb = 0; nb < 15; nb++) {
                uint32_t bd;
                ldsm_x1(&bd, dfb + nb * 128);
                float pa[4] = {bfLo, bfLo, bfHi, bfHi};
                mma16808(pa, wa2, bd);
                int m0 = nb * 8 + tg * 2;
                __half2 gA = gelu_h2(__floats2half2_rn(pa[0], pa[1]), gc0, gc1, gh5);
                __half2 gB = gelu_h2(__floats2half2_rn(pa[2], pa[3]), gc0, gc1, gh5);
                G_s[m0 * 136 + eLo]       = __low2half(gA);
                G_s[(m0 + 1) * 136 + eLo] = __high2half(gA);
                G_s[m0 * 136 + eHi]       = __low2half(gB);
                G_s[(m0 + 1) * 136 + eHi] = __high2half(gB);
            }
        }
        __syncthreads();   // sync1: G ready

        // phase 2: D = w2b . G^T, warp = (eb, mh), fp16 accumulators
        uint32_t acch[2][8][2];
        #pragma unroll
        for (int t = 0; t < 2; t++)
            #pragma unroll
            for (int q = 0; q < 8; q++) { acch[t][q][0] = 0u; acch[t][q][1] = 0u; }

        if (mh == 0) {
            #pragma unroll
            for (int kt = 0; kt < 8; kt++) {
                uint32_t a0[4], a1[4];
                ldsm_x4(a0, aW2 + kt * 32);
                ldsm_x4(a1, aW2 + 16 * PITCHB + kt * 32);
                #pragma unroll
                for (int q2 = 0; q2 < 4; q2++) {
                    uint32_t bg[4];
                    ldsm_x4(bg, bGm + q2 * (16 * PITCHB) + kt * 32);
                    mma16816h(acch[0][2 * q2],     a0, bg);
                    mma16816h(acch[0][2 * q2 + 1], a0, bg + 2);
                    mma16816h(acch[1][2 * q2],     a1, bg);
                    mma16816h(acch[1][2 * q2 + 1], a1, bg + 2);
                }
            }
        } else {
            #pragma unroll
            for (int kt = 0; kt < 8; kt++) {
                uint32_t a0[4], a1[4];
                ldsm_x4(a0, aW2 + kt * 32);
                ldsm_x4(a1, aW2 + 16 * PITCHB + kt * 32);
                #pragma unroll
                for (int q2 = 0; q2 < 3; q2++) {
                    uint32_t bg[4];
                    ldsm_x4(bg, bGm + q2 * (16 * PITCHB) + kt * 32);
                    mma16816h(acch[0][2 * q2],     a0, bg);
                    mma16816h(acch[0][2 * q2 + 1], a0, bg + 2);
                    mma16816h(acch[1][2 * q2],     a1, bg);
                    mma16816h(acch[1][2 * q2 + 1], a1, bg + 2);
                }
                uint32_t b2[2];
                ldsm_x2(b2, bG2x + kt * 32);
                mma16816h(acch[0][6], a0, b2);
                mma16816h(acch[1][6], a1, b2);
            }
        }

        // partial max over this warp's neighbor subset: packed hmax2, both points at once
        {
            __half* nep = (__half*)(smem + OFF_NE0 + mh * (OFF_NE1 - OFF_NE0));
            int p0 = tg * 2, p1 = p0 + 1;
            #pragma unroll
            for (int t = 0; t < 2; t++) {
                #pragma unroll
                for (int r = 0; r < 2; r++) {
                    __half2 mv = *(__half2*)&acch[t][0][r];
                    #pragma unroll
                    for (int q = 1; q < 8; q++)
                        if (q < nq) mv = __hmax2(mv, *(__half2*)&acch[t][q][r]);
                    int e = eb * 32 + 16 * t + 8 * r + g;
                    nep[p0 * 136 + e] = __low2half(mv);
                    nep[p1 * 136 + e] = __high2half(mv);
                }
            }
        }
        COMMIT(buf ^ 1);
        __syncthreads();   // sync2: NE + next diff/xi/ids ready

        // epilogue (tile t) — Wn fragments hoisted; no barrier after
        {
            float f2[4] = {0.f, 0.f, 0.f, 0.f};
            #pragma unroll
            for (int kt = 0; kt < 8; kt++) {
                uint32_t b0[2], b1[2], c[2];
                ldsm_x2(b0, bNe0 + kt * 32);
                ldsm_x2(b1, bNe1 + kt * 32);
                __half2 c0 = __hmax2(*(__half2*)&b0[0], *(__half2*)&b1[0]);
                __half2 c1 = __hmax2(*(__half2*)&b0[1], *(__half2*)&b1[1]);
                c[0] = *(uint32_t*)&c0; c[1] = *(uint32_t*)&c1;
                mma16816(f2, wnf[kt], c);
            }
            const float* xb = (const float*)(smem + OFF_XI0 + buf * (OFF_XI1 - OFF_XI0));
            int p0 = tg * 2, p1 = p0 + 1;
            float uLo0 = bevLo, uLo1 = bevLo, uHi0 = bevHi, uHi1 = bevHi;
            #pragma unroll
            for (int c = 0; c < CIN; c++) {
                float x0 = xb[p0 * 8 + c], x1 = xb[p1 * 8 + c];
                uLo0 = fmaf(wpeLo[c], x0, uLo0);
                uLo1 = fmaf(wpeLo[c], x1, uLo1);
                uHi0 = fmaf(wpeHi[c], x0, uHi0);
                uHi1 = fmaf(wpeHi[c], x1, uHi1);
            }
            int n0 = ids_s[buf * 8 + p0], n1 = ids_s[buf * 8 + p1];
            if (p0 < np) {
                d_feats[n0 * DCH + eLo] = f2[0] + uLo0;
                d_feats[n0 * DCH + eHi] = f2[2] + uHi0;
            }
            if (p1 < np) {
                d_feats[n1 * DCH + eLo] = f2[1] + uLo1;
                d_feats[n1 * DCH + eHi] = f2[3] + uHi1;
            }
        }

        // prefetch tile t+2 (overlaps with next iteration's compute)
        PREFETCH(base + 2 * stride);
        buf ^= 1;
    }
    #undef PREFETCH
    #undef COMMIT
}

// ---------------- emit ---------------------------------------------------------
#define EM_TILE 64
__global__ void emit_kernel(float* __restrict__ out)
{
    __shared__ float s[EM_TILE * 129];
    const int pixbase = blockIdx.x * EM_TILE;
    const int tid = threadIdx.x;

    for (int i = tid; i < EM_TILE * DCH; i += blockDim.x) {
        int p = i >> 7, d = i & 127;
        int w = d_winner[pixbase + p];
        s[p * 129 + d] = (w >= 0) ? d_feats[w * DCH + d] : -1.0f;
    }
    __syncthreads();
    for (int i = tid; i < EM_TILE * DCH; i += blockDim.x) {
        int d = i >> 6, p = i & 63;
        out[d * HW + pixbase + p] = s[p * 129 + d];
    }
}

// ---------------- launch --------------------------------------------------------
extern "C" void kernel_launch(void* const* d_in, const int* in_sizes, int n_in,
                              void* d_out, int out_size)
{
    const float* pc        = (const float*)d_in[0];
    const int*   neighbors = (const int*)  d_in[1];
    const int*   px        = (const int*)  d_in[2];
    const int*   py        = (const int*)  d_in[3];
    const float* ng        = (const float*)d_in[4];
    const float* nb_       = (const float*)d_in[5];
    const float* nm        = (const float*)d_in[6];
    const float* nv        = (const float*)d_in[7];
    const float* c1w       = (const float*)d_in[8];
    const float* c1b       = (const float*)d_in[9];
    const float* g2a       = (const float*)d_in[10];
    const float* b2a       = (const float*)d_in[11];
    const float* m2a       = (const float*)d_in[12];
    const float* v2a       = (const float*)d_in[13];
    const float* w2a       = (const float*)d_in[14];
    const float* g2b       = (const float*)d_in[15];
    const float* b2b       = (const float*)d_in[16];
    const float* m2b       = (const float*)d_in[17];
    const float* v2b       = (const float*)d_in[18];
    const float* w2b       = (const float*)d_in[19];
    const float* fw        = (const float*)d_in[20];
    const float* fb        = (const float*)d_in[21];
    float* out = (float*)d_out;

    cudaFuncSetAttribute(main_kernel, cudaFuncAttributeMaxDynamicSharedMemorySize, SMEM_SZ);

    prep_kernel<<<128, 128>>>(ng, nb_, nm, nv, c1w, c1b,
                              g2a, b2a, m2a, v2a, w2a,
                              g2b, b2b, m2b, v2b, fw, fb);
    norm_kernel<<<(NPTS * 8) / 256, 256>>>(pc);
    wscat_kernel<<<NPTS / 4 / 256, 256>>>(px, py);
    compact_kernel<<<HW / 4 / 256, 256>>>();
    main_kernel<<<296, 256, SMEM_SZ>>>(w2b, fw, neighbors);
    emit_kernel<<<HW / EM_TILE, 256>>>(out);
}

// round 16
// speedup vs baseline: 8.0918x; 1.0255x over previous
#include <cuda_runtime.h>
#include <cuda_fp16.h>
#include <math.h>
#include <stdint.h>

// Problem constants
#define NPTS   65536
#define CIN    5
#define DCH    128
#define KNBR   16
#define KK     15
#define HH     64
#define WW     1024
#define HW     (HH*WW)
#define EPS    1e-5f

#define PTILE  8            // points per CTA tile
#define MROWS  (PTILE*KK)   // 120 G cols, col m = k*8 + p (neighbor-major)
#define PITCHB 272          // byte pitch (136 halfs) for W / Wn / ne tiles
#define PITCHG 240          // byte pitch (120 halfs) for G^T [e][m]

// ---------------- device scratch ----------------------------------------------
__device__ float d_xn[NPTS * 8];
__device__ float d_feats[NPTS * DCH];
__device__ int   d_winner[HW];
__device__ int   d_live[HW];
__device__ int   d_live_count;

__device__ float d_waf[DCH * CIN];
__device__ float d_bf[DCH];
__device__ float d_wpe[DCH * CIN];
__device__ float d_be[DCH];
__device__ float d_sn[CIN];
__device__ float d_shn[CIN];

// ---------------- PTX helpers -------------------------------------------------
__device__ __forceinline__ uint32_t smem_u32(const void* p) {
    uint32_t a;
    asm("{ .reg .u64 t; cvta.to.shared.u64 t, %1; cvt.u32.u64 %0, t; }" : "=r"(a) : "l"(p));
    return a;
}
__device__ __forceinline__ void ldsm_x4(uint32_t* r, uint32_t addr) {
    asm volatile("ldmatrix.sync.aligned.m8n8.x4.shared.b16 {%0,%1,%2,%3}, [%4];"
        : "=r"(r[0]), "=r"(r[1]), "=r"(r[2]), "=r"(r[3]) : "r"(addr));
}
__device__ __forceinline__ void ldsm_x2(uint32_t* r, uint32_t addr) {
    asm volatile("ldmatrix.sync.aligned.m8n8.x2.shared.b16 {%0,%1}, [%2];"
        : "=r"(r[0]), "=r"(r[1]) : "r"(addr));
}
__device__ __forceinline__ void ldsm_x1(uint32_t* r, uint32_t addr) {
    asm volatile("ldmatrix.sync.aligned.m8n8.x1.shared.b16 {%0}, [%1];"
        : "=r"(r[0]) : "r"(addr));
}
// transposed variants: load from k-major [k][n] layout, rows = k
__device__ __forceinline__ void ldsm_x4t(uint32_t* r, uint32_t addr) {
    asm volatile("ldmatrix.sync.aligned.m8n8.x4.trans.shared.b16 {%0,%1,%2,%3}, [%4];"
        : "=r"(r[0]), "=r"(r[1]), "=r"(r[2]), "=r"(r[3]) : "r"(addr));
}
__device__ __forceinline__ void ldsm_x2t(uint32_t* r, uint32_t addr) {
    asm volatile("ldmatrix.sync.aligned.m8n8.x2.trans.shared.b16 {%0,%1}, [%2];"
        : "=r"(r[0]), "=r"(r[1]) : "r"(addr));
}
__device__ __forceinline__ void mma16816(float* d, const uint32_t* a, const uint32_t* b) {
    asm volatile("mma.sync.aligned.m16n8k16.row.col.f32.f16.f16.f32 "
        "{%0,%1,%2,%3}, {%4,%5,%6,%7}, {%8,%9}, {%0,%1,%2,%3};"
        : "+f"(d[0]), "+f"(d[1]), "+f"(d[2]), "+f"(d[3])
        : "r"(a[0]), "r"(a[1]), "r"(a[2]), "r"(a[3]), "r"(b[0]), "r"(b[1]));
}
// fp16-accumulator variant
__device__ __forceinline__ void mma16816h(uint32_t* d, const uint32_t* a, const uint32_t* b) {
    asm volatile("mma.sync.aligned.m16n8k16.row.col.f16.f16.f16.f16 "
        "{%0,%1}, {%2,%3,%4,%5}, {%6,%7}, {%0,%1};"
        : "+r"(d[0]), "+r"(d[1])
        : "r"(a[0]), "r"(a[1]), "r"(a[2]), "r"(a[3]), "r"(b[0]), "r"(b[1]));
}
__device__ __forceinline__ void mma16808(float* d, const uint32_t* a, uint32_t b) {
    asm volatile("mma.sync.aligned.m16n8k8.row.col.f32.f16.f16.f32 "
        "{%0,%1,%2,%3}, {%4,%5}, {%6}, {%0,%1,%2,%3};"
        : "+f"(d[0]), "+f"(d[1]), "+f"(d[2]), "+f"(d[3])
        : "r"(a[0]), "r"(a[1]), "r"(b));
}
// packed gelu on 2 values
__device__ __forceinline__ __half2 gelu_h2(__half2 x, __half2 c0, __half2 c1, __half2 h05) {
    __half2 z = __hmul2(x, __hfma2(c1, __hmul2(x, x), c0));
    uint32_t t;
    asm("tanh.approx.f16x2 %0, %1;" : "=r"(t) : "r"(*(uint32_t*)&z));
    __half2 hx = __hmul2(x, h05);
    return __hfma2(hx, *(__half2*)&t, hx);
}

// ---------------- SMEM layout (bytes) -----------------------------------------
#define OFF_G     0          // G^T half [e<128][m<120] pitch 120h = 30720
#define OFF_W     30720      // w2b half [e][d] pitch 136h = 34816
#define OFF_WN    65536      // Wn half [dout][e] pitch 136h = 34816
#define OFF_WA    100352     // wa half [e][8] pitch 8h = 2048
#define OFF_DIFF0 102400     // diff half [m<120][8] = 1920
#define OFF_DIFF1 104320
#define OFF_NE0   106240     // ne half [p<8][e] pitch 136h = 2176 (k 0..7 partial)
#define OFF_NE1   108416     //                                (k 8..14 partial)
#define OFF_XI0   110592     // 8x8 f32 = 256
#define OFF_XI1   110848
#define OFF_IDS   111104     // int ids[2][8]
#define SMEM_SZ   111168

// ---------------- prep: parallel fold ------------------------------------------
__device__ __forceinline__ float blockSum(float v, float* red, int tid) {
    #pragma unroll
    for (int off = 16; off; off >>= 1) v += __shfl_down_sync(0xFFFFFFFFu, v, off);
    if ((tid & 31) == 0) red[tid >> 5] = v;
    __syncthreads();
    float r = (red[0] + red[1]) + (red[2] + red[3]);
    __syncthreads();
    return r;
}

__global__ void prep_kernel(const float* ng, const float* nb_, const float* nm, const float* nv,
                            const float* c1w, const float* c1b,
                            const float* g2a, const float* b2a, const float* m2a, const float* v2a,
                            const float* w2a,
                            const float* g2b, const float* b2b, const float* m2b, const float* v2b,
                            const float* fw, const float* fb)
{
    __shared__ float red[4];
    const int d = blockIdx.x, e = threadIdx.x;
    const float f = fw[d * (2 * DCH) + e];

    float s[6];
    #pragma unroll
    for (int c = 0; c < CIN; c++) s[c] = blockSum(f * c1w[e * CIN + c], red, e);
    s[5] = blockSum(f * c1b[e], red, e);

    if (e == 0) {
        #pragma unroll
        for (int c = 0; c < CIN; c++) d_wpe[d * CIN + c] = s[c];
        d_be[d] = s[5] + fb[d];

        float s2b = g2b[d] * rsqrtf(v2b[d] + EPS);
        float t2b = b2b[d] - m2b[d] * s2b;
        float cst = 0.f;
        #pragma unroll
        for (int c = 0; c < CIN; c++) {
            float sc = g2a[c] * rsqrtf(v2a[c] + EPS);
            float sh = b2a[c] - m2a[c] * sc;
            d_waf[d * CIN + c] = w2a[d * CIN + c] * sc * s2b;
            cst += w2a[d * CIN + c] * sh;
        }
        d_bf[d] = cst * s2b + t2b;
    }
    if (d == 0 && e < CIN) {
        float sn = ng[e] * rsqrtf(nv[e] + EPS);
        d_sn[e]  = sn;
        d_shn[e] = nb_[e] - nm[e] * sn;
    }
}

// ---------------- norm + winit merged ------------------------------------------
__global__ void norm_kernel(const float* pc)
{
    int t = blockIdx.x * blockDim.x + threadIdx.x;
    if (t < HW) d_winner[t] = -1;
    if (t == 0) d_live_count = 0;
    if (t >= NPTS * 8) return;
    int n = t >> 3, c = t & 7;
    float v = 0.f;
    if (c < CIN) v = pc[n * CIN + c] * d_sn[c] + d_shn[c];
    d_xn[t] = v;
}

// 4-wide scatter: MLP=4 per thread
__global__ void wscat_kernel(const int* px, const int* py)
{
    int t = blockIdx.x * blockDim.x + threadIdx.x;       // over NPTS/4
    int4 x4 = ((const int4*)px)[t];
    int4 y4 = ((const int4*)py)[t];
    int n0 = t * 4;
    atomicMax(&d_winner[y4.x * WW + x4.x], n0);
    atomicMax(&d_winner[y4.y * WW + x4.y], n0 + 1);
    atomicMax(&d_winner[y4.z * WW + x4.z], n0 + 2);
    atomicMax(&d_winner[y4.w * WW + x4.w], n0 + 3);
}

// 4-wide warp-aggregated compaction
__global__ void compact_kernel()
{
    int t = blockIdx.x * blockDim.x + threadIdx.x;       // over HW/4
    int4 w4 = ((const int4*)d_winner)[t];
    int lane = threadIdx.x & 31;
    int cntl = (w4.x >= 0) + (w4.y >= 0) + (w4.z >= 0) + (w4.w >= 0);
    int pref = cntl;
    #pragma unroll
    for (int off = 1; off < 32; off <<= 1) {
        int v = __shfl_up_sync(0xFFFFFFFFu, pref, off);
        if (lane >= off) pref += v;
    }
    int total = __shfl_sync(0xFFFFFFFFu, pref, 31);
    int excl = pref - cntl;
    int basep = 0;
    if (lane == 31 && total) basep = atomicAdd(&d_live_count, total);
    basep = __shfl_sync(0xFFFFFFFFu, basep, 31);
    int p = basep + excl;
    if (w4.x >= 0) d_live[p++] = w4.x;
    if (w4.y >= 0) d_live[p++] = w4.y;
    if (w4.z >= 0) d_live[p++] = w4.z;
    if (w4.w >= 0) d_live[p++] = w4.w;
}

// ---------------- main kernel --------------------------------------------------
__global__ void __launch_bounds__(256, 2)
main_kernel(const float* __restrict__ w2b, const float* __restrict__ fw,
            const int* __restrict__ nbr)
{
    extern __shared__ char smem[];
    const uint32_t smb = smem_u32(smem);
    __half* W_s  = (__half*)(smem + OFF_W);
    __half* Wn_s = (__half*)(smem + OFF_WN);
    __half* Wa_s = (__half*)(smem + OFF_WA);
    int*    ids_s = (int*)(smem + OFF_IDS);

    const int tid  = threadIdx.x;
    const int wid  = tid >> 5;
    const int lane = tid & 31;
    const int tg   = lane & 3;
    const int g    = lane >> 2;

    // ---- prologue: weights into SMEM ----
    for (int i = tid; i < DCH * DCH; i += 256) {
        int e = i >> 7, d = i & 127;
        W_s[e * 136 + d] = __float2half_rn(w2b[i]);
    }
    for (int i = tid; i < DCH * DCH; i += 256) {
        int dout = i >> 7, e = i & 127;
        Wn_s[dout * 136 + e] = __float2half_rn(fw[dout * (2 * DCH) + DCH + e]);
    }
    for (int i = tid; i < DCH * 8; i += 256) {
        int e = i >> 3, k = i & 7;
        Wa_s[i] = (k < CIN) ? __float2half_rn(d_waf[e * CIN + k]) : __float2half_rn(0.f);
    }

    const int eLo = 16 * wid + g;
    const int eHi = eLo + 8;
    const float bfLo = d_bf[eLo], bfHi = d_bf[eHi];
    const float bevLo = d_be[eLo], bevHi = d_be[eHi];
    float wpeLo[CIN], wpeHi[CIN];
    #pragma unroll
    for (int c = 0; c < CIN; c++) { wpeLo[c] = d_wpe[eLo * CIN + c]; wpeHi[c] = d_wpe[eHi * CIN + c]; }

    const __half2 gc0 = __float2half2_rn(0.79788456f);
    const __half2 gc1 = __float2half2_rn(0.035677408f);
    const __half2 gh5 = __float2half2_rn(0.5f);

    const int eb = wid & 3, mh = wid >> 2;
    const int nq = 8 - mh;

    const uint32_t colh = ((lane >> 3) & 1) << 3;   // B-operand k-half (ldsm_x2 row pairs)
    const uint32_t kha  = ((lane >> 4) & 1) << 3;   // A-operand k-half (ldsm_x4 tile pairs)
    const uint32_t aWa = smb + OFF_WA + ((16 * wid + (lane & 15)) << 4);
    const uint32_t aW2 = smb + OFF_W  + (eb * 32 + (lane & 15)) * PITCHB + (kha << 1);
    const uint32_t aWn = smb + OFF_WN + (16 * wid + (lane & 15)) * PITCHB + (kha << 1);
    // G^T trans-B bases: rows = e (k of the mma), cols = m (n of the mma)
    const uint32_t rowT = ((lane >> 3) & 1) * 8 + (lane & 7);
    const uint32_t mstat = ((lane >> 4) & 1) * 8;
    const uint32_t bGT  = smb + OFF_G + rowT * PITCHG + ((mh * 64 + mstat) << 1);  // + kt*16*PITCHG + q2*32
    const uint32_t bG2T = smb + OFF_G + rowT * PITCHG + (112 << 1);                // + kt*16*PITCHG
    const uint32_t bDf  = smb + OFF_DIFF0 + ((lane & 7) << 4);
    const uint32_t bNe0 = smb + OFF_NE0 + (lane & 7) * PITCHB + (colh << 1);
    const uint32_t bNe1 = bNe0 + (OFF_NE1 - OFF_NE0);

    __syncthreads();

    uint32_t wa2[2];
    ldsm_x2(wa2, aWa);
    // hoist loop-invariant epilogue Wn fragments
    uint32_t wnf[8][4];
    #pragma unroll
    for (int kt = 0; kt < 8; kt++) ldsm_x4(wnf[kt], aWn + kt * 32);

    const int cnt = d_live_count;
    const int stride = gridDim.x * PTILE;
    int buf = 0;

    uint32_t s0 = 0, s1 = 0, s2 = 0;
    int sid = 0;
    float sx[8];

    #define PREFETCH(pbase) do { \
        if (tid < 128) { \
            int _p = (tid < MROWS) ? (tid & 7) : (tid - MROWS); \
            int _idx = (pbase) + _p; \
            _idx = min(_idx, cnt - 1); if (_idx < 0) _idx = 0; \
            sid = d_live[_idx]; \
            if (tid < MROWS) { \
                int _k = tid >> 3; \
                int _j = nbr[sid * KNBR + 1 + _k]; \
                float4 _a0 = ((const float4*)&d_xn[_j * 8])[0]; \
                float4 _b0 = ((const float4*)&d_xn[sid * 8])[0]; \
                float _a4 = d_xn[_j * 8 + 4], _b4 = d_xn[sid * 8 + 4]; \
                __half2 _h01 = __floats2half2_rn(_a0.x - _b0.x, _a0.y - _b0.y); \
                __half2 _h23 = __floats2half2_rn(_a0.z - _b0.z, _a0.w - _b0.w); \
                __half2 _h45 = __floats2half2_rn(_a4 - _b4, 0.f); \
                s0 = *(uint32_t*)&_h01; s1 = *(uint32_t*)&_h23; s2 = *(uint32_t*)&_h45; \
            } else { \
                float4 _q0 = ((const float4*)&d_xn[sid * 8])[0]; \
                float4 _q1 = ((const float4*)&d_xn[sid * 8])[1]; \
                sx[0] = _q0.x; sx[1] = _q0.y; sx[2] = _q0.z; sx[3] = _q0.w; \
                sx[4] = _q1.x; sx[5] = _q1.y; sx[6] = _q1.z; sx[7] = _q1.w; \
            } \
        } \
    } while (0)

    #define COMMIT(bi) do { \
        if (tid < MROWS) { \
            ((uint4*)(smem + OFF_DIFF0 + (bi) * (OFF_DIFF1 - OFF_DIFF0)))[tid] = make_uint4(s0, s1, s2, 0u); \
            if (tid < PTILE) ids_s[(bi) * 8 + tid] = sid; \
        } else if (tid < 128) { \
            float* _xb = (float*)(smem + OFF_XI0 + (bi) * (OFF_XI1 - OFF_XI0)); \
            int _p = tid - MROWS; \
            ((float4*)(_xb + _p * 8))[0] = make_float4(sx[0], sx[1], sx[2], sx[3]); \
            ((float4*)(_xb + _p * 8))[1] = make_float4(sx[4], sx[5], sx[6], sx[7]); \
        } \
    } while (0)

    // pre-loop: stage + commit tile 0, then stage tile 1
    const int base0 = blockIdx.x * PTILE;
    PREFETCH(base0);
    COMMIT(0);
    __syncthreads();
    PREFETCH(base0 + stride);

    for (int base = base0; base < cnt; base += stride) {
        const int np = min(PTILE, cnt - base);

        // phase 1: pre = wa.diff + bf (HMMA k=8), gelu, store G^T (half2 stores)
        {
            const uint32_t dfb = bDf + buf * (OFF_DIFF1 - OFF_DIFF0);
            #pragma unroll
            for (int nb = 0; nb < 15; nb++) {
                uint32_t bd;
                ldsm_x1(&bd, dfb + nb * 128);
                float pa[4] = {bfLo, bfLo, bfHi, bfHi};
                mma16808(pa, wa2, bd);
                int m0 = nb * 8 + tg * 2;
                __half2 gA = gelu_h2(__floats2half2_rn(pa[0], pa[1]), gc0, gc1, gh5);
                __half2 gB = gelu_h2(__floats2half2_rn(pa[2], pa[3]), gc0, gc1, gh5);
                *(__half2*)(smem + OFF_G + eLo * PITCHG + m0 * 2) = gA;
                *(__half2*)(smem + OFF_G + eHi * PITCHG + m0 * 2) = gB;
            }
        }
        __syncthreads();   // sync1: G ready

        // phase 2: D = w2b . G^T (trans-B ldsm), warp = (eb, mh), fp16 accumulators
        uint32_t acch[2][8][2];
        #pragma unroll
        for (int t = 0; t < 2; t++)
            #pragma unroll
            for (int q = 0; q < 8; q++) { acch[t][q][0] = 0u; acch[t][q][1] = 0u; }

        if (mh == 0) {
            #pragma unroll
            for (int kt = 0; kt < 8; kt++) {
                uint32_t a0[4], a1[4];
                ldsm_x4(a0, aW2 + kt * 32);
                ldsm_x4(a1, aW2 + 16 * PITCHB + kt * 32);
                #pragma unroll
                for (int q2 = 0; q2 < 4; q2++) {
                    uint32_t bg[4];
                    ldsm_x4t(bg, bGT + kt * (16 * PITCHG) + q2 * 32);
                    mma16816h(acch[0][2 * q2],     a0, bg);
                    mma16816h(acch[0][2 * q2 + 1], a0, bg + 2);
                    mma16816h(acch[1][2 * q2],     a1, bg);
                    mma16816h(acch[1][2 * q2 + 1], a1, bg + 2);
                }
            }
        } else {
            #pragma unroll
            for (int kt = 0; kt < 8; kt++) {
                uint32_t a0[4], a1[4];
                ldsm_x4(a0, aW2 + kt * 32);
                ldsm_x4(a1, aW2 + 16 * PITCHB + kt * 32);
                #pragma unroll
                for (int q2 = 0; q2 < 3; q2++) {
                    uint32_t bg[4];
                    ldsm_x4t(bg, bGT + kt * (16 * PITCHG) + q2 * 32);
                    mma16816h(acch[0][2 * q2],     a0, bg);
                    mma16816h(acch[0][2 * q2 + 1], a0, bg + 2);
                    mma16816h(acch[1][2 * q2],     a1, bg);
                    mma16816h(acch[1][2 * q2 + 1], a1, bg + 2);
                }
                uint32_t b2[2];
                ldsm_x2t(b2, bG2T + kt * (16 * PITCHG));
                mma16816h(acch[0][6], a0, b2);
                mma16816h(acch[1][6], a1, b2);
            }
        }

        // partial max over this warp's neighbor subset: packed hmax2
        {
            __half* nep = (__half*)(smem + OFF_NE0 + mh * (OFF_NE1 - OFF_NE0));
            int p0 = tg * 2, p1 = p0 + 1;
            #pragma unroll
            for (int t = 0; t < 2; t++) {
                #pragma unroll
                for (int r = 0; r < 2; r++) {
                    __half2 mv = *(__half2*)&acch[t][0][r];
                    #pragma unroll
                    for (int q = 1; q < 8; q++)
                        if (q < nq) mv = __hmax2(mv, *(__half2*)&acch[t][q][r]);
                    int e = eb * 32 + 16 * t + 8 * r + g;
                    nep[p0 * 136 + e] = __low2half(mv);
                    nep[p1 * 136 + e] = __high2half(mv);
                }
            }
        }
        COMMIT(buf ^ 1);
        __syncthreads();   // sync2: NE + next diff/xi/ids ready

        // epilogue (tile t) — Wn fragments hoisted; no barrier after
        {
            float f2[4] = {0.f, 0.f, 0.f, 0.f};
            #pragma unroll
            for (int kt = 0; kt < 8; kt++) {
                uint32_t b0[2], b1[2], c[2];
                ldsm_x2(b0, bNe0 + kt * 32);
                ldsm_x2(b1, bNe1 + kt * 32);
                __half2 c0 = __hmax2(*(__half2*)&b0[0], *(__half2*)&b1[0]);
                __half2 c1 = __hmax2(*(__half2*)&b0[1], *(__half2*)&b1[1]);
                c[0] = *(uint32_t*)&c0; c[1] = *(uint32_t*)&c1;
                mma16816(f2, wnf[kt], c);
            }
            const float* xb = (const float*)(smem + OFF_XI0 + buf * (OFF_XI1 - OFF_XI0));
            int p0 = tg * 2, p1 = p0 + 1;
            float uLo0 = bevLo, uLo1 = bevLo, uHi0 = bevHi, uHi1 = bevHi;
            #pragma unroll
            for (int c = 0; c < CIN; c++) {
                float x0 = xb[p0 * 8 + c], x1 = xb[p1 * 8 + c];
                uLo0 = fmaf(wpeLo[c], x0, uLo0);
                uLo1 = fmaf(wpeLo[c], x1, uLo1);
                uHi0 = fmaf(wpeHi[c], x0, uHi0);
                uHi1 = fmaf(wpeHi[c], x1, uHi1);
            }
            int n0 = ids_s[buf * 8 + p0], n1 = ids_s[buf * 8 + p1];
            if (p0 < np) {
                d_feats[n0 * DCH + eLo] = f2[0] + uLo0;
                d_feats[n0 * DCH + eHi] = f2[2] + uHi0;
            }
            if (p1 < np) {
                d_feats[n1 * DCH + eLo] = f2[1] + uLo1;
                d_feats[n1 * DCH + eHi] = f2[3] + uHi1;
            }
        }

        // prefetch tile t+2 (overlaps with next iteration's compute)
        PREFETCH(base + 2 * stride);
        buf ^= 1;
    }
    #undef PREFETCH
    #undef COMMIT
}

// ---------------- emit ---------------------------------------------------------
#define EM_TILE 64
__global__ void emit_kernel(float* __restrict__ out)
{
    __shared__ float s[EM_TILE * 129];
    const int pixbase = blockIdx.x * EM_TILE;
    const int tid = threadIdx.x;

    for (int i = tid; i < EM_TILE * DCH; i += blockDim.x) {
        int p = i >> 7, d = i & 127;
        int w = d_winner[pixbase + p];
        s[p * 129 + d] = (w >= 0) ? d_feats[w * DCH + d] : -1.0f;
    }
    __syncthreads();
    for (int i = tid; i < EM_TILE * DCH; i += blockDim.x) {
        int d = i >> 6, p = i & 63;
        out[d * HW + pixbase + p] = s[p * 129 + d];
    }
}

// ---------------- launch --------------------------------------------------------
extern "C" void kernel_launch(void* const* d_in, const int* in_sizes, int n_in,
                              void* d_out, int out_size)
{
    const float* pc        = (const float*)d_in[0];
    const int*   neighbors = (const int*)  d_in[1];
    const int*   px        = (const int*)  d_in[2];
    const int*   py        = (const int*)  d_in[3];
    const float* ng        = (const float*)d_in[4];
    const float* nb_       = (const float*)d_in[5];
    const float* nm        = (const float*)d_in[6];
    const float* nv        = (const float*)d_in[7];
    const float* c1w       = (const float*)d_in[8];
    const float* c1b       = (const float*)d_in[9];
    const float* g2a       = (const float*)d_in[10];
    const float* b2a       = (const float*)d_in[11];
    const float* m2a       = (const float*)d_in[12];
    const float* v2a       = (const float*)d_in[13];
    const float* w2a       = (const float*)d_in[14];
    const float* g2b       = (const float*)d_in[15];
    const float* b2b       = (const float*)d_in[16];
    const float* m2b       = (const float*)d_in[17];
    const float* v2b       = (const float*)d_in[18];
    const float* w2b       = (const float*)d_in[19];
    const float* fw        = (const float*)d_in[20];
    const float* fb        = (const float*)d_in[21];
    float* out = (float*)d_out;

    cudaFuncSetAttribute(main_kernel, cudaFuncAttributeMaxDynamicSharedMemorySize, SMEM_SZ);

    prep_kernel<<<128, 128>>>(ng, nb_, nm, nv, c1w, c1b,
                              g2a, b2a, m2a, v2a, w2a,
                              g2b, b2b, m2b, v2b, fw, fb);
    norm_kernel<<<(NPTS * 8) / 256, 256>>>(pc);
    wscat_kernel<<<NPTS / 4 / 256, 256>>>(px, py);
    compact_kernel<<<HW / 4 / 256, 256>>>();
    main_kernel<<<296, 256, SMEM_SZ>>>(w2b, fw, neighbors);
    emit_kernel<<<HW / EM_TILE, 256>>>(out);
}